// round 10
// baseline (speedup 1.0000x reference)
#include <cuda_runtime.h>
#include <cuda_bf16.h>
#include <cstdint>
#include <cstddef>

#define Bsz 16
#define Lsz 2048
#define Dsz 512
#define NLsz 4
#define Tsz (Bsz * Lsz)  // 32768
#define DD (Dsz * Dsz)

// weight arena offsets (units of DD)
#define W_CONV(i) ((size_t)(i) * 3 * DD)
#define W_WOUT(i) ((size_t)(12 + (i)) * DD)      // wout^T (prep only)
#define W_FC(i)   ((size_t)(16 + 2 * (i)) * DD)  // after prep: Wcomb = Wf@Wo
#define W_MO(i)   ((size_t)(24 + (i)) * DD)
#define W_HEAD    ((size_t)28 * DD)

// scan chunking
#define SCH 256
#define NCH (Lsz / SCH)  // 8
#define NFLAGS (NLsz * NCH * Bsz * 4)  // 2048

// ---------------- scratch (device globals; no allocation allowed) ----------
__device__ float g_y[Tsz * Dsz];
__device__ float g_z2[Tsz * Dsz];
__device__ float g_gate[Tsz];
__device__ float g_gatep[16 * Tsz];
__device__ float g_bcomb[NLsz * 2 * Dsz];
__device__ float g_hfin[NCH * Bsz * Dsz];   // scan: inclusive chunk-end states
__device__ int   g_sflag[NFLAGS];           // scan chain flags (per layer)
__device__ float g_w0t[3 * DD];
__device__ float g_u0[3 * Dsz];
__device__ __nv_bfloat16 g_zh[Tsz * Dsz], g_zl[Tsz * Dsz];
__device__ __nv_bfloat16 g_hh[Tsz * Dsz], g_hl[Tsz * Dsz];
__device__ __nv_bfloat16 g_gh[Tsz * Dsz], g_gl[Tsz * Dsz];
__device__ __nv_bfloat16 g_wh[29 * DD], g_wl[29 * DD];

// ---------------- helpers ---------------------------------------------------
__device__ __forceinline__ uint32_t smem_u32(const void* p) {
    return (uint32_t)__cvta_generic_to_shared(p);
}
__device__ __forceinline__ uint32_t swz(uint32_t x) { return x ^ ((x >> 3) & 0x70); }

__device__ __forceinline__ void cp16(uint32_t dst, const void* src, bool v) {
    int sz = v ? 16 : 0;
    asm volatile("cp.async.cg.shared.global [%0], [%1], 16, %2;"
                 :: "r"(dst), "l"(src), "r"(sz) : "memory");
}
#define CP_COMMIT() asm volatile("cp.async.commit_group;" ::: "memory")

#define LDSM_X4(r, a)                                                          \
    asm volatile("ldmatrix.sync.aligned.m8n8.x4.shared.b16 {%0,%1,%2,%3}, [%4];" \
                 : "=r"((r)[0]), "=r"((r)[1]), "=r"((r)[2]), "=r"((r)[3]) : "r"(a))

#define MMA_BF16(d, a, b0, b1)                                                 \
    asm volatile(                                                              \
        "mma.sync.aligned.m16n8k16.row.col.f32.bf16.bf16.f32 "                 \
        "{%0,%1,%2,%3},{%4,%5,%6,%7},{%8,%9},{%0,%1,%2,%3};"                   \
        : "+f"((d)[0]), "+f"((d)[1]), "+f"((d)[2]), "+f"((d)[3])               \
        : "r"((a)[0]), "r"((a)[1]), "r"((a)[2]), "r"((a)[3]), "r"(b0), "r"(b1))

__device__ __forceinline__ void split2(float a, float b, __nv_bfloat162& hi,
                                       __nv_bfloat162& lo) {
    hi = __floats2bfloat162_rn(a, b);
    lo = __floats2bfloat162_rn(a - __bfloat162float(hi.x), b - __bfloat162float(hi.y));
}

// ============================================================================
// Generic bf16-split GEMM, 512 threads, tile 128x128, single-sync pipeline.
// flags: 1=addBias, 2=accum fp32, 4=split bf16 out, 8=gate partials,
//        16=one-hot residual add.
// ============================================================================
#define STAGE_B 65536
#define GSMEM (3 * STAGE_B)

__global__ __launch_bounds__(512, 1)
void mma_gemm_k(const __nv_bfloat16* __restrict__ Ah, const __nv_bfloat16* __restrict__ Al,
                const __nv_bfloat16* __restrict__ Wh, const __nv_bfloat16* __restrict__ Wl,
                const float* __restrict__ bias, float* __restrict__ Cf,
                __nv_bfloat16* __restrict__ Ch, __nv_bfloat16* __restrict__ Cl,
                const float* __restrict__ wgv, const int* __restrict__ xTok,
                float* __restrict__ gateOut,
                int N, int nPasses, int s0, int s1, int s2, int flags,
                int wLayerStride) {
    extern __shared__ char smem[];
    const uint32_t smb = smem_u32(smem);
    const int tid = threadIdx.x, lane = tid & 31, wid = tid >> 5;
    const int mBase = blockIdx.y << 7, nBase = blockIdx.x << 7;
    const int wm = wid & 3, wn = wid >> 2;

    float acc[2][4][4];
#pragma unroll
    for (int t = 0; t < 2; t++)
#pragma unroll
        for (int j = 0; j < 4; j++)
#pragma unroll
            for (int q = 0; q < 4; q++) acc[t][j][q] = 0.f;

    const int total = nPasses * 8;
    const int rowIdx = tid >> 3, col16 = tid & 7;

    auto issue = [&](int idx) {
        const int p = idx >> 3, c8 = idx & 7;
        const int shift = (p == 0) ? s0 : ((p == 1) ? s1 : s2);
        const size_t wOff = (size_t)p * DD + (size_t)(mBase >> 10) * wLayerStride;
        const uint32_t sb = smb + (uint32_t)(idx % 3) * STAGE_B;
        const int kOff = c8 * 64 + col16 * 8;
#pragma unroll
        for (int c = 0; c < 2; c++) {
            const int row = rowIdx + c * 64;
            const uint32_t dsw = swz((uint32_t)(row * 128 + col16 * 16));
            const int m = mBase + row;
            const int l = m & (Lsz - 1);
            const bool valid = ((unsigned)(l + shift) < (unsigned)Lsz);
            const size_t aoff = (size_t)(m + (valid ? shift : 0)) * Dsz + kOff;
            cp16(sb + dsw, Ah + aoff, valid);
            cp16(sb + 16384 + dsw, Al + aoff, valid);
            const size_t woff = wOff + (size_t)(nBase + row) * Dsz + kOff;
            cp16(sb + 32768 + dsw, Wh + woff, true);
            cp16(sb + 49152 + dsw, Wl + woff, true);
        }
        CP_COMMIT();
    };

    issue(0);
    if (total > 1) issue(1);
    for (int idx = 0; idx < total; idx++) {
        if (idx + 1 < total) {
            asm volatile("cp.async.wait_group 1;" ::: "memory");
        } else {
            asm volatile("cp.async.wait_group 0;" ::: "memory");
        }
        __syncthreads();
        if (idx + 2 < total) issue(idx + 2);
        const uint32_t sb = smb + (uint32_t)(idx % 3) * STAGE_B;
#pragma unroll
        for (int kk = 0; kk < 4; kk++) {
            uint32_t ah[2][4], al[2][4];
#pragma unroll
            for (int t = 0; t < 2; t++) {
                const int row = wm * 32 + t * 16 + (lane & 15);
                const uint32_t off =
                    swz((uint32_t)(row * 128 + kk * 32 + (lane >> 4) * 16));
                LDSM_X4(ah[t], sb + off);
                LDSM_X4(al[t], sb + 16384 + off);
            }
#pragma unroll
            for (int jp = 0; jp < 2; jp++) {
                const int nrow = wn * 32 + jp * 16 + (lane & 7) + ((lane >> 4) << 3);
                const uint32_t off =
                    swz((uint32_t)(nrow * 128 + kk * 32 + ((lane >> 3) & 1) * 16));
                uint32_t bh[4], bl[4];
                LDSM_X4(bh, sb + 32768 + off);
                LDSM_X4(bl, sb + 49152 + off);
#pragma unroll
                for (int t = 0; t < 2; t++) {
#pragma unroll
                    for (int jj = 0; jj < 2; jj++) {
                        float* d = acc[t][jp * 2 + jj];
                        MMA_BF16(d, ah[t], bh[jj * 2], bh[jj * 2 + 1]);
                        MMA_BF16(d, ah[t], bl[jj * 2], bl[jj * 2 + 1]);
                        MMA_BF16(d, al[t], bh[jj * 2], bh[jj * 2 + 1]);
                    }
                }
            }
        }
    }

    const bool addB = (flags & 1) != 0;
    const bool accum = (flags & 2) != 0;
    const bool splitO = (flags & 4) != 0;
    const bool gateDot = (flags & 8) != 0;
    const bool onehot = (flags & 16) != 0;
#pragma unroll
    for (int t = 0; t < 2; t++) {
        const int r0 = mBase + wm * 32 + t * 16 + (lane >> 2);
        float p0 = 0.f, p1 = 0.f;
#pragma unroll
        for (int j = 0; j < 4; j++) {
            const int col = nBase + wn * 32 + j * 8 + (lane & 3) * 2;
            float b0 = 0.f, b1 = 0.f;
            if (addB) { b0 = bias[col]; b1 = bias[col + 1]; }
            float v0 = acc[t][j][0] + b0, v1 = acc[t][j][1] + b1;
            float v2 = acc[t][j][2] + b0, v3 = acc[t][j][3] + b1;
            const size_t o0 = (size_t)r0 * N + col;
            const size_t o1 = (size_t)(r0 + 8) * N + col;
            if (splitO) {
                __nv_bfloat162 h, lo;
                split2(v0, v1, h, lo);
                *(__nv_bfloat162*)(Ch + o0) = h;
                *(__nv_bfloat162*)(Cl + o0) = lo;
                split2(v2, v3, h, lo);
                *(__nv_bfloat162*)(Ch + o1) = h;
                *(__nv_bfloat162*)(Cl + o1) = lo;
            } else {
                if (onehot) {
                    const int t0 = xTok[r0], t1 = xTok[r0 + 8];
                    v0 += (col == t0) ? 1.f : 0.f;
                    v1 += (col + 1 == t0) ? 1.f : 0.f;
                    v2 += (col == t1) ? 1.f : 0.f;
                    v3 += (col + 1 == t1) ? 1.f : 0.f;
                }
                if (accum) {
                    float2 q0 = *(float2*)(Cf + o0);
                    float2 q1 = *(float2*)(Cf + o1);
                    v0 += q0.x; v1 += q0.y; v2 += q1.x; v3 += q1.y;
                }
                *(float2*)(Cf + o0) = make_float2(v0, v1);
                *(float2*)(Cf + o1) = make_float2(v2, v3);
            }
            if (gateDot) {
                const float w0 = __ldg(wgv + col), w1 = __ldg(wgv + col + 1);
                p0 = fmaf(v0, w0, fmaf(v1, w1, p0));
                p1 = fmaf(v2, w0, fmaf(v3, w1, p1));
            }
        }
        if (gateDot) {
            p0 += __shfl_xor_sync(0xffffffffu, p0, 1);
            p0 += __shfl_xor_sync(0xffffffffu, p0, 2);
            p1 += __shfl_xor_sync(0xffffffffu, p1, 1);
            p1 += __shfl_xor_sync(0xffffffffu, p1, 2);
            if ((lane & 3) == 0) {
                float* gp = gateOut + ((size_t)((nBase >> 7) * 4 + wn)) * Tsz;
                gp[r0] = p0;
                gp[r0 + 8] = p1;
            }
        }
    }
}

// ============================================================================
// Fused fc(+folded wout) + gated-MLP GEMM, 512 threads.
// ============================================================================
#define FC_STAGE 98304
#define FCSMEM (2 * FC_STAGE)

__global__ __launch_bounds__(512, 1)
void mma_fc_k(const __nv_bfloat16* __restrict__ Ah, const __nv_bfloat16* __restrict__ Al,
              const __nv_bfloat16* __restrict__ Wh, const __nv_bfloat16* __restrict__ Wl,
              const float* __restrict__ bias,
              __nv_bfloat16* __restrict__ Oh, __nv_bfloat16* __restrict__ Ol) {
    extern __shared__ char smem[];
    const uint32_t smb = smem_u32(smem);
    const int tid = threadIdx.x, lane = tid & 31, wid = tid >> 5;
    const int mBase = blockIdx.y << 7, nBase = blockIdx.x << 7;
    const int wm = wid & 3, wn = wid >> 2;

    float accg[2][4][4], accv[2][4][4];
#pragma unroll
    for (int t = 0; t < 2; t++)
#pragma unroll
        for (int j = 0; j < 4; j++)
#pragma unroll
            for (int q = 0; q < 4; q++) { accg[t][j][q] = 0.f; accv[t][j][q] = 0.f; }

    const int rowIdx = tid >> 3, col16 = tid & 7;

    auto issue = [&](int idx) {
        const int c8 = idx & 7;
        const uint32_t sb = smb + (uint32_t)(idx & 1) * FC_STAGE;
        const int kOff = c8 * 64 + col16 * 8;
#pragma unroll
        for (int c = 0; c < 2; c++) {
            const int row = rowIdx + c * 64;
            const uint32_t dsw = swz((uint32_t)(row * 128 + col16 * 16));
            const size_t aoff = (size_t)(mBase + row) * Dsz + kOff;
            cp16(sb + dsw, Ah + aoff, true);
            cp16(sb + 16384 + dsw, Al + aoff, true);
            const size_t wgoff = (size_t)(nBase + row) * Dsz + kOff;
            cp16(sb + 32768 + dsw, Wh + wgoff, true);
            cp16(sb + 49152 + dsw, Wl + wgoff, true);
            const size_t wvoff = (size_t)(512 + nBase + row) * Dsz + kOff;
            cp16(sb + 65536 + dsw, Wh + wvoff, true);
            cp16(sb + 81920 + dsw, Wl + wvoff, true);
        }
        CP_COMMIT();
    };

    issue(0);
    for (int idx = 0; idx < 8; idx++) {
        asm volatile("cp.async.wait_group 0;" ::: "memory");
        __syncthreads();
        if (idx + 1 < 8) issue(idx + 1);
        const uint32_t sb = smb + (uint32_t)(idx & 1) * FC_STAGE;
#pragma unroll
        for (int kk = 0; kk < 4; kk++) {
            uint32_t ah[2][4], al[2][4];
#pragma unroll
            for (int t = 0; t < 2; t++) {
                const int row = wm * 32 + t * 16 + (lane & 15);
                const uint32_t off =
                    swz((uint32_t)(row * 128 + kk * 32 + (lane >> 4) * 16));
                LDSM_X4(ah[t], sb + off);
                LDSM_X4(al[t], sb + 16384 + off);
            }
#pragma unroll
            for (int jp = 0; jp < 2; jp++) {
                const int nrow = wn * 32 + jp * 16 + (lane & 7) + ((lane >> 4) << 3);
                const uint32_t off =
                    swz((uint32_t)(nrow * 128 + kk * 32 + ((lane >> 3) & 1) * 16));
                {
                    uint32_t bh[4], bl[4];
                    LDSM_X4(bh, sb + 32768 + off);
                    LDSM_X4(bl, sb + 49152 + off);
#pragma unroll
                    for (int t = 0; t < 2; t++)
#pragma unroll
                        for (int jj = 0; jj < 2; jj++) {
                            float* d = accg[t][jp * 2 + jj];
                            MMA_BF16(d, ah[t], bh[jj * 2], bh[jj * 2 + 1]);
                            MMA_BF16(d, ah[t], bl[jj * 2], bl[jj * 2 + 1]);
                            MMA_BF16(d, al[t], bh[jj * 2], bh[jj * 2 + 1]);
                        }
                }
                {
                    uint32_t bh[4], bl[4];
                    LDSM_X4(bh, sb + 65536 + off);
                    LDSM_X4(bl, sb + 81920 + off);
#pragma unroll
                    for (int t = 0; t < 2; t++)
#pragma unroll
                        for (int jj = 0; jj < 2; jj++) {
                            float* d = accv[t][jp * 2 + jj];
                            MMA_BF16(d, ah[t], bh[jj * 2], bh[jj * 2 + 1]);
                            MMA_BF16(d, ah[t], bl[jj * 2], bl[jj * 2 + 1]);
                            MMA_BF16(d, al[t], bh[jj * 2], bh[jj * 2 + 1]);
                        }
                }
            }
        }
    }

#pragma unroll
    for (int t = 0; t < 2; t++) {
#pragma unroll
        for (int j = 0; j < 4; j++) {
            const int r0 = mBase + wm * 32 + t * 16 + (lane >> 2);
            const int col = nBase + wn * 32 + j * 8 + (lane & 3) * 2;
            const float bg0 = bias[col], bg1 = bias[col + 1];
            const float bv0 = bias[512 + col], bv1 = bias[512 + col + 1];
            float s0 = 1.f / (1.f + expf(-(accg[t][j][0] + bg0)));
            float s1 = 1.f / (1.f + expf(-(accg[t][j][1] + bg1)));
            float s2 = 1.f / (1.f + expf(-(accg[t][j][2] + bg0)));
            float s3 = 1.f / (1.f + expf(-(accg[t][j][3] + bg1)));
            float v0 = s0 * (accv[t][j][0] + bv0);
            float v1 = s1 * (accv[t][j][1] + bv1);
            float v2 = s2 * (accv[t][j][2] + bv0);
            float v3 = s3 * (accv[t][j][3] + bv1);
            const size_t o0 = (size_t)r0 * Dsz + col;
            const size_t o1 = (size_t)(r0 + 8) * Dsz + col;
            __nv_bfloat162 h, lo;
            split2(v0, v1, h, lo);
            *(__nv_bfloat162*)(Oh + o0) = h;
            *(__nv_bfloat162*)(Ol + o0) = lo;
            split2(v2, v3, h, lo);
            *(__nv_bfloat162*)(Oh + o1) = h;
            *(__nv_bfloat162*)(Ol + o1) = lo;
        }
    }
}

// ============================================================================
// Layer-0 conv as gather (exact fp32) + fused gate.
// ============================================================================
__global__ void conv0_k(const int* __restrict__ x, const float* __restrict__ w0t,
                        const float* __restrict__ u0, const float* __restrict__ cb,
                        const float* __restrict__ lng, const float* __restrict__ wgv,
                        const float* __restrict__ bg,
                        float* __restrict__ z2, float* __restrict__ gt) {
    const int t = blockIdx.x, tid = threadIdx.x;
    const int l = t & (Lsz - 1);
    const float mean = 1.0f / 512.0f;
    const float rstd = rsqrtf(mean * (511.0f / 512.0f) + 1e-5f);

    const int tokm = (l > 0) ? x[t - 1] : -1;
    const int tok0 = x[t];
    const int tokp = (l < Lsz - 1) ? x[t + 1] : -1;

    float4 acc = ((const float4*)cb)[tid];
    {
        const float s = rstd * lng[tok0];
        float4 w = ((const float4*)(w0t + (size_t)DD + (size_t)tok0 * Dsz))[tid];
        float4 u = ((const float4*)(u0 + Dsz))[tid];
        acc.x += s * w.x + u.x; acc.y += s * w.y + u.y;
        acc.z += s * w.z + u.z; acc.w += s * w.w + u.w;
    }
    if (tokm >= 0) {
        const float s = rstd * lng[tokm];
        float4 w = ((const float4*)(w0t + (size_t)tokm * Dsz))[tid];
        float4 u = ((const float4*)u0)[tid];
        acc.x += s * w.x + u.x; acc.y += s * w.y + u.y;
        acc.z += s * w.z + u.z; acc.w += s * w.w + u.w;
    }
    if (tokp >= 0) {
        const float s = rstd * lng[tokp];
        float4 w = ((const float4*)(w0t + (size_t)2 * DD + (size_t)tokp * Dsz))[tid];
        float4 u = ((const float4*)(u0 + 2 * Dsz))[tid];
        acc.x += s * w.x + u.x; acc.y += s * w.y + u.y;
        acc.z += s * w.z + u.z; acc.w += s * w.w + u.w;
    }
    ((float4*)(z2 + (size_t)t * Dsz))[tid] = acc;

    float4 wv = ((const float4*)wgv)[tid];
    float p = acc.x * wv.x + acc.y * wv.y + acc.z * wv.z + acc.w * wv.w;
#pragma unroll
    for (int o = 16; o; o >>= 1) p += __shfl_xor_sync(0xffffffffu, p, o);
    __shared__ float smr[4];
    if ((tid & 31) == 0) smr[tid >> 5] = p;
    __syncthreads();
    if (tid == 0) {
        float s = smr[0] + smr[1] + smr[2] + smr[3];
        gt[t] = 1.0f / (1.0f + expf(-(s + bg[0])));
    }
}

// ---------------- layer-0 conv prep ------------------------------------------
__global__ void w0t_k(const float* __restrict__ cw, float* __restrict__ w0t) {
    int idx = blockIdx.x * blockDim.x + threadIdx.x;
    int h = idx / DD;
    int r = idx - h * DD;
    int i = r >> 9, o = r & 511;
    w0t[idx] = cw[((size_t)o * Dsz + i) * 3 + h];
}
__global__ void u0_k(const float* __restrict__ cw, const float* __restrict__ lng,
                     const float* __restrict__ lnb, float* __restrict__ u0) {
    int w = (blockIdx.x * blockDim.x + threadIdx.x) >> 5;
    int lane = threadIdx.x & 31;
    int h = w >> 9, o = w & 511;
    const float mean = 1.0f / 512.0f;
    const float rstd = rsqrtf(mean * (511.0f / 512.0f) + 1e-5f);
    float s = 0.f;
#pragma unroll
    for (int c = 0; c < 16; c++) {
        int i = lane + 32 * c;
        float v = lnb[i] - rstd * mean * lng[i];
        s = fmaf(cw[((size_t)o * Dsz + i) * 3 + h], v, s);
    }
#pragma unroll
    for (int ofs = 16; ofs; ofs >>= 1) s += __shfl_xor_sync(0xffffffffu, s, ofs);
    if (lane == 0) u0[w] = s;
}

// ---------------- layernorm with fused bf16 hi/lo split ----------------------
__global__ void ln_split_k(const float* __restrict__ in,
                           __nv_bfloat16* __restrict__ oh, __nv_bfloat16* __restrict__ ol,
                           const float* __restrict__ gamma, const float* __restrict__ beta) {
    int t = blockIdx.x, tid = threadIdx.x;
    const float4* rp = (const float4*)(in + (size_t)t * Dsz);
    float4 v = rp[tid];
    float s = v.x + v.y + v.z + v.w;
#pragma unroll
    for (int o = 16; o; o >>= 1) s += __shfl_xor_sync(0xffffffffu, s, o);
    __shared__ float smr[4];
    if ((tid & 31) == 0) smr[tid >> 5] = s;
    __syncthreads();
    float mean = (smr[0] + smr[1] + smr[2] + smr[3]) * (1.0f / Dsz);
    float dx = v.x - mean, dy = v.y - mean, dz = v.z - mean, dw = v.w - mean;
    float q = dx * dx + dy * dy + dz * dz + dw * dw;
#pragma unroll
    for (int o = 16; o; o >>= 1) q += __shfl_xor_sync(0xffffffffu, q, o);
    __syncthreads();
    if ((tid & 31) == 0) smr[tid >> 5] = q;
    __syncthreads();
    float var = (smr[0] + smr[1] + smr[2] + smr[3]) * (1.0f / Dsz);
    float rstd = rsqrtf(var + 1e-5f);
    float4 g4 = ((const float4*)gamma)[tid];
    float4 b4 = ((const float4*)beta)[tid];
    float f0 = dx * rstd * g4.x + b4.x, f1 = dy * rstd * g4.y + b4.y;
    float f2 = dz * rstd * g4.z + b4.z, f3 = dw * rstd * g4.w + b4.w;
    __nv_bfloat162 h01, l01, h23, l23;
    split2(f0, f1, h01, l01);
    split2(f2, f3, h23, l23);
    __nv_bfloat162* ph = (__nv_bfloat162*)(oh + (size_t)t * Dsz);
    __nv_bfloat162* pl = (__nv_bfloat162*)(ol + (size_t)t * Dsz);
    ph[2 * tid] = h01; ph[2 * tid + 1] = h23;
    pl[2 * tid] = l01; pl[2 * tid + 1] = l23;
}

// ---------------- conv weight repack + split (+ scan flag reset) --------------
__global__ void cwsplit_k(const float* __restrict__ cw,
                          __nv_bfloat16* __restrict__ wh, __nv_bfloat16* __restrict__ wl) {
    int idx = blockIdx.x * blockDim.x + threadIdx.x;
    if (idx < NFLAGS) g_sflag[idx] = 0;   // reset scan chain flags every call
    int layer = idx / (3 * DD);
    int r = idx - layer * (3 * DD);
    int h = r / DD;
    int rr = r - h * DD;
    int o = rr >> 9, i = rr & 511;
    float v = cw[(size_t)layer * 3 * DD + ((size_t)o * Dsz + i) * 3 + h];
    __nv_bfloat16 hi = __float2bfloat16(v);
    wh[idx] = hi;
    wl[idx] = __float2bfloat16(v - __bfloat162float(hi));
}

// ---------------- generic weight split ---------------------------------------
__global__ void wsplit_k(const float* __restrict__ w, __nv_bfloat16* __restrict__ wh,
                         __nv_bfloat16* __restrict__ wl, int n) {
    int idx = blockIdx.x * blockDim.x + threadIdx.x;
    if (idx >= n) return;
    float v = w[idx];
    __nv_bfloat16 hi = __float2bfloat16(v);
    wh[idx] = hi;
    wl[idx] = __float2bfloat16(v - __bfloat162float(hi));
}

// ---------------- transpose-split --------------------------------------------
__global__ void wsplit_t_k(const float* __restrict__ w, __nv_bfloat16* __restrict__ wh,
                           __nv_bfloat16* __restrict__ wl) {
    int idx = blockIdx.x * blockDim.x + threadIdx.x;
    int layer = idx / DD;
    int r = idx - layer * DD;
    int n = r >> 9, k = r & 511;
    float v = w[(size_t)layer * DD + (size_t)k * Dsz + n];
    __nv_bfloat16 hi = __float2bfloat16(v);
    wh[idx] = hi;
    wl[idx] = __float2bfloat16(v - __bfloat162float(hi));
}

// ---------------- bcomb = Wf·bo + fb ------------------------------------------
__global__ void bcomb_k(const float* __restrict__ fw, const float* __restrict__ bo,
                        const float* __restrict__ fb, float* __restrict__ out) {
    int w = (blockIdx.x * blockDim.x + threadIdx.x) >> 5;
    int lane = threadIdx.x & 31;
    int layer = w >> 10, e = w & 1023;
    const float* fr = fw + ((size_t)layer * 1024 + e) * Dsz;
    const float* br = bo + (size_t)layer * Dsz;
    float s = 0.f;
#pragma unroll
    for (int i = 0; i < 16; i++) s = fmaf(fr[lane + 32 * i], br[lane + 32 * i], s);
#pragma unroll
    for (int o = 16; o; o >>= 1) s += __shfl_xor_sync(0xffffffffu, s, o);
    if (lane == 0) out[w] = s + fb[(size_t)layer * 1024 + e];
}

// ============================================================================
// Unified chained scan: local scan + flag-chained carry + bf16-split output.
// Flags are zeroed at the start of every kernel_launch call (in cwsplit_k),
// so replays are deterministic. Entire grid is co-resident -> no deadlock.
// ============================================================================
__global__ void scan_u_k(const float* __restrict__ z2,
                         const float* __restrict__ gatep,
                         const float* __restrict__ gt0,
                         const float* __restrict__ bgp,
                         float* __restrict__ hfin, int* __restrict__ flags,
                         __nv_bfloat16* __restrict__ hh, __nv_bfloat16* __restrict__ hl) {
    const int bx = blockIdx.x;                 // c*64 + b*4 + dch
    const int c = bx >> 6, b = (bx >> 2) & 15, dch = bx & 3;
    const int tid = threadIdx.x;
    const int d = (dch << 7) + tid;
    const int l0 = c * SCH;
    __shared__ float gsm[SCH];

    if (gt0) {
        for (int j = tid; j < SCH; j += 128)
            gsm[j] = gt0[b * Lsz + l0 + j];
    } else {
        const float bgv = bgp[0];
        for (int j = tid; j < SCH; j += 128) {
            const int t = b * Lsz + l0 + j;
            float s = 0.f;
#pragma unroll
            for (int p = 0; p < 16; p++) s += gatep[(size_t)p * Tsz + t];
            gsm[j] = 1.0f / (1.0f + expf(-(s + bgv)));
        }
    }
    __syncthreads();

    const size_t base = (size_t)b * Lsz * Dsz + (size_t)l0 * Dsz + d;
    // pass 1: local chunk-end state + decay product
    float hv = 0.f, ap = 1.f;
    for (int l = 0; l < SCH; l += 8) {
        float xs[8], gs[8];
#pragma unroll
        for (int j = 0; j < 8; j++) {
            xs[j] = z2[base + (size_t)(l + j) * Dsz];
            gs[j] = gsm[l + j];
        }
#pragma unroll
        for (int j = 0; j < 8; j++) {
            hv = fmaf(gs[j], xs[j] - hv, hv);
            ap *= (1.f - gs[j]);
        }
    }
    // chained carry
    float carry = 0.f;
    const size_t fo = (size_t)c * (Bsz * Dsz) + (size_t)b * Dsz + d;
    if (c > 0) {
        if (tid == 0) {
            volatile int* f = flags + (bx - 64);
            while (*f == 0) {}
        }
        __syncthreads();
        __threadfence();
        carry = __ldcg(hfin + fo - (size_t)(Bsz * Dsz));
    }
    hfin[fo] = hv + ap * carry;   // inclusive chunk-end state
    __syncthreads();
    __threadfence();
    if (tid == 0) *((volatile int*)(flags + bx)) = 1;

    // pass 2: full scan with carry, split-bf16 output (z2 re-read is L2-hot)
    hv = carry;
    for (int l = 0; l < SCH; l += 8) {
        float xs[8], gs[8];
#pragma unroll
        for (int j = 0; j < 8; j++) {
            xs[j] = z2[base + (size_t)(l + j) * Dsz];
            gs[j] = gsm[l + j];
        }
#pragma unroll
        for (int j = 0; j < 8; j++) {
            hv = fmaf(gs[j], xs[j] - hv, hv);
            __nv_bfloat16 hi = __float2bfloat16(hv);
            size_t o = base + (size_t)(l + j) * Dsz;
            hh[o] = hi;
            hl[o] = __float2bfloat16(hv - __bfloat162float(hi));
        }
    }
}

// ---------------- launch --------------------------------------------------------
extern "C" void kernel_launch(void* const* d_in, const int* in_sizes, int n_in,
                              void* d_out, int out_size) {
    const int* x = (const int*)d_in[0];
    const float* ln_g = (const float*)d_in[1];
    const float* ln_b = (const float*)d_in[2];
    const float* conv_w = (const float*)d_in[3];
    const float* conv_b = (const float*)d_in[4];
    const float* wg = (const float*)d_in[5];
    const float* bg = (const float*)d_in[6];
    const float* wout = (const float*)d_in[7];
    const float* bout = (const float*)d_in[8];
    const float* fc_w = (const float*)d_in[9];
    const float* fc_b = (const float*)d_in[10];
    const float* mo_w = (const float*)d_in[11];
    const float* mo_b = (const float*)d_in[12];
    const float* lnf_g = (const float*)d_in[13];
    const float* lnf_b = (const float*)d_in[14];
    const float* head_w = (const float*)d_in[15];
    const float* head_b = (const float*)d_in[16];

    float *y, *z2, *gt, *gp, *bcomb, *hfin, *w0t, *u0;
    int* sflag;
    __nv_bfloat16 *zh, *zl, *hh, *hl, *gh, *gl, *wh, *wl;
    cudaGetSymbolAddress((void**)&y, g_y);
    cudaGetSymbolAddress((void**)&z2, g_z2);
    cudaGetSymbolAddress((void**)&gt, g_gate);
    cudaGetSymbolAddress((void**)&gp, g_gatep);
    cudaGetSymbolAddress((void**)&bcomb, g_bcomb);
    cudaGetSymbolAddress((void**)&hfin, g_hfin);
    cudaGetSymbolAddress((void**)&sflag, g_sflag);
    cudaGetSymbolAddress((void**)&w0t, g_w0t);
    cudaGetSymbolAddress((void**)&u0, g_u0);
    cudaGetSymbolAddress((void**)&zh, g_zh);
    cudaGetSymbolAddress((void**)&zl, g_zl);
    cudaGetSymbolAddress((void**)&hh, g_hh);
    cudaGetSymbolAddress((void**)&hl, g_hl);
    cudaGetSymbolAddress((void**)&gh, g_gh);
    cudaGetSymbolAddress((void**)&gl, g_gl);
    cudaGetSymbolAddress((void**)&wh, g_wh);
    cudaGetSymbolAddress((void**)&wl, g_wl);

    cudaFuncSetAttribute(mma_gemm_k, cudaFuncAttributeMaxDynamicSharedMemorySize, GSMEM);
    cudaFuncSetAttribute(mma_fc_k, cudaFuncAttributeMaxDynamicSharedMemorySize, FCSMEM);

    const dim3 g512(4, Tsz / 128);

    // ---- one-time per call: weight splits (also resets scan flags), folding ----
    cwsplit_k<<<(NLsz * 3 * DD) / 256, 256>>>(conv_w, wh + W_CONV(0), wl + W_CONV(0));
    wsplit_k<<<(NLsz * 2 * DD) / 256, 256>>>(fc_w, wh + W_FC(0), wl + W_FC(0), NLsz * 2 * DD);
    wsplit_t_k<<<(NLsz * DD) / 256, 256>>>(wout, wh + W_WOUT(0), wl + W_WOUT(0));
    wsplit_k<<<(NLsz * DD) / 256, 256>>>(mo_w, wh + W_MO(0), wl + W_MO(0), NLsz * DD);
    wsplit_k<<<DD / 256, 256>>>(head_w, wh + W_HEAD, wl + W_HEAD, DD);
    bcomb_k<<<(NLsz * 1024 * 32) / 256, 256>>>(fc_w, bout, fc_b, bcomb);
    w0t_k<<<(3 * DD) / 256, 256>>>(conv_w, w0t);
    u0_k<<<(3 * Dsz * 32) / 256, 256>>>(conv_w, ln_g, ln_b, u0);
    // Wcomb = Wf @ Wo  (batched over layers)
    mma_gemm_k<<<dim3(4, 32), 512, GSMEM>>>(wh + W_FC(0), wl + W_FC(0),
                                            wh + W_WOUT(0), wl + W_WOUT(0),
                                            nullptr, z2, nullptr, nullptr,
                                            nullptr, nullptr, nullptr,
                                            Dsz, 1, 0, 0, 0, 0, (int)DD);
    wsplit_k<<<(8 * DD) / 256, 256>>>(z2, wh + W_FC(0), wl + W_FC(0), 8 * DD);

    for (int i = 0; i < NLsz; i++) {
        if (i == 0) {
            conv0_k<<<Tsz, 128>>>(x, w0t, u0, conv_b, ln_g, wg, bg, z2, gt);
        } else {
            ln_split_k<<<Tsz, 128>>>(y, zh, zl, ln_g + (size_t)i * Dsz, ln_b + (size_t)i * Dsz);
            mma_gemm_k<<<g512, 512, GSMEM>>>(zh, zl, wh + W_CONV(i), wl + W_CONV(i),
                                             conv_b + (size_t)i * Dsz, z2, nullptr, nullptr,
                                             wg + (size_t)i * Dsz, nullptr, gp,
                                             Dsz, 3, -1, 0, 1, 1 | 8, 0);
        }
        // unified chained scan (gates inline for layers >=1)
        scan_u_k<<<NCH * 64, 128>>>(z2, gp, (i == 0) ? gt : nullptr, bg + i,
                                    hfin, sflag + (size_t)i * (NCH * Bsz * 4), hh, hl);
        mma_fc_k<<<g512, 512, FCSMEM>>>(hh, hl, wh + W_FC(i), wl + W_FC(i),
                                        bcomb + (size_t)i * 1024, gh, gl);
        mma_gemm_k<<<g512, 512, GSMEM>>>(gh, gl, wh + W_MO(i), wl + W_MO(i),
                                         mo_b + (size_t)i * Dsz, y, nullptr, nullptr,
                                         nullptr, (i == 0) ? x : nullptr, nullptr,
                                         Dsz, 1, 0, 0, 0, (i == 0) ? (1 | 16) : (1 | 2), 0);
    }

    ln_split_k<<<Tsz, 128>>>(y, zh, zl, lnf_g, lnf_b);
    mma_gemm_k<<<g512, 512, GSMEM>>>(zh, zl, wh + W_HEAD, wl + W_HEAD, head_b,
                                     (float*)d_out, nullptr, nullptr,
                                     nullptr, nullptr, nullptr, Dsz, 1, 0, 0, 0, 1, 0);
}

// round 11
// speedup vs baseline: 1.3342x; 1.3342x over previous
#include <cuda_runtime.h>
#include <cuda_fp16.h>
#include <cstdint>
#include <cstddef>

#define Bsz 16
#define Lsz 2048
#define Dsz 512
#define NLsz 4
#define Tsz (Bsz * Lsz)  // 32768
#define DD (Dsz * Dsz)

// weight arena offsets (units of DD)
#define W_CONV(i) ((size_t)(i) * 3 * DD)
#define W_WOUT(i) ((size_t)(12 + (i)) * DD)      // wout^T (prep only)
#define W_FC(i)   ((size_t)(16 + 2 * (i)) * DD)  // after prep: Wcomb = Wf@Wo
#define W_MO(i)   ((size_t)(24 + (i)) * DD)
#define W_HEAD    ((size_t)28 * DD)

// scan chunking
#define SCH 256
#define NCH (Lsz / SCH)  // 8
#define NFLAGS (NLsz * NCH * Bsz * 4)  // 2048

// ---------------- scratch (device globals; no allocation allowed) ----------
__device__ float g_y[Tsz * Dsz];
__device__ float g_z2[Tsz * Dsz];
__device__ float g_gate[Tsz];
__device__ float g_gatep[16 * Tsz];
__device__ float g_bcomb[NLsz * 2 * Dsz];
__device__ float g_hfin[NCH * Bsz * Dsz];
__device__ int   g_sflag[NFLAGS];
__device__ float g_w0t[3 * DD];
__device__ float g_u0[3 * Dsz];
__device__ __half g_zh[Tsz * Dsz], g_zl[Tsz * Dsz];
__device__ __half g_hh[Tsz * Dsz], g_hl[Tsz * Dsz];
__device__ __half g_gh[Tsz * Dsz], g_gl[Tsz * Dsz];   // also prep scratch
__device__ __half g_wh[29 * DD];                       // weights, 1-term fp16

// ---------------- helpers ---------------------------------------------------
__device__ __forceinline__ uint32_t smem_u32(const void* p) {
    return (uint32_t)__cvta_generic_to_shared(p);
}
__device__ __forceinline__ uint32_t swz(uint32_t x) { return x ^ ((x >> 3) & 0x70); }

__device__ __forceinline__ void cp16(uint32_t dst, const void* src, bool v) {
    int sz = v ? 16 : 0;
    asm volatile("cp.async.cg.shared.global [%0], [%1], 16, %2;"
                 :: "r"(dst), "l"(src), "r"(sz) : "memory");
}
#define CP_COMMIT() asm volatile("cp.async.commit_group;" ::: "memory")

#define LDSM_X4(r, a)                                                          \
    asm volatile("ldmatrix.sync.aligned.m8n8.x4.shared.b16 {%0,%1,%2,%3}, [%4];" \
                 : "=r"((r)[0]), "=r"((r)[1]), "=r"((r)[2]), "=r"((r)[3]) : "r"(a))

#define MMA_F16(d, a, b0, b1)                                                  \
    asm volatile(                                                              \
        "mma.sync.aligned.m16n8k16.row.col.f32.f16.f16.f32 "                   \
        "{%0,%1,%2,%3},{%4,%5,%6,%7},{%8,%9},{%0,%1,%2,%3};"                   \
        : "+f"((d)[0]), "+f"((d)[1]), "+f"((d)[2]), "+f"((d)[3])               \
        : "r"((a)[0]), "r"((a)[1]), "r"((a)[2]), "r"((a)[3]), "r"(b0), "r"(b1))

__device__ __forceinline__ void split2h(float a, float b, __half2& hi, __half2& lo) {
    hi = __floats2half2_rn(a, b);
    lo = __floats2half2_rn(a - __half2float(__low2half(hi)),
                           b - __half2float(__high2half(hi)));
}

// ============================================================================
// Generic GEMM, fp16: A 2-term split (exact), W 1-term. 512 threads, 128x128.
// Stage: Ah 16K | Al 16K | W 16K = 48KB. 3 stages.
// flags: 1=addBias, 2=accum fp32, 4=split fp16 out, 8=gate partials,
//        16=one-hot residual add.
// ============================================================================
#define STAGE_B 49152
#define GSMEM (3 * STAGE_B)

__global__ __launch_bounds__(512, 1)
void mma_gemm_k(const __half* __restrict__ Ah, const __half* __restrict__ Al,
                const __half* __restrict__ Wh,
                const float* __restrict__ bias, float* __restrict__ Cf,
                __half* __restrict__ Ch, __half* __restrict__ Cl,
                const float* __restrict__ wgv, const int* __restrict__ xTok,
                float* __restrict__ gateOut,
                int N, int nPasses, int s0, int s1, int s2, int flags,
                int wLayerStride) {
    extern __shared__ char smem[];
    const uint32_t smb = smem_u32(smem);
    const int tid = threadIdx.x, lane = tid & 31, wid = tid >> 5;
    const int mBase = blockIdx.y << 7, nBase = blockIdx.x << 7;
    const int wm = wid & 3, wn = wid >> 2;

    float acc[2][4][4];
#pragma unroll
    for (int t = 0; t < 2; t++)
#pragma unroll
        for (int j = 0; j < 4; j++)
#pragma unroll
            for (int q = 0; q < 4; q++) acc[t][j][q] = 0.f;

    const int total = nPasses * 8;
    const int rowIdx = tid >> 3, col16 = tid & 7;

    auto issue = [&](int idx) {
        const int p = idx >> 3, c8 = idx & 7;
        const int shift = (p == 0) ? s0 : ((p == 1) ? s1 : s2);
        const size_t wOff = (size_t)p * DD + (size_t)(mBase >> 10) * wLayerStride;
        const uint32_t sb = smb + (uint32_t)(idx % 3) * STAGE_B;
        const int kOff = c8 * 64 + col16 * 8;
#pragma unroll
        for (int c = 0; c < 2; c++) {
            const int row = rowIdx + c * 64;
            const uint32_t dsw = swz((uint32_t)(row * 128 + col16 * 16));
            const int m = mBase + row;
            const int l = m & (Lsz - 1);
            const bool valid = ((unsigned)(l + shift) < (unsigned)Lsz);
            const size_t aoff = (size_t)(m + (valid ? shift : 0)) * Dsz + kOff;
            cp16(sb + dsw, Ah + aoff, valid);
            cp16(sb + 16384 + dsw, Al + aoff, valid);
            const size_t woff = wOff + (size_t)(nBase + row) * Dsz + kOff;
            cp16(sb + 32768 + dsw, Wh + woff, true);
        }
        CP_COMMIT();
    };

    issue(0);
    if (total > 1) issue(1);
    for (int idx = 0; idx < total; idx++) {
        if (idx + 1 < total) {
            asm volatile("cp.async.wait_group 1;" ::: "memory");
        } else {
            asm volatile("cp.async.wait_group 0;" ::: "memory");
        }
        __syncthreads();
        if (idx + 2 < total) issue(idx + 2);
        const uint32_t sb = smb + (uint32_t)(idx % 3) * STAGE_B;
#pragma unroll
        for (int kk = 0; kk < 4; kk++) {
            uint32_t ah[2][4], al[2][4];
#pragma unroll
            for (int t = 0; t < 2; t++) {
                const int row = wm * 32 + t * 16 + (lane & 15);
                const uint32_t off =
                    swz((uint32_t)(row * 128 + kk * 32 + (lane >> 4) * 16));
                LDSM_X4(ah[t], sb + off);
                LDSM_X4(al[t], sb + 16384 + off);
            }
#pragma unroll
            for (int jp = 0; jp < 2; jp++) {
                const int nrow = wn * 32 + jp * 16 + (lane & 7) + ((lane >> 4) << 3);
                const uint32_t off =
                    swz((uint32_t)(nrow * 128 + kk * 32 + ((lane >> 3) & 1) * 16));
                uint32_t bh[4];
                LDSM_X4(bh, sb + 32768 + off);
#pragma unroll
                for (int t = 0; t < 2; t++) {
#pragma unroll
                    for (int jj = 0; jj < 2; jj++) {
                        float* d = acc[t][jp * 2 + jj];
                        MMA_F16(d, ah[t], bh[jj * 2], bh[jj * 2 + 1]);
                        MMA_F16(d, al[t], bh[jj * 2], bh[jj * 2 + 1]);
                    }
                }
            }
        }
    }

    const bool addB = (flags & 1) != 0;
    const bool accum = (flags & 2) != 0;
    const bool splitO = (flags & 4) != 0;
    const bool gateDot = (flags & 8) != 0;
    const bool onehot = (flags & 16) != 0;
#pragma unroll
    for (int t = 0; t < 2; t++) {
        const int r0 = mBase + wm * 32 + t * 16 + (lane >> 2);
        float p0 = 0.f, p1 = 0.f;
#pragma unroll
        for (int j = 0; j < 4; j++) {
            const int col = nBase + wn * 32 + j * 8 + (lane & 3) * 2;
            float b0 = 0.f, b1 = 0.f;
            if (addB) { b0 = bias[col]; b1 = bias[col + 1]; }
            float v0 = acc[t][j][0] + b0, v1 = acc[t][j][1] + b1;
            float v2 = acc[t][j][2] + b0, v3 = acc[t][j][3] + b1;
            const size_t o0 = (size_t)r0 * N + col;
            const size_t o1 = (size_t)(r0 + 8) * N + col;
            if (splitO) {
                __half2 h, lo;
                split2h(v0, v1, h, lo);
                *(__half2*)(Ch + o0) = h;
                *(__half2*)(Cl + o0) = lo;
                split2h(v2, v3, h, lo);
                *(__half2*)(Ch + o1) = h;
                *(__half2*)(Cl + o1) = lo;
            } else {
                if (onehot) {
                    const int t0 = xTok[r0], t1 = xTok[r0 + 8];
                    v0 += (col == t0) ? 1.f : 0.f;
                    v1 += (col + 1 == t0) ? 1.f : 0.f;
                    v2 += (col == t1) ? 1.f : 0.f;
                    v3 += (col + 1 == t1) ? 1.f : 0.f;
                }
                if (accum) {
                    float2 q0 = *(float2*)(Cf + o0);
                    float2 q1 = *(float2*)(Cf + o1);
                    v0 += q0.x; v1 += q0.y; v2 += q1.x; v3 += q1.y;
                }
                *(float2*)(Cf + o0) = make_float2(v0, v1);
                *(float2*)(Cf + o1) = make_float2(v2, v3);
            }
            if (gateDot) {
                const float w0 = __ldg(wgv + col), w1 = __ldg(wgv + col + 1);
                p0 = fmaf(v0, w0, fmaf(v1, w1, p0));
                p1 = fmaf(v2, w0, fmaf(v3, w1, p1));
            }
        }
        if (gateDot) {
            p0 += __shfl_xor_sync(0xffffffffu, p0, 1);
            p0 += __shfl_xor_sync(0xffffffffu, p0, 2);
            p1 += __shfl_xor_sync(0xffffffffu, p1, 1);
            p1 += __shfl_xor_sync(0xffffffffu, p1, 2);
            if ((lane & 3) == 0) {
                float* gp = gateOut + ((size_t)((nBase >> 7) * 4 + wn)) * Tsz;
                gp[r0] = p0;
                gp[r0 + 8] = p1;
            }
        }
    }
}

// ============================================================================
// Fused fc(+folded wout) + gated-MLP GEMM, fp16 A-split / W 1-term.
// Stage: Ah | Al | Wg | Wv = 64KB, 2 stages.
// ============================================================================
#define FC_STAGE 65536
#define FCSMEM (2 * FC_STAGE)

__global__ __launch_bounds__(512, 1)
void mma_fc_k(const __half* __restrict__ Ah, const __half* __restrict__ Al,
              const __half* __restrict__ Wh, const float* __restrict__ bias,
              __half* __restrict__ Oh, __half* __restrict__ Ol) {
    extern __shared__ char smem[];
    const uint32_t smb = smem_u32(smem);
    const int tid = threadIdx.x, lane = tid & 31, wid = tid >> 5;
    const int mBase = blockIdx.y << 7, nBase = blockIdx.x << 7;
    const int wm = wid & 3, wn = wid >> 2;

    float accg[2][4][4], accv[2][4][4];
#pragma unroll
    for (int t = 0; t < 2; t++)
#pragma unroll
        for (int j = 0; j < 4; j++)
#pragma unroll
            for (int q = 0; q < 4; q++) { accg[t][j][q] = 0.f; accv[t][j][q] = 0.f; }

    const int rowIdx = tid >> 3, col16 = tid & 7;

    auto issue = [&](int idx) {
        const int c8 = idx & 7;
        const uint32_t sb = smb + (uint32_t)(idx & 1) * FC_STAGE;
        const int kOff = c8 * 64 + col16 * 8;
#pragma unroll
        for (int c = 0; c < 2; c++) {
            const int row = rowIdx + c * 64;
            const uint32_t dsw = swz((uint32_t)(row * 128 + col16 * 16));
            const size_t aoff = (size_t)(mBase + row) * Dsz + kOff;
            cp16(sb + dsw, Ah + aoff, true);
            cp16(sb + 16384 + dsw, Al + aoff, true);
            const size_t wgoff = (size_t)(nBase + row) * Dsz + kOff;
            cp16(sb + 32768 + dsw, Wh + wgoff, true);
            const size_t wvoff = (size_t)(512 + nBase + row) * Dsz + kOff;
            cp16(sb + 49152 + dsw, Wh + wvoff, true);
        }
        CP_COMMIT();
    };

    issue(0);
    for (int idx = 0; idx < 8; idx++) {
        asm volatile("cp.async.wait_group 0;" ::: "memory");
        __syncthreads();
        if (idx + 1 < 8) issue(idx + 1);
        const uint32_t sb = smb + (uint32_t)(idx & 1) * FC_STAGE;
#pragma unroll
        for (int kk = 0; kk < 4; kk++) {
            uint32_t ah[2][4], al[2][4];
#pragma unroll
            for (int t = 0; t < 2; t++) {
                const int row = wm * 32 + t * 16 + (lane & 15);
                const uint32_t off =
                    swz((uint32_t)(row * 128 + kk * 32 + (lane >> 4) * 16));
                LDSM_X4(ah[t], sb + off);
                LDSM_X4(al[t], sb + 16384 + off);
            }
#pragma unroll
            for (int jp = 0; jp < 2; jp++) {
                const int nrow = wn * 32 + jp * 16 + (lane & 7) + ((lane >> 4) << 3);
                const uint32_t off =
                    swz((uint32_t)(nrow * 128 + kk * 32 + ((lane >> 3) & 1) * 16));
                {
                    uint32_t bh[4];
                    LDSM_X4(bh, sb + 32768 + off);
#pragma unroll
                    for (int t = 0; t < 2; t++)
#pragma unroll
                        for (int jj = 0; jj < 2; jj++) {
                            float* d = accg[t][jp * 2 + jj];
                            MMA_F16(d, ah[t], bh[jj * 2], bh[jj * 2 + 1]);
                            MMA_F16(d, al[t], bh[jj * 2], bh[jj * 2 + 1]);
                        }
                }
                {
                    uint32_t bh[4];
                    LDSM_X4(bh, sb + 49152 + off);
#pragma unroll
                    for (int t = 0; t < 2; t++)
#pragma unroll
                        for (int jj = 0; jj < 2; jj++) {
                            float* d = accv[t][jp * 2 + jj];
                            MMA_F16(d, ah[t], bh[jj * 2], bh[jj * 2 + 1]);
                            MMA_F16(d, al[t], bh[jj * 2], bh[jj * 2 + 1]);
                        }
                }
            }
        }
    }

#pragma unroll
    for (int t = 0; t < 2; t++) {
#pragma unroll
        for (int j = 0; j < 4; j++) {
            const int r0 = mBase + wm * 32 + t * 16 + (lane >> 2);
            const int col = nBase + wn * 32 + j * 8 + (lane & 3) * 2;
            const float bg0 = bias[col], bg1 = bias[col + 1];
            const float bv0 = bias[512 + col], bv1 = bias[512 + col + 1];
            float s0 = 1.f / (1.f + expf(-(accg[t][j][0] + bg0)));
            float s1 = 1.f / (1.f + expf(-(accg[t][j][1] + bg1)));
            float s2 = 1.f / (1.f + expf(-(accg[t][j][2] + bg0)));
            float s3 = 1.f / (1.f + expf(-(accg[t][j][3] + bg1)));
            float v0 = s0 * (accv[t][j][0] + bv0);
            float v1 = s1 * (accv[t][j][1] + bv1);
            float v2 = s2 * (accv[t][j][2] + bv0);
            float v3 = s3 * (accv[t][j][3] + bv1);
            const size_t o0 = (size_t)r0 * Dsz + col;
            const size_t o1 = (size_t)(r0 + 8) * Dsz + col;
            __half2 h, lo;
            split2h(v0, v1, h, lo);
            *(__half2*)(Oh + o0) = h;
            *(__half2*)(Ol + o0) = lo;
            split2h(v2, v3, h, lo);
            *(__half2*)(Oh + o1) = h;
            *(__half2*)(Ol + o1) = lo;
        }
    }
}

// ============================================================================
// Layer-0 conv as gather (exact fp32) + fused gate.
// ============================================================================
__global__ void conv0_k(const int* __restrict__ x, const float* __restrict__ w0t,
                        const float* __restrict__ u0, const float* __restrict__ cb,
                        const float* __restrict__ lng, const float* __restrict__ wgv,
                        const float* __restrict__ bg,
                        float* __restrict__ z2, float* __restrict__ gt) {
    const int t = blockIdx.x, tid = threadIdx.x;
    const int l = t & (Lsz - 1);
    const float mean = 1.0f / 512.0f;
    const float rstd = rsqrtf(mean * (511.0f / 512.0f) + 1e-5f);

    const int tokm = (l > 0) ? x[t - 1] : -1;
    const int tok0 = x[t];
    const int tokp = (l < Lsz - 1) ? x[t + 1] : -1;

    float4 acc = ((const float4*)cb)[tid];
    {
        const float s = rstd * lng[tok0];
        float4 w = ((const float4*)(w0t + (size_t)DD + (size_t)tok0 * Dsz))[tid];
        float4 u = ((const float4*)(u0 + Dsz))[tid];
        acc.x += s * w.x + u.x; acc.y += s * w.y + u.y;
        acc.z += s * w.z + u.z; acc.w += s * w.w + u.w;
    }
    if (tokm >= 0) {
        const float s = rstd * lng[tokm];
        float4 w = ((const float4*)(w0t + (size_t)tokm * Dsz))[tid];
        float4 u = ((const float4*)u0)[tid];
        acc.x += s * w.x + u.x; acc.y += s * w.y + u.y;
        acc.z += s * w.z + u.z; acc.w += s * w.w + u.w;
    }
    if (tokp >= 0) {
        const float s = rstd * lng[tokp];
        float4 w = ((const float4*)(w0t + (size_t)2 * DD + (size_t)tokp * Dsz))[tid];
        float4 u = ((const float4*)(u0 + 2 * Dsz))[tid];
        acc.x += s * w.x + u.x; acc.y += s * w.y + u.y;
        acc.z += s * w.z + u.z; acc.w += s * w.w + u.w;
    }
    ((float4*)(z2 + (size_t)t * Dsz))[tid] = acc;

    float4 wv = ((const float4*)wgv)[tid];
    float p = acc.x * wv.x + acc.y * wv.y + acc.z * wv.z + acc.w * wv.w;
#pragma unroll
    for (int o = 16; o; o >>= 1) p += __shfl_xor_sync(0xffffffffu, p, o);
    __shared__ float smr[4];
    if ((tid & 31) == 0) smr[tid >> 5] = p;
    __syncthreads();
    if (tid == 0) {
        float s = smr[0] + smr[1] + smr[2] + smr[3];
        gt[t] = 1.0f / (1.0f + expf(-(s + bg[0])));
    }
}

// ---------------- layer-0 conv prep ------------------------------------------
__global__ void w0t_k(const float* __restrict__ cw, float* __restrict__ w0t) {
    int idx = blockIdx.x * blockDim.x + threadIdx.x;
    int h = idx / DD;
    int r = idx - h * DD;
    int i = r >> 9, o = r & 511;
    w0t[idx] = cw[((size_t)o * Dsz + i) * 3 + h];
}
__global__ void u0_k(const float* __restrict__ cw, const float* __restrict__ lng,
                     const float* __restrict__ lnb, float* __restrict__ u0) {
    int w = (blockIdx.x * blockDim.x + threadIdx.x) >> 5;
    int lane = threadIdx.x & 31;
    int h = w >> 9, o = w & 511;
    const float mean = 1.0f / 512.0f;
    const float rstd = rsqrtf(mean * (511.0f / 512.0f) + 1e-5f);
    float s = 0.f;
#pragma unroll
    for (int c = 0; c < 16; c++) {
        int i = lane + 32 * c;
        float v = lnb[i] - rstd * mean * lng[i];
        s = fmaf(cw[((size_t)o * Dsz + i) * 3 + h], v, s);
    }
#pragma unroll
    for (int ofs = 16; ofs; ofs >>= 1) s += __shfl_xor_sync(0xffffffffu, s, ofs);
    if (lane == 0) u0[w] = s;
}

// ---------------- layernorm with fused fp16 hi/lo split ----------------------
__global__ void ln_split_k(const float* __restrict__ in,
                           __half* __restrict__ oh, __half* __restrict__ ol,
                           const float* __restrict__ gamma, const float* __restrict__ beta) {
    int t = blockIdx.x, tid = threadIdx.x;
    const float4* rp = (const float4*)(in + (size_t)t * Dsz);
    float4 v = rp[tid];
    float s = v.x + v.y + v.z + v.w;
#pragma unroll
    for (int o = 16; o; o >>= 1) s += __shfl_xor_sync(0xffffffffu, s, o);
    __shared__ float smr[4];
    if ((tid & 31) == 0) smr[tid >> 5] = s;
    __syncthreads();
    float mean = (smr[0] + smr[1] + smr[2] + smr[3]) * (1.0f / Dsz);
    float dx = v.x - mean, dy = v.y - mean, dz = v.z - mean, dw = v.w - mean;
    float q = dx * dx + dy * dy + dz * dz + dw * dw;
#pragma unroll
    for (int o = 16; o; o >>= 1) q += __shfl_xor_sync(0xffffffffu, q, o);
    __syncthreads();
    if ((tid & 31) == 0) smr[tid >> 5] = q;
    __syncthreads();
    float var = (smr[0] + smr[1] + smr[2] + smr[3]) * (1.0f / Dsz);
    float rstd = rsqrtf(var + 1e-5f);
    float4 g4 = ((const float4*)gamma)[tid];
    float4 b4 = ((const float4*)beta)[tid];
    float f0 = dx * rstd * g4.x + b4.x, f1 = dy * rstd * g4.y + b4.y;
    float f2 = dz * rstd * g4.z + b4.z, f3 = dw * rstd * g4.w + b4.w;
    __half2 h01, l01, h23, l23;
    split2h(f0, f1, h01, l01);
    split2h(f2, f3, h23, l23);
    __half2* ph = (__half2*)(oh + (size_t)t * Dsz);
    __half2* pl = (__half2*)(ol + (size_t)t * Dsz);
    ph[2 * tid] = h01; ph[2 * tid + 1] = h23;
    pl[2 * tid] = l01; pl[2 * tid + 1] = l23;
}

// ---------------- conv weight repack, 1-term fp16 (+ scan flag reset) ---------
__global__ void cwsplit_k(const float* __restrict__ cw, __half* __restrict__ wh) {
    int idx = blockIdx.x * blockDim.x + threadIdx.x;
    if (idx < NFLAGS) g_sflag[idx] = 0;   // reset scan chain flags every call
    int layer = idx / (3 * DD);
    int r = idx - layer * (3 * DD);
    int h = r / DD;
    int rr = r - h * DD;
    int o = rr >> 9, i = rr & 511;
    wh[idx] = __float2half_rn(cw[(size_t)layer * 3 * DD + ((size_t)o * Dsz + i) * 3 + h]);
}

// ---------------- generic 1-term fp16 convert ---------------------------------
__global__ void wsplit1_k(const float* __restrict__ w, __half* __restrict__ wh, int n) {
    int idx = blockIdx.x * blockDim.x + threadIdx.x;
    if (idx >= n) return;
    wh[idx] = __float2half_rn(w[idx]);
}

// ---------------- 2-term fp16 split (prep scratch) ----------------------------
__global__ void wsplit2_k(const float* __restrict__ w, __half* __restrict__ wh,
                          __half* __restrict__ wl, int n) {
    int idx = blockIdx.x * blockDim.x + threadIdx.x;
    if (idx >= n) return;
    float v = w[idx];
    __half hi = __float2half_rn(v);
    wh[idx] = hi;
    wl[idx] = __float2half_rn(v - __half2float(hi));
}

// ---------------- transpose 1-term: out[l][n*512+k] = w[l][k*512+n] -----------
__global__ void wsplit_t1_k(const float* __restrict__ w, __half* __restrict__ wh) {
    int idx = blockIdx.x * blockDim.x + threadIdx.x;
    int layer = idx / DD;
    int r = idx - layer * DD;
    int n = r >> 9, k = r & 511;
    wh[idx] = __float2half_rn(w[(size_t)layer * DD + (size_t)k * Dsz + n]);
}

// ---------------- bcomb = Wf·bo + fb ------------------------------------------
__global__ void bcomb_k(const float* __restrict__ fw, const float* __restrict__ bo,
                        const float* __restrict__ fb, float* __restrict__ out) {
    int w = (blockIdx.x * blockDim.x + threadIdx.x) >> 5;
    int lane = threadIdx.x & 31;
    int layer = w >> 10, e = w & 1023;
    const float* fr = fw + ((size_t)layer * 1024 + e) * Dsz;
    const float* br = bo + (size_t)layer * Dsz;
    float s = 0.f;
#pragma unroll
    for (int i = 0; i < 16; i++) s = fmaf(fr[lane + 32 * i], br[lane + 32 * i], s);
#pragma unroll
    for (int o = 16; o; o >>= 1) s += __shfl_xor_sync(0xffffffffu, s, o);
    if (lane == 0) out[w] = s + fb[(size_t)layer * 1024 + e];
}

// ============================================================================
// Unified chained scan (flags zeroed per call in cwsplit_k -> deterministic).
// ============================================================================
__global__ void scan_u_k(const float* __restrict__ z2,
                         const float* __restrict__ gatep,
                         const float* __restrict__ gt0,
                         const float* __restrict__ bgp,
                         float* __restrict__ hfin, int* __restrict__ flags,
                         __half* __restrict__ hh, __half* __restrict__ hl) {
    const int bx = blockIdx.x;
    const int c = bx >> 6, b = (bx >> 2) & 15, dch = bx & 3;
    const int tid = threadIdx.x;
    const int d = (dch << 7) + tid;
    const int l0 = c * SCH;
    __shared__ float gsm[SCH];

    if (gt0) {
        for (int j = tid; j < SCH; j += 128)
            gsm[j] = gt0[b * Lsz + l0 + j];
    } else {
        const float bgv = bgp[0];
        for (int j = tid; j < SCH; j += 128) {
            const int t = b * Lsz + l0 + j;
            float s = 0.f;
#pragma unroll
            for (int p = 0; p < 16; p++) s += gatep[(size_t)p * Tsz + t];
            gsm[j] = 1.0f / (1.0f + expf(-(s + bgv)));
        }
    }
    __syncthreads();

    const size_t base = (size_t)b * Lsz * Dsz + (size_t)l0 * Dsz + d;
    float hv = 0.f, ap = 1.f;
    for (int l = 0; l < SCH; l += 8) {
        float xs[8], gs[8];
#pragma unroll
        for (int j = 0; j < 8; j++) {
            xs[j] = z2[base + (size_t)(l + j) * Dsz];
            gs[j] = gsm[l + j];
        }
#pragma unroll
        for (int j = 0; j < 8; j++) {
            hv = fmaf(gs[j], xs[j] - hv, hv);
            ap *= (1.f - gs[j]);
        }
    }
    float carry = 0.f;
    const size_t fo = (size_t)c * (Bsz * Dsz) + (size_t)b * Dsz + d;
    if (c > 0) {
        if (tid == 0) {
            volatile int* f = flags + (bx - 64);
            while (*f == 0) {}
        }
        __syncthreads();
        __threadfence();
        carry = __ldcg(hfin + fo - (size_t)(Bsz * Dsz));
    }
    hfin[fo] = hv + ap * carry;
    __syncthreads();
    __threadfence();
    if (tid == 0) *((volatile int*)(flags + bx)) = 1;

    hv = carry;
    for (int l = 0; l < SCH; l += 8) {
        float xs[8], gs[8];
#pragma unroll
        for (int j = 0; j < 8; j++) {
            xs[j] = z2[base + (size_t)(l + j) * Dsz];
            gs[j] = gsm[l + j];
        }
#pragma unroll
        for (int j = 0; j < 8; j++) {
            hv = fmaf(gs[j], xs[j] - hv, hv);
            __half hi = __float2half_rn(hv);
            size_t o = base + (size_t)(l + j) * Dsz;
            hh[o] = hi;
            hl[o] = __float2half_rn(hv - __half2float(hi));
        }
    }
}

// ---------------- launch --------------------------------------------------------
extern "C" void kernel_launch(void* const* d_in, const int* in_sizes, int n_in,
                              void* d_out, int out_size) {
    const int* x = (const int*)d_in[0];
    const float* ln_g = (const float*)d_in[1];
    const float* ln_b = (const float*)d_in[2];
    const float* conv_w = (const float*)d_in[3];
    const float* conv_b = (const float*)d_in[4];
    const float* wg = (const float*)d_in[5];
    const float* bg = (const float*)d_in[6];
    const float* wout = (const float*)d_in[7];
    const float* bout = (const float*)d_in[8];
    const float* fc_w = (const float*)d_in[9];
    const float* fc_b = (const float*)d_in[10];
    const float* mo_w = (const float*)d_in[11];
    const float* mo_b = (const float*)d_in[12];
    const float* lnf_g = (const float*)d_in[13];
    const float* lnf_b = (const float*)d_in[14];
    const float* head_w = (const float*)d_in[15];
    const float* head_b = (const float*)d_in[16];

    float *y, *z2, *gt, *gp, *bcomb, *hfin, *w0t, *u0;
    int* sflag;
    __half *zh, *zl, *hh, *hl, *gh, *gl, *wh;
    cudaGetSymbolAddress((void**)&y, g_y);
    cudaGetSymbolAddress((void**)&z2, g_z2);
    cudaGetSymbolAddress((void**)&gt, g_gate);
    cudaGetSymbolAddress((void**)&gp, g_gatep);
    cudaGetSymbolAddress((void**)&bcomb, g_bcomb);
    cudaGetSymbolAddress((void**)&hfin, g_hfin);
    cudaGetSymbolAddress((void**)&sflag, g_sflag);
    cudaGetSymbolAddress((void**)&w0t, g_w0t);
    cudaGetSymbolAddress((void**)&u0, g_u0);
    cudaGetSymbolAddress((void**)&zh, g_zh);
    cudaGetSymbolAddress((void**)&zl, g_zl);
    cudaGetSymbolAddress((void**)&hh, g_hh);
    cudaGetSymbolAddress((void**)&hl, g_hl);
    cudaGetSymbolAddress((void**)&gh, g_gh);
    cudaGetSymbolAddress((void**)&gl, g_gl);
    cudaGetSymbolAddress((void**)&wh, g_wh);

    cudaFuncSetAttribute(mma_gemm_k, cudaFuncAttributeMaxDynamicSharedMemorySize, GSMEM);
    cudaFuncSetAttribute(mma_fc_k, cudaFuncAttributeMaxDynamicSharedMemorySize, FCSMEM);

    const dim3 g512(4, Tsz / 128);

    // ---- one-time per call: weight converts (+ flag reset), wout folding ----
    cwsplit_k<<<(NLsz * 3 * DD) / 256, 256>>>(conv_w, wh + W_CONV(0));
    // fc weights 2-term split into scratch (gh/gl) for the folding GEMM
    wsplit2_k<<<(NLsz * 2 * DD) / 256, 256>>>(fc_w, gh, gl, NLsz * 2 * DD);
    wsplit_t1_k<<<(NLsz * DD) / 256, 256>>>(wout, wh + W_WOUT(0));
    wsplit1_k<<<(NLsz * DD) / 256, 256>>>(mo_w, wh + W_MO(0), NLsz * DD);
    wsplit1_k<<<DD / 256, 256>>>(head_w, wh + W_HEAD, DD);
    bcomb_k<<<(NLsz * 1024 * 32) / 256, 256>>>(fc_w, bout, fc_b, bcomb);
    w0t_k<<<(3 * DD) / 256, 256>>>(conv_w, w0t);
    u0_k<<<(3 * Dsz * 32) / 256, 256>>>(conv_w, ln_g, ln_b, u0);
    // Wcomb = Wf @ Wo (batched over layers; A = fc split, W = wout^T 1-term)
    mma_gemm_k<<<dim3(4, 32), 512, GSMEM>>>(gh, gl, wh + W_WOUT(0),
                                            nullptr, z2, nullptr, nullptr,
                                            nullptr, nullptr, nullptr,
                                            Dsz, 1, 0, 0, 0, 0, (int)DD);
    wsplit1_k<<<(8 * DD) / 256, 256>>>(z2, wh + W_FC(0), 8 * DD);

    for (int i = 0; i < NLsz; i++) {
        if (i == 0) {
            conv0_k<<<Tsz, 128>>>(x, w0t, u0, conv_b, ln_g, wg, bg, z2, gt);
        } else {
            ln_split_k<<<Tsz, 128>>>(y, zh, zl, ln_g + (size_t)i * Dsz, ln_b + (size_t)i * Dsz);
            mma_gemm_k<<<g512, 512, GSMEM>>>(zh, zl, wh + W_CONV(i),
                                             conv_b + (size_t)i * Dsz, z2, nullptr, nullptr,
                                             wg + (size_t)i * Dsz, nullptr, gp,
                                             Dsz, 3, -1, 0, 1, 1 | 8, 0);
        }
        scan_u_k<<<NCH * 64, 128>>>(z2, gp, (i == 0) ? gt : nullptr, bg + i,
                                    hfin, sflag + (size_t)i * (NCH * Bsz * 4), hh, hl);
        mma_fc_k<<<g512, 512, FCSMEM>>>(hh, hl, wh + W_FC(i),
                                        bcomb + (size_t)i * 1024, gh, gl);
        mma_gemm_k<<<g512, 512, GSMEM>>>(gh, gl, wh + W_MO(i),
                                         mo_b + (size_t)i * Dsz, y, nullptr, nullptr,
                                         nullptr, (i == 0) ? x : nullptr, nullptr,
                                         Dsz, 1, 0, 0, 0, (i == 0) ? (1 | 16) : (1 | 2), 0);
    }

    ln_split_k<<<Tsz, 128>>>(y, zh, zl, lnf_g, lnf_b);
    mma_gemm_k<<<g512, 512, GSMEM>>>(zh, zl, wh + W_HEAD, head_b,
                                     (float*)d_out, nullptr, nullptr,
                                     nullptr, nullptr, nullptr, Dsz, 1, 0, 0, 0, 1, 0);
}

// round 12
// speedup vs baseline: 1.4018x; 1.0507x over previous
#include <cuda_runtime.h>
#include <cuda_fp16.h>
#include <cstdint>
#include <cstddef>

#define Bsz 16
#define Lsz 2048
#define Dsz 512
#define NLsz 4
#define Tsz (Bsz * Lsz)  // 32768
#define DD (Dsz * Dsz)

// weight arena offsets (units of DD)
#define W_CONV(i) ((size_t)(i) * 3 * DD)
#define W_WOUT(i) ((size_t)(12 + (i)) * DD)      // wout^T (prep only)
#define W_FC(i)   ((size_t)(16 + 2 * (i)) * DD)  // after prep: Wcomb = Wf@Wo
#define W_MO(i)   ((size_t)(24 + (i)) * DD)
#define W_HEAD    ((size_t)28 * DD)

// scan chunking
#define SCH 256
#define NCH (Lsz / SCH)  // 8
#define NFLAGS (NLsz * NCH * Bsz * 4)  // 2048

// ---------------- scratch (device globals; no allocation allowed) ----------
__device__ float g_y[Tsz * Dsz];
__device__ float g_z2[Tsz * Dsz];
__device__ float g_gate[Tsz];
__device__ float g_gatep[16 * Tsz];
__device__ float g_bcomb[NLsz * 2 * Dsz];
__device__ float g_hfin[NCH * Bsz * Dsz];
__device__ int   g_sflag[NFLAGS];
__device__ float g_w0t[3 * DD];
__device__ float g_u0[3 * Dsz];
__device__ __half g_zh[Tsz * Dsz], g_zl[Tsz * Dsz];
__device__ __half g_hh[Tsz * Dsz], g_hl[Tsz * Dsz];
__device__ __half g_gh[Tsz * Dsz], g_gl[Tsz * Dsz];   // also prep scratch
__device__ __half g_wh[29 * DD];                       // weights, 1-term fp16

// ---------------- helpers ---------------------------------------------------
__device__ __forceinline__ uint32_t smem_u32(const void* p) {
    return (uint32_t)__cvta_generic_to_shared(p);
}
__device__ __forceinline__ uint32_t swz(uint32_t x) { return x ^ ((x >> 3) & 0x70); }

__device__ __forceinline__ void cp16(uint32_t dst, const void* src, bool v) {
    int sz = v ? 16 : 0;
    asm volatile("cp.async.cg.shared.global [%0], [%1], 16, %2;"
                 :: "r"(dst), "l"(src), "r"(sz) : "memory");
}
#define CP_COMMIT() asm volatile("cp.async.commit_group;" ::: "memory")

#define LDSM_X4(r, a)                                                          \
    asm volatile("ldmatrix.sync.aligned.m8n8.x4.shared.b16 {%0,%1,%2,%3}, [%4];" \
                 : "=r"((r)[0]), "=r"((r)[1]), "=r"((r)[2]), "=r"((r)[3]) : "r"(a))

#define MMA_F16(d, a, b0, b1)                                                  \
    asm volatile(                                                              \
        "mma.sync.aligned.m16n8k16.row.col.f32.f16.f16.f32 "                   \
        "{%0,%1,%2,%3},{%4,%5,%6,%7},{%8,%9},{%0,%1,%2,%3};"                   \
        : "+f"((d)[0]), "+f"((d)[1]), "+f"((d)[2]), "+f"((d)[3])               \
        : "r"((a)[0]), "r"((a)[1]), "r"((a)[2]), "r"((a)[3]), "r"(b0), "r"(b1))

__device__ __forceinline__ void split2h(float a, float b, __half2& hi, __half2& lo) {
    hi = __floats2half2_rn(a, b);
    lo = __floats2half2_rn(a - __half2float(__low2half(hi)),
                           b - __half2float(__high2half(hi)));
}

// ============================================================================
// Generic GEMM (single pass): A 2-term fp16 split, W 1-term. 512 thr, 128x128.
// flags: 1=addBias, 2=accum fp32, 16=one-hot residual add.
// ============================================================================
#define STAGE_B 49152
#define GSMEM (3 * STAGE_B)

__global__ __launch_bounds__(512, 1)
void mma_gemm_k(const __half* __restrict__ Ah, const __half* __restrict__ Al,
                const __half* __restrict__ Wh,
                const float* __restrict__ bias, float* __restrict__ Cf,
                const int* __restrict__ xTok,
                int N, int flags, int wLayerStride) {
    extern __shared__ char smem[];
    const uint32_t smb = smem_u32(smem);
    const int tid = threadIdx.x, lane = tid & 31, wid = tid >> 5;
    const int mBase = blockIdx.y << 7, nBase = blockIdx.x << 7;
    const int wm = wid & 3, wn = wid >> 2;

    float acc[2][4][4];
#pragma unroll
    for (int t = 0; t < 2; t++)
#pragma unroll
        for (int j = 0; j < 4; j++)
#pragma unroll
            for (int q = 0; q < 4; q++) acc[t][j][q] = 0.f;

    const int rowIdx = tid >> 3, col16 = tid & 7;

    auto issue = [&](int idx) {
        const size_t wOff = (size_t)(mBase >> 10) * wLayerStride;
        const uint32_t sb = smb + (uint32_t)(idx % 3) * STAGE_B;
        const int kOff = idx * 64 + col16 * 8;
#pragma unroll
        for (int c = 0; c < 2; c++) {
            const int row = rowIdx + c * 64;
            const uint32_t dsw = swz((uint32_t)(row * 128 + col16 * 16));
            const size_t aoff = (size_t)(mBase + row) * Dsz + kOff;
            cp16(sb + dsw, Ah + aoff, true);
            cp16(sb + 16384 + dsw, Al + aoff, true);
            const size_t woff = wOff + (size_t)(nBase + row) * Dsz + kOff;
            cp16(sb + 32768 + dsw, Wh + woff, true);
        }
        CP_COMMIT();
    };

    issue(0);
    issue(1);
    for (int idx = 0; idx < 8; idx++) {
        if (idx + 1 < 8) {
            asm volatile("cp.async.wait_group 1;" ::: "memory");
        } else {
            asm volatile("cp.async.wait_group 0;" ::: "memory");
        }
        __syncthreads();
        if (idx + 2 < 8) issue(idx + 2);
        const uint32_t sb = smb + (uint32_t)(idx % 3) * STAGE_B;
#pragma unroll
        for (int kk = 0; kk < 4; kk++) {
            uint32_t ah[2][4], al[2][4];
#pragma unroll
            for (int t = 0; t < 2; t++) {
                const int row = wm * 32 + t * 16 + (lane & 15);
                const uint32_t off =
                    swz((uint32_t)(row * 128 + kk * 32 + (lane >> 4) * 16));
                LDSM_X4(ah[t], sb + off);
                LDSM_X4(al[t], sb + 16384 + off);
            }
#pragma unroll
            for (int jp = 0; jp < 2; jp++) {
                const int nrow = wn * 32 + jp * 16 + (lane & 7) + ((lane >> 4) << 3);
                const uint32_t off =
                    swz((uint32_t)(nrow * 128 + kk * 32 + ((lane >> 3) & 1) * 16));
                uint32_t bh[4];
                LDSM_X4(bh, sb + 32768 + off);
#pragma unroll
                for (int t = 0; t < 2; t++) {
#pragma unroll
                    for (int jj = 0; jj < 2; jj++) {
                        float* d = acc[t][jp * 2 + jj];
                        MMA_F16(d, ah[t], bh[jj * 2], bh[jj * 2 + 1]);
                        MMA_F16(d, al[t], bh[jj * 2], bh[jj * 2 + 1]);
                    }
                }
            }
        }
    }

    const bool addB = (flags & 1) != 0;
    const bool accum = (flags & 2) != 0;
    const bool onehot = (flags & 16) != 0;
#pragma unroll
    for (int t = 0; t < 2; t++) {
        const int r0 = mBase + wm * 32 + t * 16 + (lane >> 2);
#pragma unroll
        for (int j = 0; j < 4; j++) {
            const int col = nBase + wn * 32 + j * 8 + (lane & 3) * 2;
            float b0 = 0.f, b1 = 0.f;
            if (addB) { b0 = bias[col]; b1 = bias[col + 1]; }
            float v0 = acc[t][j][0] + b0, v1 = acc[t][j][1] + b1;
            float v2 = acc[t][j][2] + b0, v3 = acc[t][j][3] + b1;
            const size_t o0 = (size_t)r0 * N + col;
            const size_t o1 = (size_t)(r0 + 8) * N + col;
            if (onehot) {
                const int t0 = xTok[r0], t1 = xTok[r0 + 8];
                v0 += (col == t0) ? 1.f : 0.f;
                v1 += (col + 1 == t0) ? 1.f : 0.f;
                v2 += (col == t1) ? 1.f : 0.f;
                v3 += (col + 1 == t1) ? 1.f : 0.f;
            }
            if (accum) {
                float2 q0 = *(float2*)(Cf + o0);
                float2 q1 = *(float2*)(Cf + o1);
                v0 += q0.x; v1 += q0.y; v2 += q1.x; v3 += q1.y;
            }
            *(float2*)(Cf + o0) = make_float2(v0, v1);
            *(float2*)(Cf + o1) = make_float2(v2, v3);
        }
    }
}

// ============================================================================
// Conv GEMM: 3 taps share one 130-row A tile. Stage: Ah|Al (17408B each,
// 130 rows used) + 3 W tap tiles (16KB each) = 83968B, 2 stages.
// Epilogue: bias + z2 write + gate partials.
// ============================================================================
#define CONV_A 17408
#define CONV_STAGE (2 * CONV_A + 3 * 16384)  // 83968
#define CONVSMEM (2 * CONV_STAGE)            // 167936

__global__ __launch_bounds__(512, 1)
void mma_conv_k(const __half* __restrict__ Ah, const __half* __restrict__ Al,
                const __half* __restrict__ Wh, const float* __restrict__ bias,
                float* __restrict__ Cf, const float* __restrict__ wgv,
                float* __restrict__ gateOut) {
    extern __shared__ char smem[];
    const uint32_t smb = smem_u32(smem);
    const int tid = threadIdx.x, lane = tid & 31, wid = tid >> 5;
    const int mBase = blockIdx.y << 7, nBase = blockIdx.x << 7;
    const int wm = wid & 3, wn = wid >> 2;

    float acc[2][4][4];
#pragma unroll
    for (int t = 0; t < 2; t++)
#pragma unroll
        for (int j = 0; j < 4; j++)
#pragma unroll
            for (int q = 0; q < 4; q++) acc[t][j][q] = 0.f;

    const int rowIdx = tid >> 3, col16 = tid & 7;
    const bool loVal = (mBase & (Lsz - 1)) != 0;             // row mBase-1 valid
    const bool hiVal = ((mBase + 128) & (Lsz - 1)) != 0;     // row mBase+128 valid

    auto issue = [&](int c8) {
        const uint32_t sb = smb + (uint32_t)(c8 & 1) * CONV_STAGE;
        const int kOff = c8 * 64 + col16 * 8;
        // interior A rows: smem rows 1..128 = global mBase..mBase+127
#pragma unroll
        for (int c = 0; c < 2; c++) {
            const int sr = rowIdx + c * 64 + 1;
            const uint32_t dsw = swz((uint32_t)(sr * 128 + col16 * 16));
            const size_t aoff = (size_t)(mBase + sr - 1) * Dsz + kOff;
            cp16(sb + dsw, Ah + aoff, true);
            cp16(sb + CONV_A + dsw, Al + aoff, true);
        }
        // boundary rows 0 and 129
        if (tid < 8) {
            const uint32_t dsw = swz((uint32_t)(tid * 16));  // smem row 0
            const int ko = c8 * 64 + tid * 8;
            const size_t aoff = (size_t)(loVal ? mBase - 1 : mBase) * Dsz + ko;
            cp16(sb + dsw, Ah + aoff, loVal);
            cp16(sb + CONV_A + dsw, Al + aoff, loVal);
        } else if (tid < 16) {
            const int cc = tid - 8;
            const uint32_t dsw = swz((uint32_t)(129 * 128 + cc * 16));
            const int ko = c8 * 64 + cc * 8;
            const size_t aoff = (size_t)(hiVal ? mBase + 128 : mBase) * Dsz + ko;
            cp16(sb + dsw, Ah + aoff, hiVal);
            cp16(sb + CONV_A + dsw, Al + aoff, hiVal);
        }
        // 3 W tap tiles
#pragma unroll
        for (int p = 0; p < 3; p++) {
#pragma unroll
            for (int c = 0; c < 2; c++) {
                const int row = rowIdx + c * 64;
                const uint32_t dsw = swz((uint32_t)(row * 128 + col16 * 16));
                const size_t woff = (size_t)p * DD + (size_t)(nBase + row) * Dsz + kOff;
                cp16(sb + 2 * CONV_A + (uint32_t)p * 16384 + dsw, Wh + woff, true);
            }
        }
        CP_COMMIT();
    };

    issue(0);
    for (int c8 = 0; c8 < 8; c8++) {
        asm volatile("cp.async.wait_group 0;" ::: "memory");
        __syncthreads();
        if (c8 + 1 < 8) issue(c8 + 1);
        const uint32_t sb = smb + (uint32_t)(c8 & 1) * CONV_STAGE;
#pragma unroll
        for (int kk = 0; kk < 4; kk++) {
#pragma unroll
            for (int p = 0; p < 3; p++) {
                uint32_t ah[2][4], al[2][4];
#pragma unroll
                for (int t = 0; t < 2; t++) {
                    const int row = wm * 32 + t * 16 + (lane & 15) + p;
                    const uint32_t off =
                        swz((uint32_t)(row * 128 + kk * 32 + (lane >> 4) * 16));
                    LDSM_X4(ah[t], sb + off);
                    LDSM_X4(al[t], sb + CONV_A + off);
                }
#pragma unroll
                for (int jp = 0; jp < 2; jp++) {
                    const int nrow = wn * 32 + jp * 16 + (lane & 7) + ((lane >> 4) << 3);
                    const uint32_t off =
                        swz((uint32_t)(nrow * 128 + kk * 32 + ((lane >> 3) & 1) * 16));
                    uint32_t bh[4];
                    LDSM_X4(bh, sb + 2 * CONV_A + (uint32_t)p * 16384 + off);
#pragma unroll
                    for (int t = 0; t < 2; t++) {
#pragma unroll
                        for (int jj = 0; jj < 2; jj++) {
                            float* d = acc[t][jp * 2 + jj];
                            MMA_F16(d, ah[t], bh[jj * 2], bh[jj * 2 + 1]);
                            MMA_F16(d, al[t], bh[jj * 2], bh[jj * 2 + 1]);
                        }
                    }
                }
            }
        }
    }

    // epilogue: bias + z2 write + gate partials
#pragma unroll
    for (int t = 0; t < 2; t++) {
        const int r0 = mBase + wm * 32 + t * 16 + (lane >> 2);
        float p0 = 0.f, p1 = 0.f;
#pragma unroll
        for (int j = 0; j < 4; j++) {
            const int col = nBase + wn * 32 + j * 8 + (lane & 3) * 2;
            const float b0 = bias[col], b1 = bias[col + 1];
            float v0 = acc[t][j][0] + b0, v1 = acc[t][j][1] + b1;
            float v2 = acc[t][j][2] + b0, v3 = acc[t][j][3] + b1;
            const size_t o0 = (size_t)r0 * Dsz + col;
            const size_t o1 = (size_t)(r0 + 8) * Dsz + col;
            *(float2*)(Cf + o0) = make_float2(v0, v1);
            *(float2*)(Cf + o1) = make_float2(v2, v3);
            const float w0 = __ldg(wgv + col), w1 = __ldg(wgv + col + 1);
            p0 = fmaf(v0, w0, fmaf(v1, w1, p0));
            p1 = fmaf(v2, w0, fmaf(v3, w1, p1));
        }
        p0 += __shfl_xor_sync(0xffffffffu, p0, 1);
        p0 += __shfl_xor_sync(0xffffffffu, p0, 2);
        p1 += __shfl_xor_sync(0xffffffffu, p1, 1);
        p1 += __shfl_xor_sync(0xffffffffu, p1, 2);
        if ((lane & 3) == 0) {
            float* gp = gateOut + ((size_t)((nBase >> 7) * 4 + wn)) * Tsz;
            gp[r0] = p0;
            gp[r0 + 8] = p1;
        }
    }
}

// ============================================================================
// Fused fc(+folded wout) + gated-MLP GEMM.
// ============================================================================
#define FC_STAGE 65536
#define FCSMEM (2 * FC_STAGE)

__global__ __launch_bounds__(512, 1)
void mma_fc_k(const __half* __restrict__ Ah, const __half* __restrict__ Al,
              const __half* __restrict__ Wh, const float* __restrict__ bias,
              __half* __restrict__ Oh, __half* __restrict__ Ol) {
    extern __shared__ char smem[];
    const uint32_t smb = smem_u32(smem);
    const int tid = threadIdx.x, lane = tid & 31, wid = tid >> 5;
    const int mBase = blockIdx.y << 7, nBase = blockIdx.x << 7;
    const int wm = wid & 3, wn = wid >> 2;

    float accg[2][4][4], accv[2][4][4];
#pragma unroll
    for (int t = 0; t < 2; t++)
#pragma unroll
        for (int j = 0; j < 4; j++)
#pragma unroll
            for (int q = 0; q < 4; q++) { accg[t][j][q] = 0.f; accv[t][j][q] = 0.f; }

    const int rowIdx = tid >> 3, col16 = tid & 7;

    auto issue = [&](int idx) {
        const uint32_t sb = smb + (uint32_t)(idx & 1) * FC_STAGE;
        const int kOff = idx * 64 + col16 * 8;
#pragma unroll
        for (int c = 0; c < 2; c++) {
            const int row = rowIdx + c * 64;
            const uint32_t dsw = swz((uint32_t)(row * 128 + col16 * 16));
            const size_t aoff = (size_t)(mBase + row) * Dsz + kOff;
            cp16(sb + dsw, Ah + aoff, true);
            cp16(sb + 16384 + dsw, Al + aoff, true);
            const size_t wgoff = (size_t)(nBase + row) * Dsz + kOff;
            cp16(sb + 32768 + dsw, Wh + wgoff, true);
            const size_t wvoff = (size_t)(512 + nBase + row) * Dsz + kOff;
            cp16(sb + 49152 + dsw, Wh + wvoff, true);
        }
        CP_COMMIT();
    };

    issue(0);
    for (int idx = 0; idx < 8; idx++) {
        asm volatile("cp.async.wait_group 0;" ::: "memory");
        __syncthreads();
        if (idx + 1 < 8) issue(idx + 1);
        const uint32_t sb = smb + (uint32_t)(idx & 1) * FC_STAGE;
#pragma unroll
        for (int kk = 0; kk < 4; kk++) {
            uint32_t ah[2][4], al[2][4];
#pragma unroll
            for (int t = 0; t < 2; t++) {
                const int row = wm * 32 + t * 16 + (lane & 15);
                const uint32_t off =
                    swz((uint32_t)(row * 128 + kk * 32 + (lane >> 4) * 16));
                LDSM_X4(ah[t], sb + off);
                LDSM_X4(al[t], sb + 16384 + off);
            }
#pragma unroll
            for (int jp = 0; jp < 2; jp++) {
                const int nrow = wn * 32 + jp * 16 + (lane & 7) + ((lane >> 4) << 3);
                const uint32_t off =
                    swz((uint32_t)(nrow * 128 + kk * 32 + ((lane >> 3) & 1) * 16));
                {
                    uint32_t bh[4];
                    LDSM_X4(bh, sb + 32768 + off);
#pragma unroll
                    for (int t = 0; t < 2; t++)
#pragma unroll
                        for (int jj = 0; jj < 2; jj++) {
                            float* d = accg[t][jp * 2 + jj];
                            MMA_F16(d, ah[t], bh[jj * 2], bh[jj * 2 + 1]);
                            MMA_F16(d, al[t], bh[jj * 2], bh[jj * 2 + 1]);
                        }
                }
                {
                    uint32_t bh[4];
                    LDSM_X4(bh, sb + 49152 + off);
#pragma unroll
                    for (int t = 0; t < 2; t++)
#pragma unroll
                        for (int jj = 0; jj < 2; jj++) {
                            float* d = accv[t][jp * 2 + jj];
                            MMA_F16(d, ah[t], bh[jj * 2], bh[jj * 2 + 1]);
                            MMA_F16(d, al[t], bh[jj * 2], bh[jj * 2 + 1]);
                        }
                }
            }
        }
    }

#pragma unroll
    for (int t = 0; t < 2; t++) {
#pragma unroll
        for (int j = 0; j < 4; j++) {
            const int r0 = mBase + wm * 32 + t * 16 + (lane >> 2);
            const int col = nBase + wn * 32 + j * 8 + (lane & 3) * 2;
            const float bg0 = bias[col], bg1 = bias[col + 1];
            const float bv0 = bias[512 + col], bv1 = bias[512 + col + 1];
            float s0 = 1.f / (1.f + expf(-(accg[t][j][0] + bg0)));
            float s1 = 1.f / (1.f + expf(-(accg[t][j][1] + bg1)));
            float s2 = 1.f / (1.f + expf(-(accg[t][j][2] + bg0)));
            float s3 = 1.f / (1.f + expf(-(accg[t][j][3] + bg1)));
            float v0 = s0 * (accv[t][j][0] + bv0);
            float v1 = s1 * (accv[t][j][1] + bv1);
            float v2 = s2 * (accv[t][j][2] + bv0);
            float v3 = s3 * (accv[t][j][3] + bv1);
            const size_t o0 = (size_t)r0 * Dsz + col;
            const size_t o1 = (size_t)(r0 + 8) * Dsz + col;
            __half2 h, lo;
            split2h(v0, v1, h, lo);
            *(__half2*)(Oh + o0) = h;
            *(__half2*)(Ol + o0) = lo;
            split2h(v2, v3, h, lo);
            *(__half2*)(Oh + o1) = h;
            *(__half2*)(Ol + o1) = lo;
        }
    }
}

// ============================================================================
// Layer-0 conv as gather (exact fp32) + fused gate.
// ============================================================================
__global__ void conv0_k(const int* __restrict__ x, const float* __restrict__ w0t,
                        const float* __restrict__ u0, const float* __restrict__ cb,
                        const float* __restrict__ lng, const float* __restrict__ wgv,
                        const float* __restrict__ bg,
                        float* __restrict__ z2, float* __restrict__ gt) {
    const int t = blockIdx.x, tid = threadIdx.x;
    const int l = t & (Lsz - 1);
    const float mean = 1.0f / 512.0f;
    const float rstd = rsqrtf(mean * (511.0f / 512.0f) + 1e-5f);

    const int tokm = (l > 0) ? x[t - 1] : -1;
    const int tok0 = x[t];
    const int tokp = (l < Lsz - 1) ? x[t + 1] : -1;

    float4 acc = ((const float4*)cb)[tid];
    {
        const float s = rstd * lng[tok0];
        float4 w = ((const float4*)(w0t + (size_t)DD + (size_t)tok0 * Dsz))[tid];
        float4 u = ((const float4*)(u0 + Dsz))[tid];
        acc.x += s * w.x + u.x; acc.y += s * w.y + u.y;
        acc.z += s * w.z + u.z; acc.w += s * w.w + u.w;
    }
    if (tokm >= 0) {
        const float s = rstd * lng[tokm];
        float4 w = ((const float4*)(w0t + (size_t)tokm * Dsz))[tid];
        float4 u = ((const float4*)u0)[tid];
        acc.x += s * w.x + u.x; acc.y += s * w.y + u.y;
        acc.z += s * w.z + u.z; acc.w += s * w.w + u.w;
    }
    if (tokp >= 0) {
        const float s = rstd * lng[tokp];
        float4 w = ((const float4*)(w0t + (size_t)2 * DD + (size_t)tokp * Dsz))[tid];
        float4 u = ((const float4*)(u0 + 2 * Dsz))[tid];
        acc.x += s * w.x + u.x; acc.y += s * w.y + u.y;
        acc.z += s * w.z + u.z; acc.w += s * w.w + u.w;
    }
    ((float4*)(z2 + (size_t)t * Dsz))[tid] = acc;

    float4 wv = ((const float4*)wgv)[tid];
    float p = acc.x * wv.x + acc.y * wv.y + acc.z * wv.z + acc.w * wv.w;
#pragma unroll
    for (int o = 16; o; o >>= 1) p += __shfl_xor_sync(0xffffffffu, p, o);
    __shared__ float smr[4];
    if ((tid & 31) == 0) smr[tid >> 5] = p;
    __syncthreads();
    if (tid == 0) {
        float s = smr[0] + smr[1] + smr[2] + smr[3];
        gt[t] = 1.0f / (1.0f + expf(-(s + bg[0])));
    }
}

// ---------------- merged prep: weight converts + w0t + fc split + flag reset --
__global__ void prep_k(const float* __restrict__ conv_w, const float* __restrict__ mo_w,
                       const float* __restrict__ head_w, const float* __restrict__ wout,
                       const float* __restrict__ fc_w,
                       __half* __restrict__ wh, float* __restrict__ w0t,
                       __half* __restrict__ fch, __half* __restrict__ fcl) {
    const int idx = blockIdx.x * blockDim.x + threadIdx.x;   // 0 .. 32*DD-1
    if (idx < NFLAGS) g_sflag[idx] = 0;
    if (idx < 12 * DD) {                       // conv repack [h][o][i] fp16
        int layer = idx / (3 * DD);
        int r = idx - layer * (3 * DD);
        int h = r / DD;
        int rr = r - h * DD;
        int o = rr >> 9, i = rr & 511;
        wh[idx] = __float2half_rn(conv_w[(size_t)layer * 3 * DD + ((size_t)o * Dsz + i) * 3 + h]);
    } else if (idx < 16 * DD) {                // mo 1-term
        int j = idx - 12 * DD;
        wh[W_MO(0) + j] = __float2half_rn(mo_w[j]);
    } else if (idx < 17 * DD) {                // head 1-term
        int j = idx - 16 * DD;
        wh[W_HEAD + j] = __float2half_rn(head_w[j]);
    } else if (idx < 21 * DD) {                // wout^T 1-term
        int j = idx - 17 * DD;
        int layer = j / DD;
        int r = j - layer * DD;
        int n = r >> 9, k = r & 511;
        wh[W_WOUT(0) + j] = __float2half_rn(wout[(size_t)layer * DD + (size_t)k * Dsz + n]);
    } else if (idx < 24 * DD) {                // layer-0 tap table (fp32)
        int j = idx - 21 * DD;
        int h = j / DD;
        int r = j - h * DD;
        int i = r >> 9, o = r & 511;
        w0t[j] = conv_w[((size_t)o * Dsz + i) * 3 + h];
    } else {                                   // fc 2-term split (prep scratch)
        int j = idx - 24 * DD;                 // 0 .. 8*DD-1
        float v = fc_w[j];
        __half hi = __float2half_rn(v);
        fch[j] = hi;
        fcl[j] = __float2half_rn(v - __half2float(hi));
    }
}

// ---------------- layernorm with fused fp16 hi/lo split ----------------------
__global__ void ln_split_k(const float* __restrict__ in,
                           __half* __restrict__ oh, __half* __restrict__ ol,
                           const float* __restrict__ gamma, const float* __restrict__ beta) {
    int t = blockIdx.x, tid = threadIdx.x;
    const float4* rp = (const float4*)(in + (size_t)t * Dsz);
    float4 v = rp[tid];
    float s = v.x + v.y + v.z + v.w;
#pragma unroll
    for (int o = 16; o; o >>= 1) s += __shfl_xor_sync(0xffffffffu, s, o);
    __shared__ float smr[4];
    if ((tid & 31) == 0) smr[tid >> 5] = s;
    __syncthreads();
    float mean = (smr[0] + smr[1] + smr[2] + smr[3]) * (1.0f / Dsz);
    float dx = v.x - mean, dy = v.y - mean, dz = v.z - mean, dw = v.w - mean;
    float q = dx * dx + dy * dy + dz * dz + dw * dw;
#pragma unroll
    for (int o = 16; o; o >>= 1) q += __shfl_xor_sync(0xffffffffu, q, o);
    __syncthreads();
    if ((tid & 31) == 0) smr[tid >> 5] = q;
    __syncthreads();
    float var = (smr[0] + smr[1] + smr[2] + smr[3]) * (1.0f / Dsz);
    float rstd = rsqrtf(var + 1e-5f);
    float4 g4 = ((const float4*)gamma)[tid];
    float4 b4 = ((const float4*)beta)[tid];
    float f0 = dx * rstd * g4.x + b4.x, f1 = dy * rstd * g4.y + b4.y;
    float f2 = dz * rstd * g4.z + b4.z, f3 = dw * rstd * g4.w + b4.w;
    __half2 h01, l01, h23, l23;
    split2h(f0, f1, h01, l01);
    split2h(f2, f3, h23, l23);
    __half2* ph = (__half2*)(oh + (size_t)t * Dsz);
    __half2* pl = (__half2*)(ol + (size_t)t * Dsz);
    ph[2 * tid] = h01; ph[2 * tid + 1] = h23;
    pl[2 * tid] = l01; pl[2 * tid + 1] = l23;
}

// ---------------- u0 = W_h^T (lnb - rstd*mean*lng) -----------------------------
__global__ void u0_k(const float* __restrict__ cw, const float* __restrict__ lng,
                     const float* __restrict__ lnb, float* __restrict__ u0) {
    int w = (blockIdx.x * blockDim.x + threadIdx.x) >> 5;
    int lane = threadIdx.x & 31;
    int h = w >> 9, o = w & 511;
    const float mean = 1.0f / 512.0f;
    const float rstd = rsqrtf(mean * (511.0f / 512.0f) + 1e-5f);
    float s = 0.f;
#pragma unroll
    for (int c = 0; c < 16; c++) {
        int i = lane + 32 * c;
        float v = lnb[i] - rstd * mean * lng[i];
        s = fmaf(cw[((size_t)o * Dsz + i) * 3 + h], v, s);
    }
#pragma unroll
    for (int ofs = 16; ofs; ofs >>= 1) s += __shfl_xor_sync(0xffffffffu, s, ofs);
    if (lane == 0) u0[w] = s;
}

// ---------------- 1-term convert (Wcomb) ---------------------------------------
__global__ void wsplit1_k(const float* __restrict__ w, __half* __restrict__ wh, int n) {
    int idx = blockIdx.x * blockDim.x + threadIdx.x;
    if (idx >= n) return;
    wh[idx] = __float2half_rn(w[idx]);
}

// ---------------- bcomb = Wf·bo + fb --------------------------------------------
__global__ void bcomb_k(const float* __restrict__ fw, const float* __restrict__ bo,
                        const float* __restrict__ fb, float* __restrict__ out) {
    int w = (blockIdx.x * blockDim.x + threadIdx.x) >> 5;
    int lane = threadIdx.x & 31;
    int layer = w >> 10, e = w & 1023;
    const float* fr = fw + ((size_t)layer * 1024 + e) * Dsz;
    const float* br = bo + (size_t)layer * Dsz;
    float s = 0.f;
#pragma unroll
    for (int i = 0; i < 16; i++) s = fmaf(fr[lane + 32 * i], br[lane + 32 * i], s);
#pragma unroll
    for (int o = 16; o; o >>= 1) s += __shfl_xor_sync(0xffffffffu, s, o);
    if (lane == 0) out[w] = s + fb[(size_t)layer * 1024 + e];
}

// ============================================================================
// Unified chained scan; c=0 blocks emit outputs in pass 1 (carry = 0).
// Flags zeroed per call in prep_k -> deterministic across graph replays.
// ============================================================================
__global__ void scan_u_k(const float* __restrict__ z2,
                         const float* __restrict__ gatep,
                         const float* __restrict__ gt0,
                         const float* __restrict__ bgp,
                         float* __restrict__ hfin, int* __restrict__ flags,
                         __half* __restrict__ hh, __half* __restrict__ hl) {
    const int bx = blockIdx.x;
    const int c = bx >> 6, b = (bx >> 2) & 15, dch = bx & 3;
    const int tid = threadIdx.x;
    const int d = (dch << 7) + tid;
    const int l0 = c * SCH;
    __shared__ float gsm[SCH];

    if (gt0) {
        for (int j = tid; j < SCH; j += 128)
            gsm[j] = gt0[b * Lsz + l0 + j];
    } else {
        const float bgv = bgp[0];
        for (int j = tid; j < SCH; j += 128) {
            const int t = b * Lsz + l0 + j;
            float s = 0.f;
#pragma unroll
            for (int p = 0; p < 16; p++) s += gatep[(size_t)p * Tsz + t];
            gsm[j] = 1.0f / (1.0f + expf(-(s + bgv)));
        }
    }
    __syncthreads();

    const size_t base = (size_t)b * Lsz * Dsz + (size_t)l0 * Dsz + d;
    const bool first = (c == 0);
    // pass 1 (for c==0 also writes final outputs since carry = 0)
    float hv = 0.f, ap = 1.f;
    for (int l = 0; l < SCH; l += 8) {
        float xs[8], gs[8];
#pragma unroll
        for (int j = 0; j < 8; j++) {
            xs[j] = z2[base + (size_t)(l + j) * Dsz];
            gs[j] = gsm[l + j];
        }
#pragma unroll
        for (int j = 0; j < 8; j++) {
            hv = fmaf(gs[j], xs[j] - hv, hv);
            ap *= (1.f - gs[j]);
            if (first) {
                __half hi = __float2half_rn(hv);
                size_t o = base + (size_t)(l + j) * Dsz;
                hh[o] = hi;
                hl[o] = __float2half_rn(hv - __half2float(hi));
            }
        }
    }
    float carry = 0.f;
    const size_t fo = (size_t)c * (Bsz * Dsz) + (size_t)b * Dsz + d;
    if (!first) {
        if (tid == 0) {
            volatile int* f = flags + (bx - 64);
            while (*f == 0) {}
        }
        __syncthreads();
        __threadfence();
        carry = __ldcg(hfin + fo - (size_t)(Bsz * Dsz));
    }
    hfin[fo] = hv + ap * carry;
    __syncthreads();
    __threadfence();
    if (tid == 0) *((volatile int*)(flags + bx)) = 1;
    if (first) return;

    // pass 2: full scan with carry, split-fp16 output
    hv = carry;
    for (int l = 0; l < SCH; l += 8) {
        float xs[8], gs[8];
#pragma unroll
        for (int j = 0; j < 8; j++) {
            xs[j] = z2[base + (size_t)(l + j) * Dsz];
            gs[j] = gsm[l + j];
        }
#pragma unroll
        for (int j = 0; j < 8; j++) {
            hv = fmaf(gs[j], xs[j] - hv, hv);
            __half hi = __float2half_rn(hv);
            size_t o = base + (size_t)(l + j) * Dsz;
            hh[o] = hi;
            hl[o] = __float2half_rn(hv - __half2float(hi));
        }
    }
}

// ---------------- launch --------------------------------------------------------
extern "C" void kernel_launch(void* const* d_in, const int* in_sizes, int n_in,
                              void* d_out, int out_size) {
    const int* x = (const int*)d_in[0];
    const float* ln_g = (const float*)d_in[1];
    const float* ln_b = (const float*)d_in[2];
    const float* conv_w = (const float*)d_in[3];
    const float* conv_b = (const float*)d_in[4];
    const float* wg = (const float*)d_in[5];
    const float* bg = (const float*)d_in[6];
    const float* wout = (const float*)d_in[7];
    const float* bout = (const float*)d_in[8];
    const float* fc_w = (const float*)d_in[9];
    const float* fc_b = (const float*)d_in[10];
    const float* mo_w = (const float*)d_in[11];
    const float* mo_b = (const float*)d_in[12];
    const float* lnf_g = (const float*)d_in[13];
    const float* lnf_b = (const float*)d_in[14];
    const float* head_w = (const float*)d_in[15];
    const float* head_b = (const float*)d_in[16];

    float *y, *z2, *gt, *gp, *bcomb, *hfin, *w0t, *u0;
    int* sflag;
    __half *zh, *zl, *hh, *hl, *gh, *gl, *wh;
    cudaGetSymbolAddress((void**)&y, g_y);
    cudaGetSymbolAddress((void**)&z2, g_z2);
    cudaGetSymbolAddress((void**)&gt, g_gate);
    cudaGetSymbolAddress((void**)&gp, g_gatep);
    cudaGetSymbolAddress((void**)&bcomb, g_bcomb);
    cudaGetSymbolAddress((void**)&hfin, g_hfin);
    cudaGetSymbolAddress((void**)&sflag, g_sflag);
    cudaGetSymbolAddress((void**)&w0t, g_w0t);
    cudaGetSymbolAddress((void**)&u0, g_u0);
    cudaGetSymbolAddress((void**)&zh, g_zh);
    cudaGetSymbolAddress((void**)&zl, g_zl);
    cudaGetSymbolAddress((void**)&hh, g_hh);
    cudaGetSymbolAddress((void**)&hl, g_hl);
    cudaGetSymbolAddress((void**)&gh, g_gh);
    cudaGetSymbolAddress((void**)&gl, g_gl);
    cudaGetSymbolAddress((void**)&wh, g_wh);

    cudaFuncSetAttribute(mma_gemm_k, cudaFuncAttributeMaxDynamicSharedMemorySize, GSMEM);
    cudaFuncSetAttribute(mma_conv_k, cudaFuncAttributeMaxDynamicSharedMemorySize, CONVSMEM);
    cudaFuncSetAttribute(mma_fc_k, cudaFuncAttributeMaxDynamicSharedMemorySize, FCSMEM);

    const dim3 g512(4, Tsz / 128);

    // ---- prep: merged converts (+flag reset), bias fold, wout folding ----
    prep_k<<<(32 * DD) / 256, 256>>>(conv_w, mo_w, head_w, wout, fc_w, wh, w0t, gh, gl);
    bcomb_k<<<(NLsz * 1024 * 32) / 256, 256>>>(fc_w, bout, fc_b, bcomb);
    u0_k<<<(3 * Dsz * 32) / 256, 256>>>(conv_w, ln_g, ln_b, u0);
    // Wcomb = Wf @ Wo (batched over layers; A = fc split scratch, W = wout^T)
    mma_gemm_k<<<dim3(4, 32), 512, GSMEM>>>(gh, gl, wh + W_WOUT(0),
                                            nullptr, z2, nullptr, Dsz, 0, (int)DD);
    wsplit1_k<<<(8 * DD) / 256, 256>>>(z2, wh + W_FC(0), 8 * DD);

    for (int i = 0; i < NLsz; i++) {
        if (i == 0) {
            conv0_k<<<Tsz, 128>>>(x, w0t, u0, conv_b, ln_g, wg, bg, z2, gt);
        } else {
            ln_split_k<<<Tsz, 128>>>(y, zh, zl, ln_g + (size_t)i * Dsz, ln_b + (size_t)i * Dsz);
            mma_conv_k<<<g512, 512, CONVSMEM>>>(zh, zl, wh + W_CONV(i),
                                                conv_b + (size_t)i * Dsz, z2,
                                                wg + (size_t)i * Dsz, gp);
        }
        scan_u_k<<<NCH * 64, 128>>>(z2, gp, (i == 0) ? gt : nullptr, bg + i,
                                    hfin, sflag + (size_t)i * (NCH * Bsz * 4), hh, hl);
        mma_fc_k<<<g512, 512, FCSMEM>>>(hh, hl, wh + W_FC(i),
                                        bcomb + (size_t)i * 1024, gh, gl);
        mma_gemm_k<<<g512, 512, GSMEM>>>(gh, gl, wh + W_MO(i),
                                         mo_b + (size_t)i * Dsz, y,
                                         (i == 0) ? x : nullptr, Dsz,
                                         (i == 0) ? (1 | 16) : (1 | 2), 0);
    }

    ln_split_k<<<Tsz, 128>>>(y, zh, zl, lnf_g, lnf_b);
    mma_gemm_k<<<g512, 512, GSMEM>>>(zh, zl, wh + W_HEAD, head_b,
                                     (float*)d_out, nullptr, Dsz, 1, 0);
}

// round 13
// speedup vs baseline: 1.4210x; 1.0137x over previous
#include <cuda_runtime.h>
#include <cuda_fp16.h>
#include <cstdint>
#include <cstddef>

#define Bsz 16
#define Lsz 2048
#define Dsz 512
#define NLsz 4
#define Tsz (Bsz * Lsz)  // 32768
#define DD (Dsz * Dsz)

// weight arena offsets (units of DD)
#define W_CONV(i) ((size_t)(i) * 3 * DD)
#define W_WOUT(i) ((size_t)(12 + (i)) * DD)      // wout^T (prep only)
#define W_FC(i)   ((size_t)(16 + 2 * (i)) * DD)  // after prep: Wcomb = Wf@Wo
#define W_MO(i)   ((size_t)(24 + (i)) * DD)
#define W_HEAD    ((size_t)28 * DD)

// scan chunking
#define SCH 256
#define NCH (Lsz / SCH)  // 8
#define NFLAGS (NLsz * NCH * Bsz * 4)  // 2048

// ---------------- scratch (device globals; no allocation allowed) ----------
__device__ float g_y[Tsz * Dsz];
__device__ float g_z2[Tsz * Dsz];
__device__ float g_gate[Tsz];
__device__ float g_gatep[16 * Tsz];
__device__ float g_bcomb[NLsz * 2 * Dsz];
__device__ float g_hfin[NCH * Bsz * Dsz];
__device__ int   g_sflag[NFLAGS];
__device__ float g_w0t[3 * DD];
__device__ float g_u0[3 * Dsz];
__device__ __half g_zh[Tsz * Dsz], g_zl[Tsz * Dsz];
__device__ __half g_hh[Tsz * Dsz], g_hl[Tsz * Dsz];
__device__ __half g_gh[Tsz * Dsz], g_gl[Tsz * Dsz];   // gl now prep scratch only
__device__ __half g_wh[29 * DD];                       // weights, 1-term fp16

// ---------------- helpers ---------------------------------------------------
__device__ __forceinline__ uint32_t smem_u32(const void* p) {
    return (uint32_t)__cvta_generic_to_shared(p);
}
__device__ __forceinline__ uint32_t swz(uint32_t x) { return x ^ ((x >> 3) & 0x70); }

__device__ __forceinline__ void cp16(uint32_t dst, const void* src, bool v) {
    int sz = v ? 16 : 0;
    asm volatile("cp.async.cg.shared.global [%0], [%1], 16, %2;"
                 :: "r"(dst), "l"(src), "r"(sz) : "memory");
}
#define CP_COMMIT() asm volatile("cp.async.commit_group;" ::: "memory")

#define LDSM_X4(r, a)                                                          \
    asm volatile("ldmatrix.sync.aligned.m8n8.x4.shared.b16 {%0,%1,%2,%3}, [%4];" \
                 : "=r"((r)[0]), "=r"((r)[1]), "=r"((r)[2]), "=r"((r)[3]) : "r"(a))

#define MMA_F16(d, a, b0, b1)                                                  \
    asm volatile(                                                              \
        "mma.sync.aligned.m16n8k16.row.col.f32.f16.f16.f32 "                   \
        "{%0,%1,%2,%3},{%4,%5,%6,%7},{%8,%9},{%0,%1,%2,%3};"                   \
        : "+f"((d)[0]), "+f"((d)[1]), "+f"((d)[2]), "+f"((d)[3])               \
        : "r"((a)[0]), "r"((a)[1]), "r"((a)[2]), "r"((a)[3]), "r"(b0), "r"(b1))

__device__ __forceinline__ void split2h(float a, float b, __half2& hi, __half2& lo) {
    hi = __floats2half2_rn(a, b);
    lo = __floats2half2_rn(a - __half2float(__low2half(hi)),
                           b - __half2float(__high2half(hi)));
}

// ============================================================================
// Generic GEMM: A 2-term fp16 split (or 1-term if Al==nullptr), W 1-term.
// 512 thr, 128x128. flags: 1=addBias, 2=accum fp32, 16=one-hot residual add.
// ============================================================================
#define STAGE_B 49152
#define GSMEM (3 * STAGE_B)

__global__ __launch_bounds__(512, 1)
void mma_gemm_k(const __half* __restrict__ Ah, const __half* __restrict__ Al,
                const __half* __restrict__ Wh,
                const float* __restrict__ bias, float* __restrict__ Cf,
                const int* __restrict__ xTok,
                int N, int flags, int wLayerStride) {
    extern __shared__ char smem[];
    const uint32_t smb = smem_u32(smem);
    const int tid = threadIdx.x, lane = tid & 31, wid = tid >> 5;
    const int mBase = blockIdx.y << 7, nBase = blockIdx.x << 7;
    const int wm = wid & 3, wn = wid >> 2;
    const bool twoTerm = (Al != nullptr);

    float acc[2][4][4];
#pragma unroll
    for (int t = 0; t < 2; t++)
#pragma unroll
        for (int j = 0; j < 4; j++)
#pragma unroll
            for (int q = 0; q < 4; q++) acc[t][j][q] = 0.f;

    const int rowIdx = tid >> 3, col16 = tid & 7;

    auto issue = [&](int idx) {
        const size_t wOff = (size_t)(mBase >> 10) * wLayerStride;
        const uint32_t sb = smb + (uint32_t)(idx % 3) * STAGE_B;
        const int kOff = idx * 64 + col16 * 8;
#pragma unroll
        for (int c = 0; c < 2; c++) {
            const int row = rowIdx + c * 64;
            const uint32_t dsw = swz((uint32_t)(row * 128 + col16 * 16));
            const size_t aoff = (size_t)(mBase + row) * Dsz + kOff;
            cp16(sb + dsw, Ah + aoff, true);
            if (twoTerm) cp16(sb + 16384 + dsw, Al + aoff, true);
            const size_t woff = wOff + (size_t)(nBase + row) * Dsz + kOff;
            cp16(sb + 32768 + dsw, Wh + woff, true);
        }
        CP_COMMIT();
    };

    issue(0);
    issue(1);
    for (int idx = 0; idx < 8; idx++) {
        if (idx + 1 < 8) {
            asm volatile("cp.async.wait_group 1;" ::: "memory");
        } else {
            asm volatile("cp.async.wait_group 0;" ::: "memory");
        }
        __syncthreads();
        if (idx + 2 < 8) issue(idx + 2);
        const uint32_t sb = smb + (uint32_t)(idx % 3) * STAGE_B;
#pragma unroll
        for (int kk = 0; kk < 4; kk++) {
            uint32_t ah[2][4], al[2][4];
#pragma unroll
            for (int t = 0; t < 2; t++) {
                const int row = wm * 32 + t * 16 + (lane & 15);
                const uint32_t off =
                    swz((uint32_t)(row * 128 + kk * 32 + (lane >> 4) * 16));
                LDSM_X4(ah[t], sb + off);
                if (twoTerm) LDSM_X4(al[t], sb + 16384 + off);
            }
#pragma unroll
            for (int jp = 0; jp < 2; jp++) {
                const int nrow = wn * 32 + jp * 16 + (lane & 7) + ((lane >> 4) << 3);
                const uint32_t off =
                    swz((uint32_t)(nrow * 128 + kk * 32 + ((lane >> 3) & 1) * 16));
                uint32_t bh[4];
                LDSM_X4(bh, sb + 32768 + off);
#pragma unroll
                for (int t = 0; t < 2; t++) {
#pragma unroll
                    for (int jj = 0; jj < 2; jj++) {
                        float* d = acc[t][jp * 2 + jj];
                        MMA_F16(d, ah[t], bh[jj * 2], bh[jj * 2 + 1]);
                        if (twoTerm) MMA_F16(d, al[t], bh[jj * 2], bh[jj * 2 + 1]);
                    }
                }
            }
        }
    }

    const bool addB = (flags & 1) != 0;
    const bool accum = (flags & 2) != 0;
    const bool onehot = (flags & 16) != 0;
#pragma unroll
    for (int t = 0; t < 2; t++) {
        const int r0 = mBase + wm * 32 + t * 16 + (lane >> 2);
#pragma unroll
        for (int j = 0; j < 4; j++) {
            const int col = nBase + wn * 32 + j * 8 + (lane & 3) * 2;
            float b0 = 0.f, b1 = 0.f;
            if (addB) { b0 = bias[col]; b1 = bias[col + 1]; }
            float v0 = acc[t][j][0] + b0, v1 = acc[t][j][1] + b1;
            float v2 = acc[t][j][2] + b0, v3 = acc[t][j][3] + b1;
            const size_t o0 = (size_t)r0 * N + col;
            const size_t o1 = (size_t)(r0 + 8) * N + col;
            if (onehot) {
                const int t0 = xTok[r0], t1 = xTok[r0 + 8];
                v0 += (col == t0) ? 1.f : 0.f;
                v1 += (col + 1 == t0) ? 1.f : 0.f;
                v2 += (col == t1) ? 1.f : 0.f;
                v3 += (col + 1 == t1) ? 1.f : 0.f;
            }
            if (accum) {
                float2 q0 = *(float2*)(Cf + o0);
                float2 q1 = *(float2*)(Cf + o1);
                v0 += q0.x; v1 += q0.y; v2 += q1.x; v3 += q1.y;
            }
            *(float2*)(Cf + o0) = make_float2(v0, v1);
            *(float2*)(Cf + o1) = make_float2(v2, v3);
        }
    }
}

// ============================================================================
// Conv GEMM: 3 taps share one 130-row A tile (2-term A). Epilogue: bias +
// z2 write + gate partials.
// ============================================================================
#define CONV_A 17408
#define CONV_STAGE (2 * CONV_A + 3 * 16384)  // 83968
#define CONVSMEM (2 * CONV_STAGE)            // 167936

__global__ __launch_bounds__(512, 1)
void mma_conv_k(const __half* __restrict__ Ah, const __half* __restrict__ Al,
                const __half* __restrict__ Wh, const float* __restrict__ bias,
                float* __restrict__ Cf, const float* __restrict__ wgv,
                float* __restrict__ gateOut) {
    extern __shared__ char smem[];
    const uint32_t smb = smem_u32(smem);
    const int tid = threadIdx.x, lane = tid & 31, wid = tid >> 5;
    const int mBase = blockIdx.y << 7, nBase = blockIdx.x << 7;
    const int wm = wid & 3, wn = wid >> 2;

    float acc[2][4][4];
#pragma unroll
    for (int t = 0; t < 2; t++)
#pragma unroll
        for (int j = 0; j < 4; j++)
#pragma unroll
            for (int q = 0; q < 4; q++) acc[t][j][q] = 0.f;

    const int rowIdx = tid >> 3, col16 = tid & 7;
    const bool loVal = (mBase & (Lsz - 1)) != 0;
    const bool hiVal = ((mBase + 128) & (Lsz - 1)) != 0;

    auto issue = [&](int c8) {
        const uint32_t sb = smb + (uint32_t)(c8 & 1) * CONV_STAGE;
        const int kOff = c8 * 64 + col16 * 8;
#pragma unroll
        for (int c = 0; c < 2; c++) {
            const int sr = rowIdx + c * 64 + 1;
            const uint32_t dsw = swz((uint32_t)(sr * 128 + col16 * 16));
            const size_t aoff = (size_t)(mBase + sr - 1) * Dsz + kOff;
            cp16(sb + dsw, Ah + aoff, true);
            cp16(sb + CONV_A + dsw, Al + aoff, true);
        }
        if (tid < 8) {
            const uint32_t dsw = swz((uint32_t)(tid * 16));
            const int ko = c8 * 64 + tid * 8;
            const size_t aoff = (size_t)(loVal ? mBase - 1 : mBase) * Dsz + ko;
            cp16(sb + dsw, Ah + aoff, loVal);
            cp16(sb + CONV_A + dsw, Al + aoff, loVal);
        } else if (tid < 16) {
            const int cc = tid - 8;
            const uint32_t dsw = swz((uint32_t)(129 * 128 + cc * 16));
            const int ko = c8 * 64 + cc * 8;
            const size_t aoff = (size_t)(hiVal ? mBase + 128 : mBase) * Dsz + ko;
            cp16(sb + dsw, Ah + aoff, hiVal);
            cp16(sb + CONV_A + dsw, Al + aoff, hiVal);
        }
#pragma unroll
        for (int p = 0; p < 3; p++) {
#pragma unroll
            for (int c = 0; c < 2; c++) {
                const int row = rowIdx + c * 64;
                const uint32_t dsw = swz((uint32_t)(row * 128 + col16 * 16));
                const size_t woff = (size_t)p * DD + (size_t)(nBase + row) * Dsz + kOff;
                cp16(sb + 2 * CONV_A + (uint32_t)p * 16384 + dsw, Wh + woff, true);
            }
        }
        CP_COMMIT();
    };

    issue(0);
    for (int c8 = 0; c8 < 8; c8++) {
        asm volatile("cp.async.wait_group 0;" ::: "memory");
        __syncthreads();
        if (c8 + 1 < 8) issue(c8 + 1);
        const uint32_t sb = smb + (uint32_t)(c8 & 1) * CONV_STAGE;
#pragma unroll
        for (int kk = 0; kk < 4; kk++) {
#pragma unroll
            for (int p = 0; p < 3; p++) {
                uint32_t ah[2][4], al[2][4];
#pragma unroll
                for (int t = 0; t < 2; t++) {
                    const int row = wm * 32 + t * 16 + (lane & 15) + p;
                    const uint32_t off =
                        swz((uint32_t)(row * 128 + kk * 32 + (lane >> 4) * 16));
                    LDSM_X4(ah[t], sb + off);
                    LDSM_X4(al[t], sb + CONV_A + off);
                }
#pragma unroll
                for (int jp = 0; jp < 2; jp++) {
                    const int nrow = wn * 32 + jp * 16 + (lane & 7) + ((lane >> 4) << 3);
                    const uint32_t off =
                        swz((uint32_t)(nrow * 128 + kk * 32 + ((lane >> 3) & 1) * 16));
                    uint32_t bh[4];
                    LDSM_X4(bh, sb + 2 * CONV_A + (uint32_t)p * 16384 + off);
#pragma unroll
                    for (int t = 0; t < 2; t++) {
#pragma unroll
                        for (int jj = 0; jj < 2; jj++) {
                            float* d = acc[t][jp * 2 + jj];
                            MMA_F16(d, ah[t], bh[jj * 2], bh[jj * 2 + 1]);
                            MMA_F16(d, al[t], bh[jj * 2], bh[jj * 2 + 1]);
                        }
                    }
                }
            }
        }
    }

#pragma unroll
    for (int t = 0; t < 2; t++) {
        const int r0 = mBase + wm * 32 + t * 16 + (lane >> 2);
        float p0 = 0.f, p1 = 0.f;
#pragma unroll
        for (int j = 0; j < 4; j++) {
            const int col = nBase + wn * 32 + j * 8 + (lane & 3) * 2;
            const float b0 = bias[col], b1 = bias[col + 1];
            float v0 = acc[t][j][0] + b0, v1 = acc[t][j][1] + b1;
            float v2 = acc[t][j][2] + b0, v3 = acc[t][j][3] + b1;
            const size_t o0 = (size_t)r0 * Dsz + col;
            const size_t o1 = (size_t)(r0 + 8) * Dsz + col;
            *(float2*)(Cf + o0) = make_float2(v0, v1);
            *(float2*)(Cf + o1) = make_float2(v2, v3);
            const float w0 = __ldg(wgv + col), w1 = __ldg(wgv + col + 1);
            p0 = fmaf(v0, w0, fmaf(v1, w1, p0));
            p1 = fmaf(v2, w0, fmaf(v3, w1, p1));
        }
        p0 += __shfl_xor_sync(0xffffffffu, p0, 1);
        p0 += __shfl_xor_sync(0xffffffffu, p0, 2);
        p1 += __shfl_xor_sync(0xffffffffu, p1, 1);
        p1 += __shfl_xor_sync(0xffffffffu, p1, 2);
        if ((lane & 3) == 0) {
            float* gp = gateOut + ((size_t)((nBase >> 7) * 4 + wn)) * Tsz;
            gp[r0] = p0;
            gp[r0 + 8] = p1;
        }
    }
}

// ============================================================================
// Fused fc(+folded wout) + gated-MLP GEMM. Output: 1-term fp16 only (mo GEMM
// consumes single-term A).
// ============================================================================
#define FC_STAGE 65536
#define FCSMEM (2 * FC_STAGE)

__global__ __launch_bounds__(512, 1)
void mma_fc_k(const __half* __restrict__ Ah, const __half* __restrict__ Al,
              const __half* __restrict__ Wh, const float* __restrict__ bias,
              __half* __restrict__ Oh) {
    extern __shared__ char smem[];
    const uint32_t smb = smem_u32(smem);
    const int tid = threadIdx.x, lane = tid & 31, wid = tid >> 5;
    const int mBase = blockIdx.y << 7, nBase = blockIdx.x << 7;
    const int wm = wid & 3, wn = wid >> 2;

    float accg[2][4][4], accv[2][4][4];
#pragma unroll
    for (int t = 0; t < 2; t++)
#pragma unroll
        for (int j = 0; j < 4; j++)
#pragma unroll
            for (int q = 0; q < 4; q++) { accg[t][j][q] = 0.f; accv[t][j][q] = 0.f; }

    const int rowIdx = tid >> 3, col16 = tid & 7;

    auto issue = [&](int idx) {
        const uint32_t sb = smb + (uint32_t)(idx & 1) * FC_STAGE;
        const int kOff = idx * 64 + col16 * 8;
#pragma unroll
        for (int c = 0; c < 2; c++) {
            const int row = rowIdx + c * 64;
            const uint32_t dsw = swz((uint32_t)(row * 128 + col16 * 16));
            const size_t aoff = (size_t)(mBase + row) * Dsz + kOff;
            cp16(sb + dsw, Ah + aoff, true);
            cp16(sb + 16384 + dsw, Al + aoff, true);
            const size_t wgoff = (size_t)(nBase + row) * Dsz + kOff;
            cp16(sb + 32768 + dsw, Wh + wgoff, true);
            const size_t wvoff = (size_t)(512 + nBase + row) * Dsz + kOff;
            cp16(sb + 49152 + dsw, Wh + wvoff, true);
        }
        CP_COMMIT();
    };

    issue(0);
    for (int idx = 0; idx < 8; idx++) {
        asm volatile("cp.async.wait_group 0;" ::: "memory");
        __syncthreads();
        if (idx + 1 < 8) issue(idx + 1);
        const uint32_t sb = smb + (uint32_t)(idx & 1) * FC_STAGE;
#pragma unroll
        for (int kk = 0; kk < 4; kk++) {
            uint32_t ah[2][4], al[2][4];
#pragma unroll
            for (int t = 0; t < 2; t++) {
                const int row = wm * 32 + t * 16 + (lane & 15);
                const uint32_t off =
                    swz((uint32_t)(row * 128 + kk * 32 + (lane >> 4) * 16));
                LDSM_X4(ah[t], sb + off);
                LDSM_X4(al[t], sb + 16384 + off);
            }
#pragma unroll
            for (int jp = 0; jp < 2; jp++) {
                const int nrow = wn * 32 + jp * 16 + (lane & 7) + ((lane >> 4) << 3);
                const uint32_t off =
                    swz((uint32_t)(nrow * 128 + kk * 32 + ((lane >> 3) & 1) * 16));
                {
                    uint32_t bh[4];
                    LDSM_X4(bh, sb + 32768 + off);
#pragma unroll
                    for (int t = 0; t < 2; t++)
#pragma unroll
                        for (int jj = 0; jj < 2; jj++) {
                            float* d = accg[t][jp * 2 + jj];
                            MMA_F16(d, ah[t], bh[jj * 2], bh[jj * 2 + 1]);
                            MMA_F16(d, al[t], bh[jj * 2], bh[jj * 2 + 1]);
                        }
                }
                {
                    uint32_t bh[4];
                    LDSM_X4(bh, sb + 49152 + off);
#pragma unroll
                    for (int t = 0; t < 2; t++)
#pragma unroll
                        for (int jj = 0; jj < 2; jj++) {
                            float* d = accv[t][jp * 2 + jj];
                            MMA_F16(d, ah[t], bh[jj * 2], bh[jj * 2 + 1]);
                            MMA_F16(d, al[t], bh[jj * 2], bh[jj * 2 + 1]);
                        }
                }
            }
        }
    }

#pragma unroll
    for (int t = 0; t < 2; t++) {
#pragma unroll
        for (int j = 0; j < 4; j++) {
            const int r0 = mBase + wm * 32 + t * 16 + (lane >> 2);
            const int col = nBase + wn * 32 + j * 8 + (lane & 3) * 2;
            const float bg0 = bias[col], bg1 = bias[col + 1];
            const float bv0 = bias[512 + col], bv1 = bias[512 + col + 1];
            float s0 = 1.f / (1.f + expf(-(accg[t][j][0] + bg0)));
            float s1 = 1.f / (1.f + expf(-(accg[t][j][1] + bg1)));
            float s2 = 1.f / (1.f + expf(-(accg[t][j][2] + bg0)));
            float s3 = 1.f / (1.f + expf(-(accg[t][j][3] + bg1)));
            float v0 = s0 * (accv[t][j][0] + bv0);
            float v1 = s1 * (accv[t][j][1] + bv1);
            float v2 = s2 * (accv[t][j][2] + bv0);
            float v3 = s3 * (accv[t][j][3] + bv1);
            const size_t o0 = (size_t)r0 * Dsz + col;
            const size_t o1 = (size_t)(r0 + 8) * Dsz + col;
            *(__half2*)(Oh + o0) = __floats2half2_rn(v0, v1);
            *(__half2*)(Oh + o1) = __floats2half2_rn(v2, v3);
        }
    }
}

// ============================================================================
// Layer-0 conv as gather (exact fp32) + fused gate.
// ============================================================================
__global__ void conv0_k(const int* __restrict__ x, const float* __restrict__ w0t,
                        const float* __restrict__ u0, const float* __restrict__ cb,
                        const float* __restrict__ lng, const float* __restrict__ wgv,
                        const float* __restrict__ bg,
                        float* __restrict__ z2, float* __restrict__ gt) {
    const int t = blockIdx.x, tid = threadIdx.x;
    const int l = t & (Lsz - 1);
    const float mean = 1.0f / 512.0f;
    const float rstd = rsqrtf(mean * (511.0f / 512.0f) + 1e-5f);

    const int tokm = (l > 0) ? x[t - 1] : -1;
    const int tok0 = x[t];
    const int tokp = (l < Lsz - 1) ? x[t + 1] : -1;

    float4 acc = ((const float4*)cb)[tid];
    {
        const float s = rstd * lng[tok0];
        float4 w = ((const float4*)(w0t + (size_t)DD + (size_t)tok0 * Dsz))[tid];
        float4 u = ((const float4*)(u0 + Dsz))[tid];
        acc.x += s * w.x + u.x; acc.y += s * w.y + u.y;
        acc.z += s * w.z + u.z; acc.w += s * w.w + u.w;
    }
    if (tokm >= 0) {
        const float s = rstd * lng[tokm];
        float4 w = ((const float4*)(w0t + (size_t)tokm * Dsz))[tid];
        float4 u = ((const float4*)u0)[tid];
        acc.x += s * w.x + u.x; acc.y += s * w.y + u.y;
        acc.z += s * w.z + u.z; acc.w += s * w.w + u.w;
    }
    if (tokp >= 0) {
        const float s = rstd * lng[tokp];
        float4 w = ((const float4*)(w0t + (size_t)2 * DD + (size_t)tokp * Dsz))[tid];
        float4 u = ((const float4*)(u0 + 2 * Dsz))[tid];
        acc.x += s * w.x + u.x; acc.y += s * w.y + u.y;
        acc.z += s * w.z + u.z; acc.w += s * w.w + u.w;
    }
    ((float4*)(z2 + (size_t)t * Dsz))[tid] = acc;

    float4 wv = ((const float4*)wgv)[tid];
    float p = acc.x * wv.x + acc.y * wv.y + acc.z * wv.z + acc.w * wv.w;
#pragma unroll
    for (int o = 16; o; o >>= 1) p += __shfl_xor_sync(0xffffffffu, p, o);
    __shared__ float smr[4];
    if ((tid & 31) == 0) smr[tid >> 5] = p;
    __syncthreads();
    if (tid == 0) {
        float s = smr[0] + smr[1] + smr[2] + smr[3];
        gt[t] = 1.0f / (1.0f + expf(-(s + bg[0])));
    }
}

// ---------------- merged prep: weight converts + w0t + fc split + flag reset --
__global__ void prep_k(const float* __restrict__ conv_w, const float* __restrict__ mo_w,
                       const float* __restrict__ head_w, const float* __restrict__ wout,
                       const float* __restrict__ fc_w,
                       __half* __restrict__ wh, float* __restrict__ w0t,
                       __half* __restrict__ fch, __half* __restrict__ fcl) {
    const int idx = blockIdx.x * blockDim.x + threadIdx.x;   // 0 .. 32*DD-1
    if (idx < NFLAGS) g_sflag[idx] = 0;
    if (idx < 12 * DD) {
        int layer = idx / (3 * DD);
        int r = idx - layer * (3 * DD);
        int h = r / DD;
        int rr = r - h * DD;
        int o = rr >> 9, i = rr & 511;
        wh[idx] = __float2half_rn(conv_w[(size_t)layer * 3 * DD + ((size_t)o * Dsz + i) * 3 + h]);
    } else if (idx < 16 * DD) {
        int j = idx - 12 * DD;
        wh[W_MO(0) + j] = __float2half_rn(mo_w[j]);
    } else if (idx < 17 * DD) {
        int j = idx - 16 * DD;
        wh[W_HEAD + j] = __float2half_rn(head_w[j]);
    } else if (idx < 21 * DD) {
        int j = idx - 17 * DD;
        int layer = j / DD;
        int r = j - layer * DD;
        int n = r >> 9, k = r & 511;
        wh[W_WOUT(0) + j] = __float2half_rn(wout[(size_t)layer * DD + (size_t)k * Dsz + n]);
    } else if (idx < 24 * DD) {
        int j = idx - 21 * DD;
        int h = j / DD;
        int r = j - h * DD;
        int i = r >> 9, o = r & 511;
        w0t[j] = conv_w[((size_t)o * Dsz + i) * 3 + h];
    } else {
        int j = idx - 24 * DD;
        float v = fc_w[j];
        __half hi = __float2half_rn(v);
        fch[j] = hi;
        fcl[j] = __float2half_rn(v - __half2float(hi));
    }
}

// ---------------- layernorm with fused fp16 hi/lo split ----------------------
__global__ void ln_split_k(const float* __restrict__ in,
                           __half* __restrict__ oh, __half* __restrict__ ol,
                           const float* __restrict__ gamma, const float* __restrict__ beta) {
    int t = blockIdx.x, tid = threadIdx.x;
    const float4* rp = (const float4*)(in + (size_t)t * Dsz);
    float4 v = rp[tid];
    float s = v.x + v.y + v.z + v.w;
#pragma unroll
    for (int o = 16; o; o >>= 1) s += __shfl_xor_sync(0xffffffffu, s, o);
    __shared__ float smr[4];
    if ((tid & 31) == 0) smr[tid >> 5] = s;
    __syncthreads();
    float mean = (smr[0] + smr[1] + smr[2] + smr[3]) * (1.0f / Dsz);
    float dx = v.x - mean, dy = v.y - mean, dz = v.z - mean, dw = v.w - mean;
    float q = dx * dx + dy * dy + dz * dz + dw * dw;
#pragma unroll
    for (int o = 16; o; o >>= 1) q += __shfl_xor_sync(0xffffffffu, q, o);
    __syncthreads();
    if ((tid & 31) == 0) smr[tid >> 5] = q;
    __syncthreads();
    float var = (smr[0] + smr[1] + smr[2] + smr[3]) * (1.0f / Dsz);
    float rstd = rsqrtf(var + 1e-5f);
    float4 g4 = ((const float4*)gamma)[tid];
    float4 b4 = ((const float4*)beta)[tid];
    float f0 = dx * rstd * g4.x + b4.x, f1 = dy * rstd * g4.y + b4.y;
    float f2 = dz * rstd * g4.z + b4.z, f3 = dw * rstd * g4.w + b4.w;
    __half2 h01, l01, h23, l23;
    split2h(f0, f1, h01, l01);
    split2h(f2, f3, h23, l23);
    __half2* ph = (__half2*)(oh + (size_t)t * Dsz);
    __half2* pl = (__half2*)(ol + (size_t)t * Dsz);
    ph[2 * tid] = h01; ph[2 * tid + 1] = h23;
    pl[2 * tid] = l01; pl[2 * tid + 1] = l23;
}

// ---------------- u0 = W_h^T (lnb - rstd*mean*lng) -----------------------------
__global__ void u0_k(const float* __restrict__ cw, const float* __restrict__ lng,
                     const float* __restrict__ lnb, float* __restrict__ u0) {
    int w = (blockIdx.x * blockDim.x + threadIdx.x) >> 5;
    int lane = threadIdx.x & 31;
    int h = w >> 9, o = w & 511;
    const float mean = 1.0f / 512.0f;
    const float rstd = rsqrtf(mean * (511.0f / 512.0f) + 1e-5f);
    float s = 0.f;
#pragma unroll
    for (int c = 0; c < 16; c++) {
        int i = lane + 32 * c;
        float v = lnb[i] - rstd * mean * lng[i];
        s = fmaf(cw[((size_t)o * Dsz + i) * 3 + h], v, s);
    }
#pragma unroll
    for (int ofs = 16; ofs; ofs >>= 1) s += __shfl_xor_sync(0xffffffffu, s, ofs);
    if (lane == 0) u0[w] = s;
}

// ---------------- 1-term convert (Wcomb) ---------------------------------------
__global__ void wsplit1_k(const float* __restrict__ w, __half* __restrict__ wh, int n) {
    int idx = blockIdx.x * blockDim.x + threadIdx.x;
    if (idx >= n) return;
    wh[idx] = __float2half_rn(w[idx]);
}

// ---------------- bcomb = Wf·bo + fb --------------------------------------------
__global__ void bcomb_k(const float* __restrict__ fw, const float* __restrict__ bo,
                        const float* __restrict__ fb, float* __restrict__ out) {
    int w = (blockIdx.x * blockDim.x + threadIdx.x) >> 5;
    int lane = threadIdx.x & 31;
    int layer = w >> 10, e = w & 1023;
    const float* fr = fw + ((size_t)layer * 1024 + e) * Dsz;
    const float* br = bo + (size_t)layer * Dsz;
    float s = 0.f;
#pragma unroll
    for (int i = 0; i < 16; i++) s = fmaf(fr[lane + 32 * i], br[lane + 32 * i], s);
#pragma unroll
    for (int o = 16; o; o >>= 1) s += __shfl_xor_sync(0xffffffffu, s, o);
    if (lane == 0) out[w] = s + fb[(size_t)layer * 1024 + e];
}

// ============================================================================
// Unified chained scan; c=0 blocks emit outputs in pass 1 (carry = 0).
// Flags zeroed per call in prep_k -> deterministic across graph replays.
// ============================================================================
__global__ void scan_u_k(const float* __restrict__ z2,
                         const float* __restrict__ gatep,
                         const float* __restrict__ gt0,
                         const float* __restrict__ bgp,
                         float* __restrict__ hfin, int* __restrict__ flags,
                         __half* __restrict__ hh, __half* __restrict__ hl) {
    const int bx = blockIdx.x;
    const int c = bx >> 6, b = (bx >> 2) & 15, dch = bx & 3;
    const int tid = threadIdx.x;
    const int d = (dch << 7) + tid;
    const int l0 = c * SCH;
    __shared__ float gsm[SCH];

    if (gt0) {
        for (int j = tid; j < SCH; j += 128)
            gsm[j] = gt0[b * Lsz + l0 + j];
    } else {
        const float bgv = bgp[0];
        for (int j = tid; j < SCH; j += 128) {
            const int t = b * Lsz + l0 + j;
            float s = 0.f;
#pragma unroll
            for (int p = 0; p < 16; p++) s += gatep[(size_t)p * Tsz + t];
            gsm[j] = 1.0f / (1.0f + expf(-(s + bgv)));
        }
    }
    __syncthreads();

    const size_t base = (size_t)b * Lsz * Dsz + (size_t)l0 * Dsz + d;
    const bool first = (c == 0);
    float hv = 0.f, ap = 1.f;
    for (int l = 0; l < SCH; l += 8) {
        float xs[8], gs[8];
#pragma unroll
        for (int j = 0; j < 8; j++) {
            xs[j] = z2[base + (size_t)(l + j) * Dsz];
            gs[j] = gsm[l + j];
        }
#pragma unroll
        for (int j = 0; j < 8; j++) {
            hv = fmaf(gs[j], xs[j] - hv, hv);
            ap *= (1.f - gs[j]);
            if (first) {
                __half hi = __float2half_rn(hv);
                size_t o = base + (size_t)(l + j) * Dsz;
                hh[o] = hi;
                hl[o] = __float2half_rn(hv - __half2float(hi));
            }
        }
    }
    float carry = 0.f;
    const size_t fo = (size_t)c * (Bsz * Dsz) + (size_t)b * Dsz + d;
    if (!first) {
        if (tid == 0) {
            volatile int* f = flags + (bx - 64);
            while (*f == 0) {}
        }
        __syncthreads();
        __threadfence();
        carry = __ldcg(hfin + fo - (size_t)(Bsz * Dsz));
    }
    hfin[fo] = hv + ap * carry;
    __syncthreads();
    __threadfence();
    if (tid == 0) *((volatile int*)(flags + bx)) = 1;
    if (first) return;

    hv = carry;
    for (int l = 0; l < SCH; l += 8) {
        float xs[8], gs[8];
#pragma unroll
        for (int j = 0; j < 8; j++) {
            xs[j] = z2[base + (size_t)(l + j) * Dsz];
            gs[j] = gsm[l + j];
        }
#pragma unroll
        for (int j = 0; j < 8; j++) {
            hv = fmaf(gs[j], xs[j] - hv, hv);
            __half hi = __float2half_rn(hv);
            size_t o = base + (size_t)(l + j) * Dsz;
            hh[o] = hi;
            hl[o] = __float2half_rn(hv - __half2float(hi));
        }
    }
}

// ---------------- launch --------------------------------------------------------
extern "C" void kernel_launch(void* const* d_in, const int* in_sizes, int n_in,
                              void* d_out, int out_size) {
    const int* x = (const int*)d_in[0];
    const float* ln_g = (const float*)d_in[1];
    const float* ln_b = (const float*)d_in[2];
    const float* conv_w = (const float*)d_in[3];
    const float* conv_b = (const float*)d_in[4];
    const float* wg = (const float*)d_in[5];
    const float* bg = (const float*)d_in[6];
    const float* wout = (const float*)d_in[7];
    const float* bout = (const float*)d_in[8];
    const float* fc_w = (const float*)d_in[9];
    const float* fc_b = (const float*)d_in[10];
    const float* mo_w = (const float*)d_in[11];
    const float* mo_b = (const float*)d_in[12];
    const float* lnf_g = (const float*)d_in[13];
    const float* lnf_b = (const float*)d_in[14];
    const float* head_w = (const float*)d_in[15];
    const float* head_b = (const float*)d_in[16];

    float *y, *z2, *gt, *gp, *bcomb, *hfin, *w0t, *u0;
    int* sflag;
    __half *zh, *zl, *hh, *hl, *gh, *gl, *wh;
    cudaGetSymbolAddress((void**)&y, g_y);
    cudaGetSymbolAddress((void**)&z2, g_z2);
    cudaGetSymbolAddress((void**)&gt, g_gate);
    cudaGetSymbolAddress((void**)&gp, g_gatep);
    cudaGetSymbolAddress((void**)&bcomb, g_bcomb);
    cudaGetSymbolAddress((void**)&hfin, g_hfin);
    cudaGetSymbolAddress((void**)&sflag, g_sflag);
    cudaGetSymbolAddress((void**)&w0t, g_w0t);
    cudaGetSymbolAddress((void**)&u0, g_u0);
    cudaGetSymbolAddress((void**)&zh, g_zh);
    cudaGetSymbolAddress((void**)&zl, g_zl);
    cudaGetSymbolAddress((void**)&hh, g_hh);
    cudaGetSymbolAddress((void**)&hl, g_hl);
    cudaGetSymbolAddress((void**)&gh, g_gh);
    cudaGetSymbolAddress((void**)&gl, g_gl);
    cudaGetSymbolAddress((void**)&wh, g_wh);

    cudaFuncSetAttribute(mma_gemm_k, cudaFuncAttributeMaxDynamicSharedMemorySize, GSMEM);
    cudaFuncSetAttribute(mma_conv_k, cudaFuncAttributeMaxDynamicSharedMemorySize, CONVSMEM);
    cudaFuncSetAttribute(mma_fc_k, cudaFuncAttributeMaxDynamicSharedMemorySize, FCSMEM);

    const dim3 g512(4, Tsz / 128);

    // ---- prep: merged converts (+flag reset), bias fold, wout folding ----
    prep_k<<<(32 * DD) / 256, 256>>>(conv_w, mo_w, head_w, wout, fc_w, wh, w0t, gh, gl);
    bcomb_k<<<(NLsz * 1024 * 32) / 256, 256>>>(fc_w, bout, fc_b, bcomb);
    u0_k<<<(3 * Dsz * 32) / 256, 256>>>(conv_w, ln_g, ln_b, u0);
    // Wcomb = Wf @ Wo (batched over layers; A = fc split scratch, W = wout^T)
    mma_gemm_k<<<dim3(4, 32), 512, GSMEM>>>(gh, gl, wh + W_WOUT(0),
                                            nullptr, z2, nullptr, Dsz, 0, (int)DD);
    wsplit1_k<<<(8 * DD) / 256, 256>>>(z2, wh + W_FC(0), 8 * DD);

    for (int i = 0; i < NLsz; i++) {
        if (i == 0) {
            conv0_k<<<Tsz, 128>>>(x, w0t, u0, conv_b, ln_g, wg, bg, z2, gt);
        } else {
            ln_split_k<<<Tsz, 128>>>(y, zh, zl, ln_g + (size_t)i * Dsz, ln_b + (size_t)i * Dsz);
            mma_conv_k<<<g512, 512, CONVSMEM>>>(zh, zl, wh + W_CONV(i),
                                                conv_b + (size_t)i * Dsz, z2,
                                                wg + (size_t)i * Dsz, gp);
        }
        scan_u_k<<<NCH * 64, 128>>>(z2, gp, (i == 0) ? gt : nullptr, bg + i,
                                    hfin, sflag + (size_t)i * (NCH * Bsz * 4), hh, hl);
        mma_fc_k<<<g512, 512, FCSMEM>>>(hh, hl, wh + W_FC(i),
                                        bcomb + (size_t)i * 1024, gh);
        // mo GEMM: 1-term activations (Al = nullptr)
        mma_gemm_k<<<g512, 512, GSMEM>>>(gh, nullptr, wh + W_MO(i),
                                         mo_b + (size_t)i * Dsz, y,
                                         (i == 0) ? x : nullptr, Dsz,
                                         (i == 0) ? (1 | 16) : (1 | 2), 0);
    }

    ln_split_k<<<Tsz, 128>>>(y, zh, zl, lnf_g, lnf_b);
    // head GEMM: 1-term activations (terminal, non-compounding)
    mma_gemm_k<<<g512, 512, GSMEM>>>(zh, nullptr, wh + W_HEAD, head_b,
                                     (float*)d_out, nullptr, Dsz, 1, 0);
}

// round 14
// speedup vs baseline: 2.1573x; 1.5182x over previous
#include <cuda_runtime.h>
#include <cuda_fp16.h>
#include <cstdint>
#include <cstddef>

#define Bsz 16
#define Lsz 2048
#define Dsz 512
#define NLsz 4
#define Tsz (Bsz * Lsz)  // 32768
#define DD (Dsz * Dsz)

// weight arena offsets (units of DD)
#define W_CONV(i) ((size_t)(i) * 3 * DD)
#define W_WOUT(i) ((size_t)(12 + (i)) * DD)      // wout^T (prep only)
#define W_FC(i)   ((size_t)(16 + 2 * (i)) * DD)  // after prep: Wcomb = Wf@Wo
#define W_MO(i)   ((size_t)(24 + (i)) * DD)
#define W_HEAD    ((size_t)28 * DD)

// scan chunking
#define SCH 256
#define NCH (Lsz / SCH)  // 8
#define NFLAGS (NLsz * NCH * Bsz * 4)  // 2048

// ---------------- scratch (device globals; no allocation allowed) ----------
__device__ float g_y[Tsz * Dsz];
__device__ float g_z2[Tsz * Dsz];
__device__ float g_gate[Tsz];
__device__ float g_gatep[16 * Tsz];
__device__ float g_bcomb[NLsz * 2 * Dsz];
__device__ float g_hfin[NCH * Bsz * Dsz];
__device__ int   g_sflag[NFLAGS];
__device__ float g_w0t[3 * DD];
__device__ float g_u0[3 * Dsz];
__device__ __half g_zh[Tsz * Dsz];       // LN out (1-term)
__device__ __half g_hh[Tsz * Dsz];       // scan out (1-term)
__device__ __half g_gh[Tsz * Dsz];       // gated out (1-term) + prep scratch
__device__ __half g_wh[29 * DD];         // weights, 1-term fp16

// ---------------- helpers ---------------------------------------------------
__device__ __forceinline__ uint32_t smem_u32(const void* p) {
    return (uint32_t)__cvta_generic_to_shared(p);
}
__device__ __forceinline__ uint32_t swz(uint32_t x) { return x ^ ((x >> 3) & 0x70); }

__device__ __forceinline__ void cp16(uint32_t dst, const void* src, bool v) {
    int sz = v ? 16 : 0;
    asm volatile("cp.async.cg.shared.global [%0], [%1], 16, %2;"
                 :: "r"(dst), "l"(src), "r"(sz) : "memory");
}
#define CP_COMMIT() asm volatile("cp.async.commit_group;" ::: "memory")

#define LDSM_X4(r, a)                                                          \
    asm volatile("ldmatrix.sync.aligned.m8n8.x4.shared.b16 {%0,%1,%2,%3}, [%4];" \
                 : "=r"((r)[0]), "=r"((r)[1]), "=r"((r)[2]), "=r"((r)[3]) : "r"(a))

#define MMA_F16(d, a, b0, b1)                                                  \
    asm volatile(                                                              \
        "mma.sync.aligned.m16n8k16.row.col.f32.f16.f16.f32 "                   \
        "{%0,%1,%2,%3},{%4,%5,%6,%7},{%8,%9},{%0,%1,%2,%3};"                   \
        : "+f"((d)[0]), "+f"((d)[1]), "+f"((d)[2]), "+f"((d)[3])               \
        : "r"((a)[0]), "r"((a)[1]), "r"((a)[2]), "r"((a)[3]), "r"(b0), "r"(b1))

// ============================================================================
// Generic GEMM: A 1-term fp16, W 1-term. 512 thr, 128x128, 3-stage 32KB.
// flags: 1=addBias, 2=accum fp32, 16=one-hot residual add.
// ============================================================================
#define STAGE_B 32768
#define GSMEM (3 * STAGE_B)

__global__ __launch_bounds__(512, 1)
void mma_gemm_k(const __half* __restrict__ Ah, const __half* __restrict__ Wh,
                const float* __restrict__ bias, float* __restrict__ Cf,
                const int* __restrict__ xTok,
                int N, int flags, int wLayerStride) {
    extern __shared__ char smem[];
    const uint32_t smb = smem_u32(smem);
    const int tid = threadIdx.x, lane = tid & 31, wid = tid >> 5;
    const int mBase = blockIdx.y << 7, nBase = blockIdx.x << 7;
    const int wm = wid & 3, wn = wid >> 2;

    float acc[2][4][4];
#pragma unroll
    for (int t = 0; t < 2; t++)
#pragma unroll
        for (int j = 0; j < 4; j++)
#pragma unroll
            for (int q = 0; q < 4; q++) acc[t][j][q] = 0.f;

    const int rowIdx = tid >> 3, col16 = tid & 7;

    auto issue = [&](int idx) {
        const size_t wOff = (size_t)(mBase >> 10) * wLayerStride;
        const uint32_t sb = smb + (uint32_t)(idx % 3) * STAGE_B;
        const int kOff = idx * 64 + col16 * 8;
#pragma unroll
        for (int c = 0; c < 2; c++) {
            const int row = rowIdx + c * 64;
            const uint32_t dsw = swz((uint32_t)(row * 128 + col16 * 16));
            const size_t aoff = (size_t)(mBase + row) * Dsz + kOff;
            cp16(sb + dsw, Ah + aoff, true);
            const size_t woff = wOff + (size_t)(nBase + row) * Dsz + kOff;
            cp16(sb + 16384 + dsw, Wh + woff, true);
        }
        CP_COMMIT();
    };

    issue(0);
    issue(1);
    for (int idx = 0; idx < 8; idx++) {
        if (idx + 1 < 8) {
            asm volatile("cp.async.wait_group 1;" ::: "memory");
        } else {
            asm volatile("cp.async.wait_group 0;" ::: "memory");
        }
        __syncthreads();
        if (idx + 2 < 8) issue(idx + 2);
        const uint32_t sb = smb + (uint32_t)(idx % 3) * STAGE_B;
#pragma unroll
        for (int kk = 0; kk < 4; kk++) {
            uint32_t ah[2][4];
#pragma unroll
            for (int t = 0; t < 2; t++) {
                const int row = wm * 32 + t * 16 + (lane & 15);
                const uint32_t off =
                    swz((uint32_t)(row * 128 + kk * 32 + (lane >> 4) * 16));
                LDSM_X4(ah[t], sb + off);
            }
#pragma unroll
            for (int jp = 0; jp < 2; jp++) {
                const int nrow = wn * 32 + jp * 16 + (lane & 7) + ((lane >> 4) << 3);
                const uint32_t off =
                    swz((uint32_t)(nrow * 128 + kk * 32 + ((lane >> 3) & 1) * 16));
                uint32_t bh[4];
                LDSM_X4(bh, sb + 16384 + off);
#pragma unroll
                for (int t = 0; t < 2; t++) {
#pragma unroll
                    for (int jj = 0; jj < 2; jj++) {
                        MMA_F16(acc[t][jp * 2 + jj], ah[t], bh[jj * 2], bh[jj * 2 + 1]);
                    }
                }
            }
        }
    }

    const bool addB = (flags & 1) != 0;
    const bool accum = (flags & 2) != 0;
    const bool onehot = (flags & 16) != 0;
#pragma unroll
    for (int t = 0; t < 2; t++) {
        const int r0 = mBase + wm * 32 + t * 16 + (lane >> 2);
#pragma unroll
        for (int j = 0; j < 4; j++) {
            const int col = nBase + wn * 32 + j * 8 + (lane & 3) * 2;
            float b0 = 0.f, b1 = 0.f;
            if (addB) { b0 = bias[col]; b1 = bias[col + 1]; }
            float v0 = acc[t][j][0] + b0, v1 = acc[t][j][1] + b1;
            float v2 = acc[t][j][2] + b0, v3 = acc[t][j][3] + b1;
            const size_t o0 = (size_t)r0 * N + col;
            const size_t o1 = (size_t)(r0 + 8) * N + col;
            if (onehot) {
                const int t0 = xTok[r0], t1 = xTok[r0 + 8];
                v0 += (col == t0) ? 1.f : 0.f;
                v1 += (col + 1 == t0) ? 1.f : 0.f;
                v2 += (col == t1) ? 1.f : 0.f;
                v3 += (col + 1 == t1) ? 1.f : 0.f;
            }
            if (accum) {
                float2 q0 = *(float2*)(Cf + o0);
                float2 q1 = *(float2*)(Cf + o1);
                v0 += q0.x; v1 += q0.y; v2 += q1.x; v3 += q1.y;
            }
            *(float2*)(Cf + o0) = make_float2(v0, v1);
            *(float2*)(Cf + o1) = make_float2(v2, v3);
        }
    }
}

// ============================================================================
// Conv GEMM: 3 taps share one 130-row A tile (1-term A). Stage = A 17408 +
// 3x16384 W = 66560B, 2 stages. Epilogue: bias + z2 + gate partials.
// ============================================================================
#define CONV_A 17408
#define CONV_STAGE (CONV_A + 3 * 16384)  // 66560
#define CONVSMEM (2 * CONV_STAGE)        // 133120

__global__ __launch_bounds__(512, 1)
void mma_conv_k(const __half* __restrict__ Ah, const __half* __restrict__ Wh,
                const float* __restrict__ bias, float* __restrict__ Cf,
                const float* __restrict__ wgv, float* __restrict__ gateOut) {
    extern __shared__ char smem[];
    const uint32_t smb = smem_u32(smem);
    const int tid = threadIdx.x, lane = tid & 31, wid = tid >> 5;
    const int mBase = blockIdx.y << 7, nBase = blockIdx.x << 7;
    const int wm = wid & 3, wn = wid >> 2;

    float acc[2][4][4];
#pragma unroll
    for (int t = 0; t < 2; t++)
#pragma unroll
        for (int j = 0; j < 4; j++)
#pragma unroll
            for (int q = 0; q < 4; q++) acc[t][j][q] = 0.f;

    const int rowIdx = tid >> 3, col16 = tid & 7;
    const bool loVal = (mBase & (Lsz - 1)) != 0;
    const bool hiVal = ((mBase + 128) & (Lsz - 1)) != 0;

    auto issue = [&](int c8) {
        const uint32_t sb = smb + (uint32_t)(c8 & 1) * CONV_STAGE;
        const int kOff = c8 * 64 + col16 * 8;
#pragma unroll
        for (int c = 0; c < 2; c++) {
            const int sr = rowIdx + c * 64 + 1;
            const uint32_t dsw = swz((uint32_t)(sr * 128 + col16 * 16));
            const size_t aoff = (size_t)(mBase + sr - 1) * Dsz + kOff;
            cp16(sb + dsw, Ah + aoff, true);
        }
        if (tid < 8) {
            const uint32_t dsw = swz((uint32_t)(tid * 16));
            const int ko = c8 * 64 + tid * 8;
            const size_t aoff = (size_t)(loVal ? mBase - 1 : mBase) * Dsz + ko;
            cp16(sb + dsw, Ah + aoff, loVal);
        } else if (tid < 16) {
            const int cc = tid - 8;
            const uint32_t dsw = swz((uint32_t)(129 * 128 + cc * 16));
            const int ko = c8 * 64 + cc * 8;
            const size_t aoff = (size_t)(hiVal ? mBase + 128 : mBase) * Dsz + ko;
            cp16(sb + dsw, Ah + aoff, hiVal);
        }
#pragma unroll
        for (int p = 0; p < 3; p++) {
#pragma unroll
            for (int c = 0; c < 2; c++) {
                const int row = rowIdx + c * 64;
                const uint32_t dsw = swz((uint32_t)(row * 128 + col16 * 16));
                const size_t woff = (size_t)p * DD + (size_t)(nBase + row) * Dsz + kOff;
                cp16(sb + CONV_A + (uint32_t)p * 16384 + dsw, Wh + woff, true);
            }
        }
        CP_COMMIT();
    };

    issue(0);
    for (int c8 = 0; c8 < 8; c8++) {
        asm volatile("cp.async.wait_group 0;" ::: "memory");
        __syncthreads();
        if (c8 + 1 < 8) issue(c8 + 1);
        const uint32_t sb = smb + (uint32_t)(c8 & 1) * CONV_STAGE;
#pragma unroll
        for (int kk = 0; kk < 4; kk++) {
#pragma unroll
            for (int p = 0; p < 3; p++) {
                uint32_t ah[2][4];
#pragma unroll
                for (int t = 0; t < 2; t++) {
                    const int row = wm * 32 + t * 16 + (lane & 15) + p;
                    const uint32_t off =
                        swz((uint32_t)(row * 128 + kk * 32 + (lane >> 4) * 16));
                    LDSM_X4(ah[t], sb + off);
                }
#pragma unroll
                for (int jp = 0; jp < 2; jp++) {
                    const int nrow = wn * 32 + jp * 16 + (lane & 7) + ((lane >> 4) << 3);
                    const uint32_t off =
                        swz((uint32_t)(nrow * 128 + kk * 32 + ((lane >> 3) & 1) * 16));
                    uint32_t bh[4];
                    LDSM_X4(bh, sb + CONV_A + (uint32_t)p * 16384 + off);
#pragma unroll
                    for (int t = 0; t < 2; t++) {
#pragma unroll
                        for (int jj = 0; jj < 2; jj++) {
                            MMA_F16(acc[t][jp * 2 + jj], ah[t], bh[jj * 2], bh[jj * 2 + 1]);
                        }
                    }
                }
            }
        }
    }

#pragma unroll
    for (int t = 0; t < 2; t++) {
        const int r0 = mBase + wm * 32 + t * 16 + (lane >> 2);
        float p0 = 0.f, p1 = 0.f;
#pragma unroll
        for (int j = 0; j < 4; j++) {
            const int col = nBase + wn * 32 + j * 8 + (lane & 3) * 2;
            const float b0 = bias[col], b1 = bias[col + 1];
            float v0 = acc[t][j][0] + b0, v1 = acc[t][j][1] + b1;
            float v2 = acc[t][j][2] + b0, v3 = acc[t][j][3] + b1;
            const size_t o0 = (size_t)r0 * Dsz + col;
            const size_t o1 = (size_t)(r0 + 8) * Dsz + col;
            *(float2*)(Cf + o0) = make_float2(v0, v1);
            *(float2*)(Cf + o1) = make_float2(v2, v3);
            const float w0 = __ldg(wgv + col), w1 = __ldg(wgv + col + 1);
            p0 = fmaf(v0, w0, fmaf(v1, w1, p0));
            p1 = fmaf(v2, w0, fmaf(v3, w1, p1));
        }
        p0 += __shfl_xor_sync(0xffffffffu, p0, 1);
        p0 += __shfl_xor_sync(0xffffffffu, p0, 2);
        p1 += __shfl_xor_sync(0xffffffffu, p1, 1);
        p1 += __shfl_xor_sync(0xffffffffu, p1, 2);
        if ((lane & 3) == 0) {
            float* gp = gateOut + ((size_t)((nBase >> 7) * 4 + wn)) * Tsz;
            gp[r0] = p0;
            gp[r0 + 8] = p1;
        }
    }
}

// ============================================================================
// Fused fc(+folded wout) + gated-MLP GEMM, 1-term A. Stage = A|Wg|Wv = 48KB.
// ============================================================================
#define FC_STAGE 49152
#define FCSMEM (2 * FC_STAGE)

__global__ __launch_bounds__(512, 1)
void mma_fc_k(const __half* __restrict__ Ah, const __half* __restrict__ Wh,
              const float* __restrict__ bias, __half* __restrict__ Oh) {
    extern __shared__ char smem[];
    const uint32_t smb = smem_u32(smem);
    const int tid = threadIdx.x, lane = tid & 31, wid = tid >> 5;
    const int mBase = blockIdx.y << 7, nBase = blockIdx.x << 7;
    const int wm = wid & 3, wn = wid >> 2;

    float accg[2][4][4], accv[2][4][4];
#pragma unroll
    for (int t = 0; t < 2; t++)
#pragma unroll
        for (int j = 0; j < 4; j++)
#pragma unroll
            for (int q = 0; q < 4; q++) { accg[t][j][q] = 0.f; accv[t][j][q] = 0.f; }

    const int rowIdx = tid >> 3, col16 = tid & 7;

    auto issue = [&](int idx) {
        const uint32_t sb = smb + (uint32_t)(idx & 1) * FC_STAGE;
        const int kOff = idx * 64 + col16 * 8;
#pragma unroll
        for (int c = 0; c < 2; c++) {
            const int row = rowIdx + c * 64;
            const uint32_t dsw = swz((uint32_t)(row * 128 + col16 * 16));
            const size_t aoff = (size_t)(mBase + row) * Dsz + kOff;
            cp16(sb + dsw, Ah + aoff, true);
            const size_t wgoff = (size_t)(nBase + row) * Dsz + kOff;
            cp16(sb + 16384 + dsw, Wh + wgoff, true);
            const size_t wvoff = (size_t)(512 + nBase + row) * Dsz + kOff;
            cp16(sb + 32768 + dsw, Wh + wvoff, true);
        }
        CP_COMMIT();
    };

    issue(0);
    for (int idx = 0; idx < 8; idx++) {
        asm volatile("cp.async.wait_group 0;" ::: "memory");
        __syncthreads();
        if (idx + 1 < 8) issue(idx + 1);
        const uint32_t sb = smb + (uint32_t)(idx & 1) * FC_STAGE;
#pragma unroll
        for (int kk = 0; kk < 4; kk++) {
            uint32_t ah[2][4];
#pragma unroll
            for (int t = 0; t < 2; t++) {
                const int row = wm * 32 + t * 16 + (lane & 15);
                const uint32_t off =
                    swz((uint32_t)(row * 128 + kk * 32 + (lane >> 4) * 16));
                LDSM_X4(ah[t], sb + off);
            }
#pragma unroll
            for (int jp = 0; jp < 2; jp++) {
                const int nrow = wn * 32 + jp * 16 + (lane & 7) + ((lane >> 4) << 3);
                const uint32_t off =
                    swz((uint32_t)(nrow * 128 + kk * 32 + ((lane >> 3) & 1) * 16));
                {
                    uint32_t bh[4];
                    LDSM_X4(bh, sb + 16384 + off);
#pragma unroll
                    for (int t = 0; t < 2; t++)
#pragma unroll
                        for (int jj = 0; jj < 2; jj++)
                            MMA_F16(accg[t][jp * 2 + jj], ah[t], bh[jj * 2], bh[jj * 2 + 1]);
                }
                {
                    uint32_t bh[4];
                    LDSM_X4(bh, sb + 32768 + off);
#pragma unroll
                    for (int t = 0; t < 2; t++)
#pragma unroll
                        for (int jj = 0; jj < 2; jj++)
                            MMA_F16(accv[t][jp * 2 + jj], ah[t], bh[jj * 2], bh[jj * 2 + 1]);
                }
            }
        }
    }

#pragma unroll
    for (int t = 0; t < 2; t++) {
#pragma unroll
        for (int j = 0; j < 4; j++) {
            const int r0 = mBase + wm * 32 + t * 16 + (lane >> 2);
            const int col = nBase + wn * 32 + j * 8 + (lane & 3) * 2;
            const float bg0 = bias[col], bg1 = bias[col + 1];
            const float bv0 = bias[512 + col], bv1 = bias[512 + col + 1];
            float s0 = 1.f / (1.f + expf(-(accg[t][j][0] + bg0)));
            float s1 = 1.f / (1.f + expf(-(accg[t][j][1] + bg1)));
            float s2 = 1.f / (1.f + expf(-(accg[t][j][2] + bg0)));
            float s3 = 1.f / (1.f + expf(-(accg[t][j][3] + bg1)));
            float v0 = s0 * (accv[t][j][0] + bv0);
            float v1 = s1 * (accv[t][j][1] + bv1);
            float v2 = s2 * (accv[t][j][2] + bv0);
            float v3 = s3 * (accv[t][j][3] + bv1);
            const size_t o0 = (size_t)r0 * Dsz + col;
            const size_t o1 = (size_t)(r0 + 8) * Dsz + col;
            *(__half2*)(Oh + o0) = __floats2half2_rn(v0, v1);
            *(__half2*)(Oh + o1) = __floats2half2_rn(v2, v3);
        }
    }
}

// ============================================================================
// Layer-0 conv as gather (exact fp32) + fused gate.
// ============================================================================
__global__ void conv0_k(const int* __restrict__ x, const float* __restrict__ w0t,
                        const float* __restrict__ u0, const float* __restrict__ cb,
                        const float* __restrict__ lng, const float* __restrict__ wgv,
                        const float* __restrict__ bg,
                        float* __restrict__ z2, float* __restrict__ gt) {
    const int t = blockIdx.x, tid = threadIdx.x;
    const int l = t & (Lsz - 1);
    const float mean = 1.0f / 512.0f;
    const float rstd = rsqrtf(mean * (511.0f / 512.0f) + 1e-5f);

    const int tokm = (l > 0) ? x[t - 1] : -1;
    const int tok0 = x[t];
    const int tokp = (l < Lsz - 1) ? x[t + 1] : -1;

    float4 acc = ((const float4*)cb)[tid];
    {
        const float s = rstd * lng[tok0];
        float4 w = ((const float4*)(w0t + (size_t)DD + (size_t)tok0 * Dsz))[tid];
        float4 u = ((const float4*)(u0 + Dsz))[tid];
        acc.x += s * w.x + u.x; acc.y += s * w.y + u.y;
        acc.z += s * w.z + u.z; acc.w += s * w.w + u.w;
    }
    if (tokm >= 0) {
        const float s = rstd * lng[tokm];
        float4 w = ((const float4*)(w0t + (size_t)tokm * Dsz))[tid];
        float4 u = ((const float4*)u0)[tid];
        acc.x += s * w.x + u.x; acc.y += s * w.y + u.y;
        acc.z += s * w.z + u.z; acc.w += s * w.w + u.w;
    }
    if (tokp >= 0) {
        const float s = rstd * lng[tokp];
        float4 w = ((const float4*)(w0t + (size_t)2 * DD + (size_t)tokp * Dsz))[tid];
        float4 u = ((const float4*)(u0 + 2 * Dsz))[tid];
        acc.x += s * w.x + u.x; acc.y += s * w.y + u.y;
        acc.z += s * w.z + u.z; acc.w += s * w.w + u.w;
    }
    ((float4*)(z2 + (size_t)t * Dsz))[tid] = acc;

    float4 wv = ((const float4*)wgv)[tid];
    float p = acc.x * wv.x + acc.y * wv.y + acc.z * wv.z + acc.w * wv.w;
#pragma unroll
    for (int o = 16; o; o >>= 1) p += __shfl_xor_sync(0xffffffffu, p, o);
    __shared__ float smr[4];
    if ((tid & 31) == 0) smr[tid >> 5] = p;
    __syncthreads();
    if (tid == 0) {
        float s = smr[0] + smr[1] + smr[2] + smr[3];
        gt[t] = 1.0f / (1.0f + expf(-(s + bg[0])));
    }
}

// ---------------- merged prep: 1-term converts + w0t + flag reset -------------
__global__ void prep_k(const float* __restrict__ conv_w, const float* __restrict__ mo_w,
                       const float* __restrict__ head_w, const float* __restrict__ wout,
                       const float* __restrict__ fc_w,
                       __half* __restrict__ wh, float* __restrict__ w0t,
                       __half* __restrict__ fch) {
    const int idx = blockIdx.x * blockDim.x + threadIdx.x;   // 0 .. 32*DD-1
    if (idx < NFLAGS) g_sflag[idx] = 0;
    if (idx < 12 * DD) {
        int layer = idx / (3 * DD);
        int r = idx - layer * (3 * DD);
        int h = r / DD;
        int rr = r - h * DD;
        int o = rr >> 9, i = rr & 511;
        wh[idx] = __float2half_rn(conv_w[(size_t)layer * 3 * DD + ((size_t)o * Dsz + i) * 3 + h]);
    } else if (idx < 16 * DD) {
        int j = idx - 12 * DD;
        wh[W_MO(0) + j] = __float2half_rn(mo_w[j]);
    } else if (idx < 17 * DD) {
        int j = idx - 16 * DD;
        wh[W_HEAD + j] = __float2half_rn(head_w[j]);
    } else if (idx < 21 * DD) {
        int j = idx - 17 * DD;
        int layer = j / DD;
        int r = j - layer * DD;
        int n = r >> 9, k = r & 511;
        wh[W_WOUT(0) + j] = __float2half_rn(wout[(size_t)layer * DD + (size_t)k * Dsz + n]);
    } else if (idx < 24 * DD) {
        int j = idx - 21 * DD;
        int h = j / DD;
        int r = j - h * DD;
        int i = r >> 9, o = r & 511;
        w0t[j] = conv_w[((size_t)o * Dsz + i) * 3 + h];
    } else {
        int j = idx - 24 * DD;                 // fc 1-term (prep scratch)
        fch[j] = __float2half_rn(fc_w[j]);
    }
}

// ---------------- layernorm with fp16 output ----------------------------------
__global__ void ln_h_k(const float* __restrict__ in, __half* __restrict__ oh,
                       const float* __restrict__ gamma, const float* __restrict__ beta) {
    int t = blockIdx.x, tid = threadIdx.x;
    const float4* rp = (const float4*)(in + (size_t)t * Dsz);
    float4 v = rp[tid];
    float s = v.x + v.y + v.z + v.w;
#pragma unroll
    for (int o = 16; o; o >>= 1) s += __shfl_xor_sync(0xffffffffu, s, o);
    __shared__ float smr[4];
    if ((tid & 31) == 0) smr[tid >> 5] = s;
    __syncthreads();
    float mean = (smr[0] + smr[1] + smr[2] + smr[3]) * (1.0f / Dsz);
    float dx = v.x - mean, dy = v.y - mean, dz = v.z - mean, dw = v.w - mean;
    float q = dx * dx + dy * dy + dz * dz + dw * dw;
#pragma unroll
    for (int o = 16; o; o >>= 1) q += __shfl_xor_sync(0xffffffffu, q, o);
    __syncthreads();
    if ((tid & 31) == 0) smr[tid >> 5] = q;
    __syncthreads();
    float var = (smr[0] + smr[1] + smr[2] + smr[3]) * (1.0f / Dsz);
    float rstd = rsqrtf(var + 1e-5f);
    float4 g4 = ((const float4*)gamma)[tid];
    float4 b4 = ((const float4*)beta)[tid];
    float f0 = dx * rstd * g4.x + b4.x, f1 = dy * rstd * g4.y + b4.y;
    float f2 = dz * rstd * g4.z + b4.z, f3 = dw * rstd * g4.w + b4.w;
    __half2* ph = (__half2*)(oh + (size_t)t * Dsz);
    ph[2 * tid] = __floats2half2_rn(f0, f1);
    ph[2 * tid + 1] = __floats2half2_rn(f2, f3);
}

// ---------------- u0 = W_h^T (lnb - rstd*mean*lng) -----------------------------
__global__ void u0_k(const float* __restrict__ cw, const float* __restrict__ lng,
                     const float* __restrict__ lnb, float* __restrict__ u0) {
    int w = (blockIdx.x * blockDim.x + threadIdx.x) >> 5;
    int lane = threadIdx.x & 31;
    int h = w >> 9, o = w & 511;
    const float mean = 1.0f / 512.0f;
    const float rstd = rsqrtf(mean * (511.0f / 512.0f) + 1e-5f);
    float s = 0.f;
#pragma unroll
    for (int c = 0; c < 16; c++) {
        int i = lane + 32 * c;
        float v = lnb[i] - rstd * mean * lng[i];
        s = fmaf(cw[((size_t)o * Dsz + i) * 3 + h], v, s);
    }
#pragma unroll
    for (int ofs = 16; ofs; ofs >>= 1) s += __shfl_xor_sync(0xffffffffu, s, ofs);
    if (lane == 0) u0[w] = s;
}

// ---------------- 1-term convert (Wcomb) ---------------------------------------
__global__ void wsplit1_k(const float* __restrict__ w, __half* __restrict__ wh, int n) {
    int idx = blockIdx.x * blockDim.x + threadIdx.x;
    if (idx >= n) return;
    wh[idx] = __float2half_rn(w[idx]);
}

// ---------------- bcomb = Wf·bo + fb --------------------------------------------
__global__ void bcomb_k(const float* __restrict__ fw, const float* __restrict__ bo,
                        const float* __restrict__ fb, float* __restrict__ out) {
    int w = (blockIdx.x * blockDim.x + threadIdx.x) >> 5;
    int lane = threadIdx.x & 31;
    int layer = w >> 10, e = w & 1023;
    const float* fr = fw + ((size_t)layer * 1024 + e) * Dsz;
    const float* br = bo + (size_t)layer * Dsz;
    float s = 0.f;
#pragma unroll
    for (int i = 0; i < 16; i++) s = fmaf(fr[lane + 32 * i], br[lane + 32 * i], s);
#pragma unroll
    for (int o = 16; o; o >>= 1) s += __shfl_xor_sync(0xffffffffu, s, o);
    if (lane == 0) out[w] = s + fb[(size_t)layer * 1024 + e];
}

// ============================================================================
// Unified chained scan; c=0 emits in pass 1. 1-term fp16 output.
// Flags zeroed per call in prep_k -> deterministic across graph replays.
// ============================================================================
__global__ void scan_u_k(const float* __restrict__ z2,
                         const float* __restrict__ gatep,
                         const float* __restrict__ gt0,
                         const float* __restrict__ bgp,
                         float* __restrict__ hfin, int* __restrict__ flags,
                         __half* __restrict__ hh) {
    const int bx = blockIdx.x;
    const int c = bx >> 6, b = (bx >> 2) & 15, dch = bx & 3;
    const int tid = threadIdx.x;
    const int d = (dch << 7) + tid;
    const int l0 = c * SCH;
    __shared__ float gsm[SCH];

    if (gt0) {
        for (int j = tid; j < SCH; j += 128)
            gsm[j] = gt0[b * Lsz + l0 + j];
    } else {
        const float bgv = bgp[0];
        for (int j = tid; j < SCH; j += 128) {
            const int t = b * Lsz + l0 + j;
            float s = 0.f;
#pragma unroll
            for (int p = 0; p < 16; p++) s += gatep[(size_t)p * Tsz + t];
            gsm[j] = 1.0f / (1.0f + expf(-(s + bgv)));
        }
    }
    __syncthreads();

    const size_t base = (size_t)b * Lsz * Dsz + (size_t)l0 * Dsz + d;
    const bool first = (c == 0);
    float hv = 0.f, ap = 1.f;
    for (int l = 0; l < SCH; l += 8) {
        float xs[8], gs[8];
#pragma unroll
        for (int j = 0; j < 8; j++) {
            xs[j] = z2[base + (size_t)(l + j) * Dsz];
            gs[j] = gsm[l + j];
        }
#pragma unroll
        for (int j = 0; j < 8; j++) {
            hv = fmaf(gs[j], xs[j] - hv, hv);
            ap *= (1.f - gs[j]);
            if (first) hh[base + (size_t)(l + j) * Dsz] = __float2half_rn(hv);
        }
    }
    float carry = 0.f;
    const size_t fo = (size_t)c * (Bsz * Dsz) + (size_t)b * Dsz + d;
    if (!first) {
        if (tid == 0) {
            volatile int* f = flags + (bx - 64);
            while (*f == 0) {}
        }
        __syncthreads();
        __threadfence();
        carry = __ldcg(hfin + fo - (size_t)(Bsz * Dsz));
    }
    hfin[fo] = hv + ap * carry;
    __syncthreads();
    __threadfence();
    if (tid == 0) *((volatile int*)(flags + bx)) = 1;
    if (first) return;

    hv = carry;
    for (int l = 0; l < SCH; l += 8) {
        float xs[8], gs[8];
#pragma unroll
        for (int j = 0; j < 8; j++) {
            xs[j] = z2[base + (size_t)(l + j) * Dsz];
            gs[j] = gsm[l + j];
        }
#pragma unroll
        for (int j = 0; j < 8; j++) {
            hv = fmaf(gs[j], xs[j] - hv, hv);
            hh[base + (size_t)(l + j) * Dsz] = __float2half_rn(hv);
        }
    }
}

// ---------------- launch --------------------------------------------------------
extern "C" void kernel_launch(void* const* d_in, const int* in_sizes, int n_in,
                              void* d_out, int out_size) {
    const int* x = (const int*)d_in[0];
    const float* ln_g = (const float*)d_in[1];
    const float* ln_b = (const float*)d_in[2];
    const float* conv_w = (const float*)d_in[3];
    const float* conv_b = (const float*)d_in[4];
    const float* wg = (const float*)d_in[5];
    const float* bg = (const float*)d_in[6];
    const float* wout = (const float*)d_in[7];
    const float* bout = (const float*)d_in[8];
    const float* fc_w = (const float*)d_in[9];
    const float* fc_b = (const float*)d_in[10];
    const float* mo_w = (const float*)d_in[11];
    const float* mo_b = (const float*)d_in[12];
    const float* lnf_g = (const float*)d_in[13];
    const float* lnf_b = (const float*)d_in[14];
    const float* head_w = (const float*)d_in[15];
    const float* head_b = (const float*)d_in[16];

    float *y, *z2, *gt, *gp, *bcomb, *hfin, *w0t, *u0;
    int* sflag;
    __half *zh, *hh, *gh, *wh;
    cudaGetSymbolAddress((void**)&y, g_y);
    cudaGetSymbolAddress((void**)&z2, g_z2);
    cudaGetSymbolAddress((void**)&gt, g_gate);
    cudaGetSymbolAddress((void**)&gp, g_gatep);
    cudaGetSymbolAddress((void**)&bcomb, g_bcomb);
    cudaGetSymbolAddress((void**)&hfin, g_hfin);
    cudaGetSymbolAddress((void**)&sflag, g_sflag);
    cudaGetSymbolAddress((void**)&w0t, g_w0t);
    cudaGetSymbolAddress((void**)&u0, g_u0);
    cudaGetSymbolAddress((void**)&zh, g_zh);
    cudaGetSymbolAddress((void**)&hh, g_hh);
    cudaGetSymbolAddress((void**)&gh, g_gh);
    cudaGetSymbolAddress((void**)&wh, g_wh);

    cudaFuncSetAttribute(mma_gemm_k, cudaFuncAttributeMaxDynamicSharedMemorySize, GSMEM);
    cudaFuncSetAttribute(mma_conv_k, cudaFuncAttributeMaxDynamicSharedMemorySize, CONVSMEM);
    cudaFuncSetAttribute(mma_fc_k, cudaFuncAttributeMaxDynamicSharedMemorySize, FCSMEM);

    const dim3 g512(4, Tsz / 128);

    // ---- prep: merged converts (+flag reset), bias fold, wout folding ----
    prep_k<<<(32 * DD) / 256, 256>>>(conv_w, mo_w, head_w, wout, fc_w, wh, w0t, gh);
    bcomb_k<<<(NLsz * 1024 * 32) / 256, 256>>>(fc_w, bout, fc_b, bcomb);
    u0_k<<<(3 * Dsz * 32) / 256, 256>>>(conv_w, ln_g, ln_b, u0);
    // Wcomb = Wf @ Wo (batched over layers; A = fc 1-term scratch, W = wout^T)
    mma_gemm_k<<<dim3(4, 32), 512, GSMEM>>>(gh, wh + W_WOUT(0),
                                            nullptr, z2, nullptr, Dsz, 0, (int)DD);
    wsplit1_k<<<(8 * DD) / 256, 256>>>(z2, wh + W_FC(0), 8 * DD);

    for (int i = 0; i < NLsz; i++) {
        if (i == 0) {
            conv0_k<<<Tsz, 128>>>(x, w0t, u0, conv_b, ln_g, wg, bg, z2, gt);
        } else {
            ln_h_k<<<Tsz, 128>>>(y, zh, ln_g + (size_t)i * Dsz, ln_b + (size_t)i * Dsz);
            mma_conv_k<<<g512, 512, CONVSMEM>>>(zh, wh + W_CONV(i),
                                                conv_b + (size_t)i * Dsz, z2,
                                                wg + (size_t)i * Dsz, gp);
        }
        scan_u_k<<<NCH * 64, 128>>>(z2, gp, (i == 0) ? gt : nullptr, bg + i,
                                    hfin, sflag + (size_t)i * (NCH * Bsz * 4), hh);
        mma_fc_k<<<g512, 512, FCSMEM>>>(hh, wh + W_FC(i),
                                        bcomb + (size_t)i * 1024, gh);
        mma_gemm_k<<<g512, 512, GSMEM>>>(gh, wh + W_MO(i),
                                         mo_b + (size_t)i * Dsz, y,
                                         (i == 0) ? x : nullptr, Dsz,
                                         (i == 0) ? (1 | 16) : (1 | 2), 0);
    }

    ln_h_k<<<Tsz, 128>>>(y, zh, lnf_g, lnf_b);
    mma_gemm_k<<<g512, 512, GSMEM>>>(zh, wh + W_HEAD, head_b,
                                     (float*)d_out, nullptr, Dsz, 1, 0);
}

// round 15
// speedup vs baseline: 2.2518x; 1.0438x over previous
#include <cuda_runtime.h>
#include <cuda_fp16.h>
#include <cstdint>
#include <cstddef>

#define Bsz 16
#define Lsz 2048
#define Dsz 512
#define NLsz 4
#define Tsz (Bsz * Lsz)  // 32768
#define DD (Dsz * Dsz)

// weight arena offsets (units of DD)
#define W_CONV(i) ((size_t)(i) * 3 * DD)
#define W_WOUT(i) ((size_t)(12 + (i)) * DD)      // wout^T (prep only)
#define W_FC(i)   ((size_t)(16 + 2 * (i)) * DD)  // after prep: Wcomb = Wf@Wo
#define W_MO(i)   ((size_t)(24 + (i)) * DD)
#define W_HEAD    ((size_t)28 * DD)

// scan chunking
#define SCH 256
#define NCH (Lsz / SCH)  // 8
#define NFLAGS (NLsz * NCH * Bsz * 4)  // 2048

// ---------------- scratch (device globals; no allocation allowed) ----------
__device__ float g_y[Tsz * Dsz];             // residual; also Wcomb prep scratch
__device__ float g_gate[Tsz];
__device__ float g_gatep[16 * Tsz];
__device__ float g_bcomb[NLsz * 2 * Dsz];
__device__ float g_hfin[NCH * Bsz * Dsz];
__device__ int   g_sflag[NFLAGS];
__device__ float g_w0t[3 * DD];
__device__ float g_u0[3 * Dsz];
__device__ __half g_z2h[Tsz * Dsz];          // conv out (fp16)
__device__ __half g_zh[Tsz * Dsz];           // LN out
__device__ __half g_hh[Tsz * Dsz];           // scan out
__device__ __half g_gh[Tsz * Dsz];           // gated out + prep scratch
__device__ __half g_wh[29 * DD];             // weights, 1-term fp16

// ---------------- helpers ---------------------------------------------------
__device__ __forceinline__ uint32_t smem_u32(const void* p) {
    return (uint32_t)__cvta_generic_to_shared(p);
}
__device__ __forceinline__ uint32_t swz(uint32_t x) { return x ^ ((x >> 3) & 0x70); }

__device__ __forceinline__ void cp16(uint32_t dst, const void* src, bool v) {
    int sz = v ? 16 : 0;
    asm volatile("cp.async.cg.shared.global [%0], [%1], 16, %2;"
                 :: "r"(dst), "l"(src), "r"(sz) : "memory");
}
#define CP_COMMIT() asm volatile("cp.async.commit_group;" ::: "memory")

#define LDSM_X4(r, a)                                                          \
    asm volatile("ldmatrix.sync.aligned.m8n8.x4.shared.b16 {%0,%1,%2,%3}, [%4];" \
                 : "=r"((r)[0]), "=r"((r)[1]), "=r"((r)[2]), "=r"((r)[3]) : "r"(a))

#define MMA_F16(d, a, b0, b1)                                                  \
    asm volatile(                                                              \
        "mma.sync.aligned.m16n8k16.row.col.f32.f16.f16.f32 "                   \
        "{%0,%1,%2,%3},{%4,%5,%6,%7},{%8,%9},{%0,%1,%2,%3};"                   \
        : "+f"((d)[0]), "+f"((d)[1]), "+f"((d)[2]), "+f"((d)[3])               \
        : "r"((a)[0]), "r"((a)[1]), "r"((a)[2]), "r"((a)[3]), "r"(b0), "r"(b1))

// ============================================================================
// Generic GEMM: A 1-term fp16, W 1-term. 512 thr, 128x128, 3-stage 32KB.
// flags: 1=addBias, 2=accum fp32, 16=one-hot residual add.
// ============================================================================
#define STAGE_B 32768
#define GSMEM (3 * STAGE_B)

__global__ __launch_bounds__(512, 1)
void mma_gemm_k(const __half* __restrict__ Ah, const __half* __restrict__ Wh,
                const float* __restrict__ bias, float* __restrict__ Cf,
                const int* __restrict__ xTok,
                int N, int flags, int wLayerStride) {
    extern __shared__ char smem[];
    const uint32_t smb = smem_u32(smem);
    const int tid = threadIdx.x, lane = tid & 31, wid = tid >> 5;
    const int mBase = blockIdx.y << 7, nBase = blockIdx.x << 7;
    const int wm = wid & 3, wn = wid >> 2;

    float acc[2][4][4];
#pragma unroll
    for (int t = 0; t < 2; t++)
#pragma unroll
        for (int j = 0; j < 4; j++)
#pragma unroll
            for (int q = 0; q < 4; q++) acc[t][j][q] = 0.f;

    const int rowIdx = tid >> 3, col16 = tid & 7;

    auto issue = [&](int idx) {
        const size_t wOff = (size_t)(mBase >> 10) * wLayerStride;
        const uint32_t sb = smb + (uint32_t)(idx % 3) * STAGE_B;
        const int kOff = idx * 64 + col16 * 8;
#pragma unroll
        for (int c = 0; c < 2; c++) {
            const int row = rowIdx + c * 64;
            const uint32_t dsw = swz((uint32_t)(row * 128 + col16 * 16));
            const size_t aoff = (size_t)(mBase + row) * Dsz + kOff;
            cp16(sb + dsw, Ah + aoff, true);
            const size_t woff = wOff + (size_t)(nBase + row) * Dsz + kOff;
            cp16(sb + 16384 + dsw, Wh + woff, true);
        }
        CP_COMMIT();
    };

    issue(0);
    issue(1);
    for (int idx = 0; idx < 8; idx++) {
        if (idx + 1 < 8) {
            asm volatile("cp.async.wait_group 1;" ::: "memory");
        } else {
            asm volatile("cp.async.wait_group 0;" ::: "memory");
        }
        __syncthreads();
        if (idx + 2 < 8) issue(idx + 2);
        const uint32_t sb = smb + (uint32_t)(idx % 3) * STAGE_B;
#pragma unroll
        for (int kk = 0; kk < 4; kk++) {
            uint32_t ah[2][4];
#pragma unroll
            for (int t = 0; t < 2; t++) {
                const int row = wm * 32 + t * 16 + (lane & 15);
                const uint32_t off =
                    swz((uint32_t)(row * 128 + kk * 32 + (lane >> 4) * 16));
                LDSM_X4(ah[t], sb + off);
            }
#pragma unroll
            for (int jp = 0; jp < 2; jp++) {
                const int nrow = wn * 32 + jp * 16 + (lane & 7) + ((lane >> 4) << 3);
                const uint32_t off =
                    swz((uint32_t)(nrow * 128 + kk * 32 + ((lane >> 3) & 1) * 16));
                uint32_t bh[4];
                LDSM_X4(bh, sb + 16384 + off);
#pragma unroll
                for (int t = 0; t < 2; t++) {
#pragma unroll
                    for (int jj = 0; jj < 2; jj++) {
                        MMA_F16(acc[t][jp * 2 + jj], ah[t], bh[jj * 2], bh[jj * 2 + 1]);
                    }
                }
            }
        }
    }

    const bool addB = (flags & 1) != 0;
    const bool accum = (flags & 2) != 0;
    const bool onehot = (flags & 16) != 0;
#pragma unroll
    for (int t = 0; t < 2; t++) {
        const int r0 = mBase + wm * 32 + t * 16 + (lane >> 2);
#pragma unroll
        for (int j = 0; j < 4; j++) {
            const int col = nBase + wn * 32 + j * 8 + (lane & 3) * 2;
            float b0 = 0.f, b1 = 0.f;
            if (addB) { b0 = bias[col]; b1 = bias[col + 1]; }
            float v0 = acc[t][j][0] + b0, v1 = acc[t][j][1] + b1;
            float v2 = acc[t][j][2] + b0, v3 = acc[t][j][3] + b1;
            const size_t o0 = (size_t)r0 * N + col;
            const size_t o1 = (size_t)(r0 + 8) * N + col;
            if (onehot) {
                const int t0 = xTok[r0], t1 = xTok[r0 + 8];
                v0 += (col == t0) ? 1.f : 0.f;
                v1 += (col + 1 == t0) ? 1.f : 0.f;
                v2 += (col == t1) ? 1.f : 0.f;
                v3 += (col + 1 == t1) ? 1.f : 0.f;
            }
            if (accum) {
                float2 q0 = *(float2*)(Cf + o0);
                float2 q1 = *(float2*)(Cf + o1);
                v0 += q0.x; v1 += q0.y; v2 += q1.x; v3 += q1.y;
            }
            *(float2*)(Cf + o0) = make_float2(v0, v1);
            *(float2*)(Cf + o1) = make_float2(v2, v3);
        }
    }
}

// ============================================================================
// Conv GEMM: 3 taps share one 130-row A tile (1-term A). Epilogue: bias +
// fp16 z2 write + gate partials (dot computed on fp32 accumulators).
// ============================================================================
#define CONV_A 17408
#define CONV_STAGE (CONV_A + 3 * 16384)  // 66560
#define CONVSMEM (2 * CONV_STAGE)        // 133120

__global__ __launch_bounds__(512, 1)
void mma_conv_k(const __half* __restrict__ Ah, const __half* __restrict__ Wh,
                const float* __restrict__ bias, __half* __restrict__ Ch,
                const float* __restrict__ wgv, float* __restrict__ gateOut) {
    extern __shared__ char smem[];
    const uint32_t smb = smem_u32(smem);
    const int tid = threadIdx.x, lane = tid & 31, wid = tid >> 5;
    const int mBase = blockIdx.y << 7, nBase = blockIdx.x << 7;
    const int wm = wid & 3, wn = wid >> 2;

    float acc[2][4][4];
#pragma unroll
    for (int t = 0; t < 2; t++)
#pragma unroll
        for (int j = 0; j < 4; j++)
#pragma unroll
            for (int q = 0; q < 4; q++) acc[t][j][q] = 0.f;

    const int rowIdx = tid >> 3, col16 = tid & 7;
    const bool loVal = (mBase & (Lsz - 1)) != 0;
    const bool hiVal = ((mBase + 128) & (Lsz - 1)) != 0;

    auto issue = [&](int c8) {
        const uint32_t sb = smb + (uint32_t)(c8 & 1) * CONV_STAGE;
        const int kOff = c8 * 64 + col16 * 8;
#pragma unroll
        for (int c = 0; c < 2; c++) {
            const int sr = rowIdx + c * 64 + 1;
            const uint32_t dsw = swz((uint32_t)(sr * 128 + col16 * 16));
            const size_t aoff = (size_t)(mBase + sr - 1) * Dsz + kOff;
            cp16(sb + dsw, Ah + aoff, true);
        }
        if (tid < 8) {
            const uint32_t dsw = swz((uint32_t)(tid * 16));
            const int ko = c8 * 64 + tid * 8;
            const size_t aoff = (size_t)(loVal ? mBase - 1 : mBase) * Dsz + ko;
            cp16(sb + dsw, Ah + aoff, loVal);
        } else if (tid < 16) {
            const int cc = tid - 8;
            const uint32_t dsw = swz((uint32_t)(129 * 128 + cc * 16));
            const int ko = c8 * 64 + cc * 8;
            const size_t aoff = (size_t)(hiVal ? mBase + 128 : mBase) * Dsz + ko;
            cp16(sb + dsw, Ah + aoff, hiVal);
        }
#pragma unroll
        for (int p = 0; p < 3; p++) {
#pragma unroll
            for (int c = 0; c < 2; c++) {
                const int row = rowIdx + c * 64;
                const uint32_t dsw = swz((uint32_t)(row * 128 + col16 * 16));
                const size_t woff = (size_t)p * DD + (size_t)(nBase + row) * Dsz + kOff;
                cp16(sb + CONV_A + (uint32_t)p * 16384 + dsw, Wh + woff, true);
            }
        }
        CP_COMMIT();
    };

    issue(0);
    for (int c8 = 0; c8 < 8; c8++) {
        asm volatile("cp.async.wait_group 0;" ::: "memory");
        __syncthreads();
        if (c8 + 1 < 8) issue(c8 + 1);
        const uint32_t sb = smb + (uint32_t)(c8 & 1) * CONV_STAGE;
#pragma unroll
        for (int kk = 0; kk < 4; kk++) {
#pragma unroll
            for (int p = 0; p < 3; p++) {
                uint32_t ah[2][4];
#pragma unroll
                for (int t = 0; t < 2; t++) {
                    const int row = wm * 32 + t * 16 + (lane & 15) + p;
                    const uint32_t off =
                        swz((uint32_t)(row * 128 + kk * 32 + (lane >> 4) * 16));
                    LDSM_X4(ah[t], sb + off);
                }
#pragma unroll
                for (int jp = 0; jp < 2; jp++) {
                    const int nrow = wn * 32 + jp * 16 + (lane & 7) + ((lane >> 4) << 3);
                    const uint32_t off =
                        swz((uint32_t)(nrow * 128 + kk * 32 + ((lane >> 3) & 1) * 16));
                    uint32_t bh[4];
                    LDSM_X4(bh, sb + CONV_A + (uint32_t)p * 16384 + off);
#pragma unroll
                    for (int t = 0; t < 2; t++) {
#pragma unroll
                        for (int jj = 0; jj < 2; jj++) {
                            MMA_F16(acc[t][jp * 2 + jj], ah[t], bh[jj * 2], bh[jj * 2 + 1]);
                        }
                    }
                }
            }
        }
    }

#pragma unroll
    for (int t = 0; t < 2; t++) {
        const int r0 = mBase + wm * 32 + t * 16 + (lane >> 2);
        float p0 = 0.f, p1 = 0.f;
#pragma unroll
        for (int j = 0; j < 4; j++) {
            const int col = nBase + wn * 32 + j * 8 + (lane & 3) * 2;
            const float b0 = bias[col], b1 = bias[col + 1];
            float v0 = acc[t][j][0] + b0, v1 = acc[t][j][1] + b1;
            float v2 = acc[t][j][2] + b0, v3 = acc[t][j][3] + b1;
            const size_t o0 = (size_t)r0 * Dsz + col;
            const size_t o1 = (size_t)(r0 + 8) * Dsz + col;
            *(__half2*)(Ch + o0) = __floats2half2_rn(v0, v1);
            *(__half2*)(Ch + o1) = __floats2half2_rn(v2, v3);
            const float w0 = __ldg(wgv + col), w1 = __ldg(wgv + col + 1);
            p0 = fmaf(v0, w0, fmaf(v1, w1, p0));
            p1 = fmaf(v2, w0, fmaf(v3, w1, p1));
        }
        p0 += __shfl_xor_sync(0xffffffffu, p0, 1);
        p0 += __shfl_xor_sync(0xffffffffu, p0, 2);
        p1 += __shfl_xor_sync(0xffffffffu, p1, 1);
        p1 += __shfl_xor_sync(0xffffffffu, p1, 2);
        if ((lane & 3) == 0) {
            float* gp = gateOut + ((size_t)((nBase >> 7) * 4 + wn)) * Tsz;
            gp[r0] = p0;
            gp[r0 + 8] = p1;
        }
    }
}

// ============================================================================
// Fused fc(+folded wout) + gated-MLP GEMM, 1-term A.
// ============================================================================
#define FC_STAGE 49152
#define FCSMEM (2 * FC_STAGE)

__global__ __launch_bounds__(512, 1)
void mma_fc_k(const __half* __restrict__ Ah, const __half* __restrict__ Wh,
              const float* __restrict__ bias, __half* __restrict__ Oh) {
    extern __shared__ char smem[];
    const uint32_t smb = smem_u32(smem);
    const int tid = threadIdx.x, lane = tid & 31, wid = tid >> 5;
    const int mBase = blockIdx.y << 7, nBase = blockIdx.x << 7;
    const int wm = wid & 3, wn = wid >> 2;

    float accg[2][4][4], accv[2][4][4];
#pragma unroll
    for (int t = 0; t < 2; t++)
#pragma unroll
        for (int j = 0; j < 4; j++)
#pragma unroll
            for (int q = 0; q < 4; q++) { accg[t][j][q] = 0.f; accv[t][j][q] = 0.f; }

    const int rowIdx = tid >> 3, col16 = tid & 7;

    auto issue = [&](int idx) {
        const uint32_t sb = smb + (uint32_t)(idx & 1) * FC_STAGE;
        const int kOff = idx * 64 + col16 * 8;
#pragma unroll
        for (int c = 0; c < 2; c++) {
            const int row = rowIdx + c * 64;
            const uint32_t dsw = swz((uint32_t)(row * 128 + col16 * 16));
            const size_t aoff = (size_t)(mBase + row) * Dsz + kOff;
            cp16(sb + dsw, Ah + aoff, true);
            const size_t wgoff = (size_t)(nBase + row) * Dsz + kOff;
            cp16(sb + 16384 + dsw, Wh + wgoff, true);
            const size_t wvoff = (size_t)(512 + nBase + row) * Dsz + kOff;
            cp16(sb + 32768 + dsw, Wh + wvoff, true);
        }
        CP_COMMIT();
    };

    issue(0);
    for (int idx = 0; idx < 8; idx++) {
        asm volatile("cp.async.wait_group 0;" ::: "memory");
        __syncthreads();
        if (idx + 1 < 8) issue(idx + 1);
        const uint32_t sb = smb + (uint32_t)(idx & 1) * FC_STAGE;
#pragma unroll
        for (int kk = 0; kk < 4; kk++) {
            uint32_t ah[2][4];
#pragma unroll
            for (int t = 0; t < 2; t++) {
                const int row = wm * 32 + t * 16 + (lane & 15);
                const uint32_t off =
                    swz((uint32_t)(row * 128 + kk * 32 + (lane >> 4) * 16));
                LDSM_X4(ah[t], sb + off);
            }
#pragma unroll
            for (int jp = 0; jp < 2; jp++) {
                const int nrow = wn * 32 + jp * 16 + (lane & 7) + ((lane >> 4) << 3);
                const uint32_t off =
                    swz((uint32_t)(nrow * 128 + kk * 32 + ((lane >> 3) & 1) * 16));
                {
                    uint32_t bh[4];
                    LDSM_X4(bh, sb + 16384 + off);
#pragma unroll
                    for (int t = 0; t < 2; t++)
#pragma unroll
                        for (int jj = 0; jj < 2; jj++)
                            MMA_F16(accg[t][jp * 2 + jj], ah[t], bh[jj * 2], bh[jj * 2 + 1]);
                }
                {
                    uint32_t bh[4];
                    LDSM_X4(bh, sb + 32768 + off);
#pragma unroll
                    for (int t = 0; t < 2; t++)
#pragma unroll
                        for (int jj = 0; jj < 2; jj++)
                            MMA_F16(accv[t][jp * 2 + jj], ah[t], bh[jj * 2], bh[jj * 2 + 1]);
                }
            }
        }
    }

#pragma unroll
    for (int t = 0; t < 2; t++) {
#pragma unroll
        for (int j = 0; j < 4; j++) {
            const int r0 = mBase + wm * 32 + t * 16 + (lane >> 2);
            const int col = nBase + wn * 32 + j * 8 + (lane & 3) * 2;
            const float bg0 = bias[col], bg1 = bias[col + 1];
            const float bv0 = bias[512 + col], bv1 = bias[512 + col + 1];
            float s0 = 1.f / (1.f + expf(-(accg[t][j][0] + bg0)));
            float s1 = 1.f / (1.f + expf(-(accg[t][j][1] + bg1)));
            float s2 = 1.f / (1.f + expf(-(accg[t][j][2] + bg0)));
            float s3 = 1.f / (1.f + expf(-(accg[t][j][3] + bg1)));
            float v0 = s0 * (accv[t][j][0] + bv0);
            float v1 = s1 * (accv[t][j][1] + bv1);
            float v2 = s2 * (accv[t][j][2] + bv0);
            float v3 = s3 * (accv[t][j][3] + bv1);
            const size_t o0 = (size_t)r0 * Dsz + col;
            const size_t o1 = (size_t)(r0 + 8) * Dsz + col;
            *(__half2*)(Oh + o0) = __floats2half2_rn(v0, v1);
            *(__half2*)(Oh + o1) = __floats2half2_rn(v2, v3);
        }
    }
}

// ============================================================================
// Layer-0 conv as gather (exact fp32) + fused gate; fp16 z2 output.
// ============================================================================
__global__ void conv0_k(const int* __restrict__ x, const float* __restrict__ w0t,
                        const float* __restrict__ u0, const float* __restrict__ cb,
                        const float* __restrict__ lng, const float* __restrict__ wgv,
                        const float* __restrict__ bg,
                        __half* __restrict__ z2h, float* __restrict__ gt) {
    const int t = blockIdx.x, tid = threadIdx.x;
    const int l = t & (Lsz - 1);
    const float mean = 1.0f / 512.0f;
    const float rstd = rsqrtf(mean * (511.0f / 512.0f) + 1e-5f);

    const int tokm = (l > 0) ? x[t - 1] : -1;
    const int tok0 = x[t];
    const int tokp = (l < Lsz - 1) ? x[t + 1] : -1;

    float4 acc = ((const float4*)cb)[tid];
    {
        const float s = rstd * lng[tok0];
        float4 w = ((const float4*)(w0t + (size_t)DD + (size_t)tok0 * Dsz))[tid];
        float4 u = ((const float4*)(u0 + Dsz))[tid];
        acc.x += s * w.x + u.x; acc.y += s * w.y + u.y;
        acc.z += s * w.z + u.z; acc.w += s * w.w + u.w;
    }
    if (tokm >= 0) {
        const float s = rstd * lng[tokm];
        float4 w = ((const float4*)(w0t + (size_t)tokm * Dsz))[tid];
        float4 u = ((const float4*)u0)[tid];
        acc.x += s * w.x + u.x; acc.y += s * w.y + u.y;
        acc.z += s * w.z + u.z; acc.w += s * w.w + u.w;
    }
    if (tokp >= 0) {
        const float s = rstd * lng[tokp];
        float4 w = ((const float4*)(w0t + (size_t)2 * DD + (size_t)tokp * Dsz))[tid];
        float4 u = ((const float4*)(u0 + 2 * Dsz))[tid];
        acc.x += s * w.x + u.x; acc.y += s * w.y + u.y;
        acc.z += s * w.z + u.z; acc.w += s * w.w + u.w;
    }
    __half2* po = (__half2*)(z2h + (size_t)t * Dsz);
    po[2 * tid] = __floats2half2_rn(acc.x, acc.y);
    po[2 * tid + 1] = __floats2half2_rn(acc.z, acc.w);

    float4 wv = ((const float4*)wgv)[tid];
    float p = acc.x * wv.x + acc.y * wv.y + acc.z * wv.z + acc.w * wv.w;
#pragma unroll
    for (int o = 16; o; o >>= 1) p += __shfl_xor_sync(0xffffffffu, p, o);
    __shared__ float smr[4];
    if ((tid & 31) == 0) smr[tid >> 5] = p;
    __syncthreads();
    if (tid == 0) {
        float s = smr[0] + smr[1] + smr[2] + smr[3];
        gt[t] = 1.0f / (1.0f + expf(-(s + bg[0])));
    }
}

// ---------------- merged prep: 1-term converts + w0t + flag reset -------------
__global__ void prep_k(const float* __restrict__ conv_w, const float* __restrict__ mo_w,
                       const float* __restrict__ head_w, const float* __restrict__ wout,
                       const float* __restrict__ fc_w,
                       __half* __restrict__ wh, float* __restrict__ w0t,
                       __half* __restrict__ fch) {
    const int idx = blockIdx.x * blockDim.x + threadIdx.x;   // 0 .. 32*DD-1
    if (idx < NFLAGS) g_sflag[idx] = 0;
    if (idx < 12 * DD) {
        int layer = idx / (3 * DD);
        int r = idx - layer * (3 * DD);
        int h = r / DD;
        int rr = r - h * DD;
        int o = rr >> 9, i = rr & 511;
        wh[idx] = __float2half_rn(conv_w[(size_t)layer * 3 * DD + ((size_t)o * Dsz + i) * 3 + h]);
    } else if (idx < 16 * DD) {
        int j = idx - 12 * DD;
        wh[W_MO(0) + j] = __float2half_rn(mo_w[j]);
    } else if (idx < 17 * DD) {
        int j = idx - 16 * DD;
        wh[W_HEAD + j] = __float2half_rn(head_w[j]);
    } else if (idx < 21 * DD) {
        int j = idx - 17 * DD;
        int layer = j / DD;
        int r = j - layer * DD;
        int n = r >> 9, k = r & 511;
        wh[W_WOUT(0) + j] = __float2half_rn(wout[(size_t)layer * DD + (size_t)k * Dsz + n]);
    } else if (idx < 24 * DD) {
        int j = idx - 21 * DD;
        int h = j / DD;
        int r = j - h * DD;
        int i = r >> 9, o = r & 511;
        w0t[j] = conv_w[((size_t)o * Dsz + i) * 3 + h];
    } else {
        int j = idx - 24 * DD;
        fch[j] = __float2half_rn(fc_w[j]);
    }
}

// ---------------- layernorm with fp16 output ----------------------------------
__global__ void ln_h_k(const float* __restrict__ in, __half* __restrict__ oh,
                       const float* __restrict__ gamma, const float* __restrict__ beta) {
    int t = blockIdx.x, tid = threadIdx.x;
    const float4* rp = (const float4*)(in + (size_t)t * Dsz);
    float4 v = rp[tid];
    float s = v.x + v.y + v.z + v.w;
#pragma unroll
    for (int o = 16; o; o >>= 1) s += __shfl_xor_sync(0xffffffffu, s, o);
    __shared__ float smr[4];
    if ((tid & 31) == 0) smr[tid >> 5] = s;
    __syncthreads();
    float mean = (smr[0] + smr[1] + smr[2] + smr[3]) * (1.0f / Dsz);
    float dx = v.x - mean, dy = v.y - mean, dz = v.z - mean, dw = v.w - mean;
    float q = dx * dx + dy * dy + dz * dz + dw * dw;
#pragma unroll
    for (int o = 16; o; o >>= 1) q += __shfl_xor_sync(0xffffffffu, q, o);
    __syncthreads();
    if ((tid & 31) == 0) smr[tid >> 5] = q;
    __syncthreads();
    float var = (smr[0] + smr[1] + smr[2] + smr[3]) * (1.0f / Dsz);
    float rstd = rsqrtf(var + 1e-5f);
    float4 g4 = ((const float4*)gamma)[tid];
    float4 b4 = ((const float4*)beta)[tid];
    float f0 = dx * rstd * g4.x + b4.x, f1 = dy * rstd * g4.y + b4.y;
    float f2 = dz * rstd * g4.z + b4.z, f3 = dw * rstd * g4.w + b4.w;
    __half2* ph = (__half2*)(oh + (size_t)t * Dsz);
    ph[2 * tid] = __floats2half2_rn(f0, f1);
    ph[2 * tid + 1] = __floats2half2_rn(f2, f3);
}

// ---------------- u0 = W_h^T (lnb - rstd*mean*lng) -----------------------------
__global__ void u0_k(const float* __restrict__ cw, const float* __restrict__ lng,
                     const float* __restrict__ lnb, float* __restrict__ u0) {
    int w = (blockIdx.x * blockDim.x + threadIdx.x) >> 5;
    int lane = threadIdx.x & 31;
    int h = w >> 9, o = w & 511;
    const float mean = 1.0f / 512.0f;
    const float rstd = rsqrtf(mean * (511.0f / 512.0f) + 1e-5f);
    float s = 0.f;
#pragma unroll
    for (int c = 0; c < 16; c++) {
        int i = lane + 32 * c;
        float v = lnb[i] - rstd * mean * lng[i];
        s = fmaf(cw[((size_t)o * Dsz + i) * 3 + h], v, s);
    }
#pragma unroll
    for (int ofs = 16; ofs; ofs >>= 1) s += __shfl_xor_sync(0xffffffffu, s, ofs);
    if (lane == 0) u0[w] = s;
}

// ---------------- 1-term convert (Wcomb) ---------------------------------------
__global__ void wsplit1_k(const float* __restrict__ w, __half* __restrict__ wh, int n) {
    int idx = blockIdx.x * blockDim.x + threadIdx.x;
    if (idx >= n) return;
    wh[idx] = __float2half_rn(w[idx]);
}

// ---------------- bcomb = Wf·bo + fb --------------------------------------------
__global__ void bcomb_k(const float* __restrict__ fw, const float* __restrict__ bo,
                        const float* __restrict__ fb, float* __restrict__ out) {
    int w = (blockIdx.x * blockDim.x + threadIdx.x) >> 5;
    int lane = threadIdx.x & 31;
    int layer = w >> 10, e = w & 1023;
    const float* fr = fw + ((size_t)layer * 1024 + e) * Dsz;
    const float* br = bo + (size_t)layer * Dsz;
    float s = 0.f;
#pragma unroll
    for (int i = 0; i < 16; i++) s = fmaf(fr[lane + 32 * i], br[lane + 32 * i], s);
#pragma unroll
    for (int o = 16; o; o >>= 1) s += __shfl_xor_sync(0xffffffffu, s, o);
    if (lane == 0) out[w] = s + fb[(size_t)layer * 1024 + e];
}

// ============================================================================
// Unified chained scan over fp16 z2; c=0 emits in pass 1. fp16 output.
// Flags zeroed per call in prep_k -> deterministic across graph replays.
// ============================================================================
__global__ void scan_u_k(const __half* __restrict__ z2h,
                         const float* __restrict__ gatep,
                         const float* __restrict__ gt0,
                         const float* __restrict__ bgp,
                         float* __restrict__ hfin, int* __restrict__ flags,
                         __half* __restrict__ hh) {
    const int bx = blockIdx.x;
    const int c = bx >> 6, b = (bx >> 2) & 15, dch = bx & 3;
    const int tid = threadIdx.x;
    const int d = (dch << 7) + tid;
    const int l0 = c * SCH;
    __shared__ float gsm[SCH];

    if (gt0) {
        for (int j = tid; j < SCH; j += 128)
            gsm[j] = gt0[b * Lsz + l0 + j];
    } else {
        const float bgv = bgp[0];
        for (int j = tid; j < SCH; j += 128) {
            const int t = b * Lsz + l0 + j;
            float s = 0.f;
#pragma unroll
            for (int p = 0; p < 16; p++) s += gatep[(size_t)p * Tsz + t];
            gsm[j] = 1.0f / (1.0f + expf(-(s + bgv)));
        }
    }
    __syncthreads();

    const size_t base = (size_t)b * Lsz * Dsz + (size_t)l0 * Dsz + d;
    const bool first = (c == 0);
    float hv = 0.f, ap = 1.f;
    for (int l = 0; l < SCH; l += 8) {
        float xs[8], gs[8];
#pragma unroll
        for (int j = 0; j < 8; j++) {
            xs[j] = __half2float(z2h[base + (size_t)(l + j) * Dsz]);
            gs[j] = gsm[l + j];
        }
#pragma unroll
        for (int j = 0; j < 8; j++) {
            hv = fmaf(gs[j], xs[j] - hv, hv);
            ap *= (1.f - gs[j]);
            if (first) hh[base + (size_t)(l + j) * Dsz] = __float2half_rn(hv);
        }
    }
    float carry = 0.f;
    const size_t fo = (size_t)c * (Bsz * Dsz) + (size_t)b * Dsz + d;
    if (!first) {
        if (tid == 0) {
            volatile int* f = flags + (bx - 64);
            while (*f == 0) {}
        }
        __syncthreads();
        __threadfence();
        carry = __ldcg(hfin + fo - (size_t)(Bsz * Dsz));
    }
    hfin[fo] = hv + ap * carry;
    __syncthreads();
    __threadfence();
    if (tid == 0) *((volatile int*)(flags + bx)) = 1;
    if (first) return;

    hv = carry;
    for (int l = 0; l < SCH; l += 8) {
        float xs[8], gs[8];
#pragma unroll
        for (int j = 0; j < 8; j++) {
            xs[j] = __half2float(z2h[base + (size_t)(l + j) * Dsz]);
            gs[j] = gsm[l + j];
        }
#pragma unroll
        for (int j = 0; j < 8; j++) {
            hv = fmaf(gs[j], xs[j] - hv, hv);
            hh[base + (size_t)(l + j) * Dsz] = __float2half_rn(hv);
        }
    }
}

// ---------------- launch --------------------------------------------------------
extern "C" void kernel_launch(void* const* d_in, const int* in_sizes, int n_in,
                              void* d_out, int out_size) {
    const int* x = (const int*)d_in[0];
    const float* ln_g = (const float*)d_in[1];
    const float* ln_b = (const float*)d_in[2];
    const float* conv_w = (const float*)d_in[3];
    const float* conv_b = (const float*)d_in[4];
    const float* wg = (const float*)d_in[5];
    const float* bg = (const float*)d_in[6];
    const float* wout = (const float*)d_in[7];
    const float* bout = (const float*)d_in[8];
    const float* fc_w = (const float*)d_in[9];
    const float* fc_b = (const float*)d_in[10];
    const float* mo_w = (const float*)d_in[11];
    const float* mo_b = (const float*)d_in[12];
    const float* lnf_g = (const float*)d_in[13];
    const float* lnf_b = (const float*)d_in[14];
    const float* head_w = (const float*)d_in[15];
    const float* head_b = (const float*)d_in[16];

    float *y, *gt, *gp, *bcomb, *hfin, *w0t, *u0;
    int* sflag;
    __half *z2h, *zh, *hh, *gh, *wh;
    cudaGetSymbolAddress((void**)&y, g_y);
    cudaGetSymbolAddress((void**)&gt, g_gate);
    cudaGetSymbolAddress((void**)&gp, g_gatep);
    cudaGetSymbolAddress((void**)&bcomb, g_bcomb);
    cudaGetSymbolAddress((void**)&hfin, g_hfin);
    cudaGetSymbolAddress((void**)&sflag, g_sflag);
    cudaGetSymbolAddress((void**)&w0t, g_w0t);
    cudaGetSymbolAddress((void**)&u0, g_u0);
    cudaGetSymbolAddress((void**)&z2h, g_z2h);
    cudaGetSymbolAddress((void**)&zh, g_zh);
    cudaGetSymbolAddress((void**)&hh, g_hh);
    cudaGetSymbolAddress((void**)&gh, g_gh);
    cudaGetSymbolAddress((void**)&wh, g_wh);

    cudaFuncSetAttribute(mma_gemm_k, cudaFuncAttributeMaxDynamicSharedMemorySize, GSMEM);
    cudaFuncSetAttribute(mma_conv_k, cudaFuncAttributeMaxDynamicSharedMemorySize, CONVSMEM);
    cudaFuncSetAttribute(mma_fc_k, cudaFuncAttributeMaxDynamicSharedMemorySize, FCSMEM);

    const dim3 g512(4, Tsz / 128);

    // ---- prep: merged converts (+flag reset), bias fold, wout folding ----
    prep_k<<<(32 * DD) / 256, 256>>>(conv_w, mo_w, head_w, wout, fc_w, wh, w0t, gh);
    bcomb_k<<<(NLsz * 1024 * 32) / 256, 256>>>(fc_w, bout, fc_b, bcomb);
    u0_k<<<(3 * Dsz * 32) / 256, 256>>>(conv_w, ln_g, ln_b, u0);
    // Wcomb = Wf @ Wo; fp32 scratch = g_y (dead until layer-0 mo overwrites it)
    mma_gemm_k<<<dim3(4, 32), 512, GSMEM>>>(gh, wh + W_WOUT(0),
                                            nullptr, y, nullptr, Dsz, 0, (int)DD);
    wsplit1_k<<<(8 * DD) / 256, 256>>>(y, wh + W_FC(0), 8 * DD);

    for (int i = 0; i < NLsz; i++) {
        if (i == 0) {
            conv0_k<<<Tsz, 128>>>(x, w0t, u0, conv_b, ln_g, wg, bg, z2h, gt);
        } else {
            ln_h_k<<<Tsz, 128>>>(y, zh, ln_g + (size_t)i * Dsz, ln_b + (size_t)i * Dsz);
            mma_conv_k<<<g512, 512, CONVSMEM>>>(zh, wh + W_CONV(i),
                                                conv_b + (size_t)i * Dsz, z2h,
                                                wg + (size_t)i * Dsz, gp);
        }
        scan_u_k<<<NCH * 64, 128>>>(z2h, gp, (i == 0) ? gt : nullptr, bg + i,
                                    hfin, sflag + (size_t)i * (NCH * Bsz * 4), hh);
        mma_fc_k<<<g512, 512, FCSMEM>>>(hh, wh + W_FC(i),
                                        bcomb + (size_t)i * 1024, gh);
        mma_gemm_k<<<g512, 512, GSMEM>>>(gh, wh + W_MO(i),
                                         mo_b + (size_t)i * Dsz, y,
                                         (i == 0) ? x : nullptr, Dsz,
                                         (i == 0) ? (1 | 16) : (1 | 2), 0);
    }

    ln_h_k<<<Tsz, 128>>>(y, zh, lnf_g, lnf_b);
    mma_gemm_k<<<g512, 512, GSMEM>>>(zh, wh + W_HEAD, head_b,
                                     (float*)d_out, nullptr, Dsz, 1, 0);
}

// round 16
// speedup vs baseline: 2.2561x; 1.0019x over previous
#include <cuda_runtime.h>
#include <cuda_fp16.h>
#include <cstdint>
#include <cstddef>

#define Bsz 16
#define Lsz 2048
#define Dsz 512
#define NLsz 4
#define Tsz (Bsz * Lsz)  // 32768
#define DD (Dsz * Dsz)

// weight arena offsets (units of DD)
#define W_CONV(i) ((size_t)(i) * 3 * DD)
#define W_WOUT(i) ((size_t)(12 + (i)) * DD)      // wout^T (prep only)
#define W_FC(i)   ((size_t)(16 + 2 * (i)) * DD)  // after prep: Wcomb = Wf@Wo
#define W_MO(i)   ((size_t)(24 + (i)) * DD)
#define W_HEAD    ((size_t)28 * DD)

// scan chunking
#define SCH 256
#define NCH (Lsz / SCH)  // 8
#define NFLAGS (NLsz * NCH * Bsz * 4)  // 2048

// ---------------- scratch (device globals; no allocation allowed) ----------
__device__ float g_y[Tsz * Dsz];             // residual; also Wcomb prep scratch
__device__ float g_gate[Tsz];
__device__ float g_gatep[16 * Tsz];
__device__ float g_bcomb[NLsz * 2 * Dsz];
__device__ float g_hfin[NCH * Bsz * Dsz];
__device__ int   g_sflag[NFLAGS];
__device__ float g_w0t[3 * DD];
__device__ float g_u0[3 * Dsz];
__device__ __half g_z2h[Tsz * Dsz];          // conv out (fp16)
__device__ __half g_zh[Tsz * Dsz];           // LN out
__device__ __half g_hh[Tsz * Dsz];           // scan out
__device__ __half g_gh[Tsz * Dsz];           // gated out + prep scratch
__device__ __half g_wh[29 * DD];             // weights, 1-term fp16

// ---------------- helpers ---------------------------------------------------
__device__ __forceinline__ uint32_t smem_u32(const void* p) {
    return (uint32_t)__cvta_generic_to_shared(p);
}
__device__ __forceinline__ uint32_t swz(uint32_t x) { return x ^ ((x >> 3) & 0x70); }

__device__ __forceinline__ void cp16(uint32_t dst, const void* src, bool v) {
    int sz = v ? 16 : 0;
    asm volatile("cp.async.cg.shared.global [%0], [%1], 16, %2;"
                 :: "r"(dst), "l"(src), "r"(sz) : "memory");
}
#define CP_COMMIT() asm volatile("cp.async.commit_group;" ::: "memory")

#define LDSM_X4(r, a)                                                          \
    asm volatile("ldmatrix.sync.aligned.m8n8.x4.shared.b16 {%0,%1,%2,%3}, [%4];" \
                 : "=r"((r)[0]), "=r"((r)[1]), "=r"((r)[2]), "=r"((r)[3]) : "r"(a))

#define MMA_F16(d, a, b0, b1)                                                  \
    asm volatile(                                                              \
        "mma.sync.aligned.m16n8k16.row.col.f32.f16.f16.f32 "                   \
        "{%0,%1,%2,%3},{%4,%5,%6,%7},{%8,%9},{%0,%1,%2,%3};"                   \
        : "+f"((d)[0]), "+f"((d)[1]), "+f"((d)[2]), "+f"((d)[3])               \
        : "r"((a)[0]), "r"((a)[1]), "r"((a)[2]), "r"((a)[3]), "r"(b0), "r"(b1))

// ============================================================================
// Generic GEMM: A 1-term fp16, W 1-term. 512 thr, 128x128, 3-stage 32KB,
// double-buffered register fragments (LDSM for kk+1 issued before kk's MMAs).
// flags: 1=addBias, 2=accum fp32, 16=one-hot residual add.
// ============================================================================
#define STAGE_B 32768
#define GSMEM (3 * STAGE_B)

__global__ __launch_bounds__(512, 1)
void mma_gemm_k(const __half* __restrict__ Ah, const __half* __restrict__ Wh,
                const float* __restrict__ bias, float* __restrict__ Cf,
                const int* __restrict__ xTok,
                int N, int flags, int wLayerStride) {
    extern __shared__ char smem[];
    const uint32_t smb = smem_u32(smem);
    const int tid = threadIdx.x, lane = tid & 31, wid = tid >> 5;
    const int mBase = blockIdx.y << 7, nBase = blockIdx.x << 7;
    const int wm = wid & 3, wn = wid >> 2;

    float acc[2][4][4];
#pragma unroll
    for (int t = 0; t < 2; t++)
#pragma unroll
        for (int j = 0; j < 4; j++)
#pragma unroll
            for (int q = 0; q < 4; q++) acc[t][j][q] = 0.f;

    const int rowIdx = tid >> 3, col16 = tid & 7;

    auto issue = [&](int idx) {
        const size_t wOff = (size_t)(mBase >> 10) * wLayerStride;
        const uint32_t sb = smb + (uint32_t)(idx % 3) * STAGE_B;
        const int kOff = idx * 64 + col16 * 8;
#pragma unroll
        for (int c = 0; c < 2; c++) {
            const int row = rowIdx + c * 64;
            const uint32_t dsw = swz((uint32_t)(row * 128 + col16 * 16));
            const size_t aoff = (size_t)(mBase + row) * Dsz + kOff;
            cp16(sb + dsw, Ah + aoff, true);
            const size_t woff = wOff + (size_t)(nBase + row) * Dsz + kOff;
            cp16(sb + 16384 + dsw, Wh + woff, true);
        }
        CP_COMMIT();
    };

    auto ldFrags = [&](uint32_t sb, int kk, uint32_t aF[2][4], uint32_t bF[2][4]) {
#pragma unroll
        for (int t = 0; t < 2; t++) {
            const int row = wm * 32 + t * 16 + (lane & 15);
            const uint32_t off =
                swz((uint32_t)(row * 128 + kk * 32 + (lane >> 4) * 16));
            LDSM_X4(aF[t], sb + off);
        }
#pragma unroll
        for (int jp = 0; jp < 2; jp++) {
            const int nrow = wn * 32 + jp * 16 + (lane & 7) + ((lane >> 4) << 3);
            const uint32_t off =
                swz((uint32_t)(nrow * 128 + kk * 32 + ((lane >> 3) & 1) * 16));
            LDSM_X4(bF[jp], sb + 16384 + off);
        }
    };

    uint32_t aF[2][2][4], bF[2][2][4];

    issue(0);
    issue(1);
    for (int idx = 0; idx < 8; idx++) {
        if (idx + 1 < 8) {
            asm volatile("cp.async.wait_group 1;" ::: "memory");
        } else {
            asm volatile("cp.async.wait_group 0;" ::: "memory");
        }
        __syncthreads();
        if (idx + 2 < 8) issue(idx + 2);
        const uint32_t sb = smb + (uint32_t)(idx % 3) * STAGE_B;
        ldFrags(sb, 0, aF[0], bF[0]);
#pragma unroll
        for (int kk = 0; kk < 4; kk++) {
            const int cur = kk & 1;
            if (kk < 3) ldFrags(sb, kk + 1, aF[cur ^ 1], bF[cur ^ 1]);
#pragma unroll
            for (int jp = 0; jp < 2; jp++)
#pragma unroll
                for (int t = 0; t < 2; t++)
#pragma unroll
                    for (int jj = 0; jj < 2; jj++)
                        MMA_F16(acc[t][jp * 2 + jj], aF[cur][t],
                                bF[cur][jp][jj * 2], bF[cur][jp][jj * 2 + 1]);
        }
    }

    const bool addB = (flags & 1) != 0;
    const bool accum = (flags & 2) != 0;
    const bool onehot = (flags & 16) != 0;
#pragma unroll
    for (int t = 0; t < 2; t++) {
        const int r0 = mBase + wm * 32 + t * 16 + (lane >> 2);
#pragma unroll
        for (int j = 0; j < 4; j++) {
            const int col = nBase + wn * 32 + j * 8 + (lane & 3) * 2;
            float b0 = 0.f, b1 = 0.f;
            if (addB) { b0 = bias[col]; b1 = bias[col + 1]; }
            float v0 = acc[t][j][0] + b0, v1 = acc[t][j][1] + b1;
            float v2 = acc[t][j][2] + b0, v3 = acc[t][j][3] + b1;
            const size_t o0 = (size_t)r0 * N + col;
            const size_t o1 = (size_t)(r0 + 8) * N + col;
            if (onehot) {
                const int t0 = xTok[r0], t1 = xTok[r0 + 8];
                v0 += (col == t0) ? 1.f : 0.f;
                v1 += (col + 1 == t0) ? 1.f : 0.f;
                v2 += (col == t1) ? 1.f : 0.f;
                v3 += (col + 1 == t1) ? 1.f : 0.f;
            }
            if (accum) {
                float2 q0 = *(float2*)(Cf + o0);
                float2 q1 = *(float2*)(Cf + o1);
                v0 += q0.x; v1 += q0.y; v2 += q1.x; v3 += q1.y;
            }
            *(float2*)(Cf + o0) = make_float2(v0, v1);
            *(float2*)(Cf + o1) = make_float2(v2, v3);
        }
    }
}

// ============================================================================
// Conv GEMM: 3 taps share one 130-row A tile, double-buffered fragments over
// the flattened (kk,p) loop. Epilogue: bias + fp16 z2 + gate partials.
// ============================================================================
#define CONV_A 17408
#define CONV_STAGE (CONV_A + 3 * 16384)  // 66560
#define CONVSMEM (2 * CONV_STAGE)        // 133120

__global__ __launch_bounds__(512, 1)
void mma_conv_k(const __half* __restrict__ Ah, const __half* __restrict__ Wh,
                const float* __restrict__ bias, __half* __restrict__ Ch,
                const float* __restrict__ wgv, float* __restrict__ gateOut) {
    extern __shared__ char smem[];
    const uint32_t smb = smem_u32(smem);
    const int tid = threadIdx.x, lane = tid & 31, wid = tid >> 5;
    const int mBase = blockIdx.y << 7, nBase = blockIdx.x << 7;
    const int wm = wid & 3, wn = wid >> 2;

    float acc[2][4][4];
#pragma unroll
    for (int t = 0; t < 2; t++)
#pragma unroll
        for (int j = 0; j < 4; j++)
#pragma unroll
            for (int q = 0; q < 4; q++) acc[t][j][q] = 0.f;

    const int rowIdx = tid >> 3, col16 = tid & 7;
    const bool loVal = (mBase & (Lsz - 1)) != 0;
    const bool hiVal = ((mBase + 128) & (Lsz - 1)) != 0;

    auto issue = [&](int c8) {
        const uint32_t sb = smb + (uint32_t)(c8 & 1) * CONV_STAGE;
        const int kOff = c8 * 64 + col16 * 8;
#pragma unroll
        for (int c = 0; c < 2; c++) {
            const int sr = rowIdx + c * 64 + 1;
            const uint32_t dsw = swz((uint32_t)(sr * 128 + col16 * 16));
            const size_t aoff = (size_t)(mBase + sr - 1) * Dsz + kOff;
            cp16(sb + dsw, Ah + aoff, true);
        }
        if (tid < 8) {
            const uint32_t dsw = swz((uint32_t)(tid * 16));
            const int ko = c8 * 64 + tid * 8;
            const size_t aoff = (size_t)(loVal ? mBase - 1 : mBase) * Dsz + ko;
            cp16(sb + dsw, Ah + aoff, loVal);
        } else if (tid < 16) {
            const int cc = tid - 8;
            const uint32_t dsw = swz((uint32_t)(129 * 128 + cc * 16));
            const int ko = c8 * 64 + cc * 8;
            const size_t aoff = (size_t)(hiVal ? mBase + 128 : mBase) * Dsz + ko;
            cp16(sb + dsw, Ah + aoff, hiVal);
        }
#pragma unroll
        for (int p = 0; p < 3; p++) {
#pragma unroll
            for (int c = 0; c < 2; c++) {
                const int row = rowIdx + c * 64;
                const uint32_t dsw = swz((uint32_t)(row * 128 + col16 * 16));
                const size_t woff = (size_t)p * DD + (size_t)(nBase + row) * Dsz + kOff;
                cp16(sb + CONV_A + (uint32_t)p * 16384 + dsw, Wh + woff, true);
            }
        }
        CP_COMMIT();
    };

    auto ldFragsC = [&](uint32_t sb, int kk, int p, uint32_t aF[2][4], uint32_t bF[2][4]) {
#pragma unroll
        for (int t = 0; t < 2; t++) {
            const int row = wm * 32 + t * 16 + (lane & 15) + p;
            const uint32_t off =
                swz((uint32_t)(row * 128 + kk * 32 + (lane >> 4) * 16));
            LDSM_X4(aF[t], sb + off);
        }
#pragma unroll
        for (int jp = 0; jp < 2; jp++) {
            const int nrow = wn * 32 + jp * 16 + (lane & 7) + ((lane >> 4) << 3);
            const uint32_t off =
                swz((uint32_t)(nrow * 128 + kk * 32 + ((lane >> 3) & 1) * 16));
            LDSM_X4(bF[jp], sb + CONV_A + (uint32_t)p * 16384 + off);
        }
    };

    uint32_t aF[2][2][4], bF[2][2][4];

    issue(0);
    for (int c8 = 0; c8 < 8; c8++) {
        asm volatile("cp.async.wait_group 0;" ::: "memory");
        __syncthreads();
        if (c8 + 1 < 8) issue(c8 + 1);
        const uint32_t sb = smb + (uint32_t)(c8 & 1) * CONV_STAGE;
        ldFragsC(sb, 0, 0, aF[0], bF[0]);
#pragma unroll
        for (int it = 0; it < 12; it++) {
            const int cur = it & 1;
            if (it < 11) {
                const int nk = (it + 1) >> 2;   // note: it+1 = nk*3+np? use /3
                (void)nk;
            }
            if (it < 11) {
                const int n1 = it + 1;
                const int nkk = n1 / 3, np = n1 - nkk * 3;
                ldFragsC(sb, nkk, np, aF[cur ^ 1], bF[cur ^ 1]);
            }
#pragma unroll
            for (int jp = 0; jp < 2; jp++)
#pragma unroll
                for (int t = 0; t < 2; t++)
#pragma unroll
                    for (int jj = 0; jj < 2; jj++)
                        MMA_F16(acc[t][jp * 2 + jj], aF[cur][t],
                                bF[cur][jp][jj * 2], bF[cur][jp][jj * 2 + 1]);
        }
    }

#pragma unroll
    for (int t = 0; t < 2; t++) {
        const int r0 = mBase + wm * 32 + t * 16 + (lane >> 2);
        float p0 = 0.f, p1 = 0.f;
#pragma unroll
        for (int j = 0; j < 4; j++) {
            const int col = nBase + wn * 32 + j * 8 + (lane & 3) * 2;
            const float b0 = bias[col], b1 = bias[col + 1];
            float v0 = acc[t][j][0] + b0, v1 = acc[t][j][1] + b1;
            float v2 = acc[t][j][2] + b0, v3 = acc[t][j][3] + b1;
            const size_t o0 = (size_t)r0 * Dsz + col;
            const size_t o1 = (size_t)(r0 + 8) * Dsz + col;
            *(__half2*)(Ch + o0) = __floats2half2_rn(v0, v1);
            *(__half2*)(Ch + o1) = __floats2half2_rn(v2, v3);
            const float w0 = __ldg(wgv + col), w1 = __ldg(wgv + col + 1);
            p0 = fmaf(v0, w0, fmaf(v1, w1, p0));
            p1 = fmaf(v2, w0, fmaf(v3, w1, p1));
        }
        p0 += __shfl_xor_sync(0xffffffffu, p0, 1);
        p0 += __shfl_xor_sync(0xffffffffu, p0, 2);
        p1 += __shfl_xor_sync(0xffffffffu, p1, 1);
        p1 += __shfl_xor_sync(0xffffffffu, p1, 2);
        if ((lane & 3) == 0) {
            float* gp = gateOut + ((size_t)((nBase >> 7) * 4 + wn)) * Tsz;
            gp[r0] = p0;
            gp[r0 + 8] = p1;
        }
    }
}

// ============================================================================
// Fused fc(+folded wout) + gated-MLP GEMM, 1-term A. All 6 LDSMs batched
// at the top of each kk before the 32 MMAs.
// ============================================================================
#define FC_STAGE 49152
#define FCSMEM (2 * FC_STAGE)

__global__ __launch_bounds__(512, 1)
void mma_fc_k(const __half* __restrict__ Ah, const __half* __restrict__ Wh,
              const float* __restrict__ bias, __half* __restrict__ Oh) {
    extern __shared__ char smem[];
    const uint32_t smb = smem_u32(smem);
    const int tid = threadIdx.x, lane = tid & 31, wid = tid >> 5;
    const int mBase = blockIdx.y << 7, nBase = blockIdx.x << 7;
    const int wm = wid & 3, wn = wid >> 2;

    float accg[2][4][4], accv[2][4][4];
#pragma unroll
    for (int t = 0; t < 2; t++)
#pragma unroll
        for (int j = 0; j < 4; j++)
#pragma unroll
            for (int q = 0; q < 4; q++) { accg[t][j][q] = 0.f; accv[t][j][q] = 0.f; }

    const int rowIdx = tid >> 3, col16 = tid & 7;

    auto issue = [&](int idx) {
        const uint32_t sb = smb + (uint32_t)(idx & 1) * FC_STAGE;
        const int kOff = idx * 64 + col16 * 8;
#pragma unroll
        for (int c = 0; c < 2; c++) {
            const int row = rowIdx + c * 64;
            const uint32_t dsw = swz((uint32_t)(row * 128 + col16 * 16));
            const size_t aoff = (size_t)(mBase + row) * Dsz + kOff;
            cp16(sb + dsw, Ah + aoff, true);
            const size_t wgoff = (size_t)(nBase + row) * Dsz + kOff;
            cp16(sb + 16384 + dsw, Wh + wgoff, true);
            const size_t wvoff = (size_t)(512 + nBase + row) * Dsz + kOff;
            cp16(sb + 32768 + dsw, Wh + wvoff, true);
        }
        CP_COMMIT();
    };

    issue(0);
    for (int idx = 0; idx < 8; idx++) {
        asm volatile("cp.async.wait_group 0;" ::: "memory");
        __syncthreads();
        if (idx + 1 < 8) issue(idx + 1);
        const uint32_t sb = smb + (uint32_t)(idx & 1) * FC_STAGE;
#pragma unroll
        for (int kk = 0; kk < 4; kk++) {
            uint32_t ah[2][4], bg2[2][4], bv2[2][4];
#pragma unroll
            for (int t = 0; t < 2; t++) {
                const int row = wm * 32 + t * 16 + (lane & 15);
                const uint32_t off =
                    swz((uint32_t)(row * 128 + kk * 32 + (lane >> 4) * 16));
                LDSM_X4(ah[t], sb + off);
            }
#pragma unroll
            for (int jp = 0; jp < 2; jp++) {
                const int nrow = wn * 32 + jp * 16 + (lane & 7) + ((lane >> 4) << 3);
                const uint32_t off =
                    swz((uint32_t)(nrow * 128 + kk * 32 + ((lane >> 3) & 1) * 16));
                LDSM_X4(bg2[jp], sb + 16384 + off);
                LDSM_X4(bv2[jp], sb + 32768 + off);
            }
#pragma unroll
            for (int jp = 0; jp < 2; jp++)
#pragma unroll
                for (int t = 0; t < 2; t++)
#pragma unroll
                    for (int jj = 0; jj < 2; jj++) {
                        MMA_F16(accg[t][jp * 2 + jj], ah[t],
                                bg2[jp][jj * 2], bg2[jp][jj * 2 + 1]);
                        MMA_F16(accv[t][jp * 2 + jj], ah[t],
                                bv2[jp][jj * 2], bv2[jp][jj * 2 + 1]);
                    }
        }
    }

#pragma unroll
    for (int t = 0; t < 2; t++) {
#pragma unroll
        for (int j = 0; j < 4; j++) {
            const int r0 = mBase + wm * 32 + t * 16 + (lane >> 2);
            const int col = nBase + wn * 32 + j * 8 + (lane & 3) * 2;
            const float bg0 = bias[col], bg1 = bias[col + 1];
            const float bv0 = bias[512 + col], bv1 = bias[512 + col + 1];
            float s0 = 1.f / (1.f + expf(-(accg[t][j][0] + bg0)));
            float s1 = 1.f / (1.f + expf(-(accg[t][j][1] + bg1)));
            float s2 = 1.f / (1.f + expf(-(accg[t][j][2] + bg0)));
            float s3 = 1.f / (1.f + expf(-(accg[t][j][3] + bg1)));
            float v0 = s0 * (accv[t][j][0] + bv0);
            float v1 = s1 * (accv[t][j][1] + bv1);
            float v2 = s2 * (accv[t][j][2] + bv0);
            float v3 = s3 * (accv[t][j][3] + bv1);
            const size_t o0 = (size_t)r0 * Dsz + col;
            const size_t o1 = (size_t)(r0 + 8) * Dsz + col;
            *(__half2*)(Oh + o0) = __floats2half2_rn(v0, v1);
            *(__half2*)(Oh + o1) = __floats2half2_rn(v2, v3);
        }
    }
}

// ============================================================================
// Layer-0 conv as gather (exact fp32) + fused gate; fp16 z2 output.
// ============================================================================
__global__ void conv0_k(const int* __restrict__ x, const float* __restrict__ w0t,
                        const float* __restrict__ u0, const float* __restrict__ cb,
                        const float* __restrict__ lng, const float* __restrict__ wgv,
                        const float* __restrict__ bg,
                        __half* __restrict__ z2h, float* __restrict__ gt) {
    const int t = blockIdx.x, tid = threadIdx.x;
    const int l = t & (Lsz - 1);
    const float mean = 1.0f / 512.0f;
    const float rstd = rsqrtf(mean * (511.0f / 512.0f) + 1e-5f);

    const int tokm = (l > 0) ? x[t - 1] : -1;
    const int tok0 = x[t];
    const int tokp = (l < Lsz - 1) ? x[t + 1] : -1;

    float4 acc = ((const float4*)cb)[tid];
    {
        const float s = rstd * lng[tok0];
        float4 w = ((const float4*)(w0t + (size_t)DD + (size_t)tok0 * Dsz))[tid];
        float4 u = ((const float4*)(u0 + Dsz))[tid];
        acc.x += s * w.x + u.x; acc.y += s * w.y + u.y;
        acc.z += s * w.z + u.z; acc.w += s * w.w + u.w;
    }
    if (tokm >= 0) {
        const float s = rstd * lng[tokm];
        float4 w = ((const float4*)(w0t + (size_t)tokm * Dsz))[tid];
        float4 u = ((const float4*)u0)[tid];
        acc.x += s * w.x + u.x; acc.y += s * w.y + u.y;
        acc.z += s * w.z + u.z; acc.w += s * w.w + u.w;
    }
    if (tokp >= 0) {
        const float s = rstd * lng[tokp];
        float4 w = ((const float4*)(w0t + (size_t)2 * DD + (size_t)tokp * Dsz))[tid];
        float4 u = ((const float4*)(u0 + 2 * Dsz))[tid];
        acc.x += s * w.x + u.x; acc.y += s * w.y + u.y;
        acc.z += s * w.z + u.z; acc.w += s * w.w + u.w;
    }
    __half2* po = (__half2*)(z2h + (size_t)t * Dsz);
    po[2 * tid] = __floats2half2_rn(acc.x, acc.y);
    po[2 * tid + 1] = __floats2half2_rn(acc.z, acc.w);

    float4 wv = ((const float4*)wgv)[tid];
    float p = acc.x * wv.x + acc.y * wv.y + acc.z * wv.z + acc.w * wv.w;
#pragma unroll
    for (int o = 16; o; o >>= 1) p += __shfl_xor_sync(0xffffffffu, p, o);
    __shared__ float smr[4];
    if ((tid & 31) == 0) smr[tid >> 5] = p;
    __syncthreads();
    if (tid == 0) {
        float s = smr[0] + smr[1] + smr[2] + smr[3];
        gt[t] = 1.0f / (1.0f + expf(-(s + bg[0])));
    }
}

// ---------------- merged prep: 1-term converts + w0t + flag reset -------------
__global__ void prep_k(const float* __restrict__ conv_w, const float* __restrict__ mo_w,
                       const float* __restrict__ head_w, const float* __restrict__ wout,
                       const float* __restrict__ fc_w,
                       __half* __restrict__ wh, float* __restrict__ w0t,
                       __half* __restrict__ fch) {
    const int idx = blockIdx.x * blockDim.x + threadIdx.x;   // 0 .. 32*DD-1
    if (idx < NFLAGS) g_sflag[idx] = 0;
    if (idx < 12 * DD) {
        int layer = idx / (3 * DD);
        int r = idx - layer * (3 * DD);
        int h = r / DD;
        int rr = r - h * DD;
        int o = rr >> 9, i = rr & 511;
        wh[idx] = __float2half_rn(conv_w[(size_t)layer * 3 * DD + ((size_t)o * Dsz + i) * 3 + h]);
    } else if (idx < 16 * DD) {
        int j = idx - 12 * DD;
        wh[W_MO(0) + j] = __float2half_rn(mo_w[j]);
    } else if (idx < 17 * DD) {
        int j = idx - 16 * DD;
        wh[W_HEAD + j] = __float2half_rn(head_w[j]);
    } else if (idx < 21 * DD) {
        int j = idx - 17 * DD;
        int layer = j / DD;
        int r = j - layer * DD;
        int n = r >> 9, k = r & 511;
        wh[W_WOUT(0) + j] = __float2half_rn(wout[(size_t)layer * DD + (size_t)k * Dsz + n]);
    } else if (idx < 24 * DD) {
        int j = idx - 21 * DD;
        int h = j / DD;
        int r = j - h * DD;
        int i = r >> 9, o = r & 511;
        w0t[j] = conv_w[((size_t)o * Dsz + i) * 3 + h];
    } else {
        int j = idx - 24 * DD;
        fch[j] = __float2half_rn(fc_w[j]);
    }
}

// ---------------- layernorm with fp16 output ----------------------------------
__global__ void ln_h_k(const float* __restrict__ in, __half* __restrict__ oh,
                       const float* __restrict__ gamma, const float* __restrict__ beta) {
    int t = blockIdx.x, tid = threadIdx.x;
    const float4* rp = (const float4*)(in + (size_t)t * Dsz);
    float4 v = rp[tid];
    float s = v.x + v.y + v.z + v.w;
#pragma unroll
    for (int o = 16; o; o >>= 1) s += __shfl_xor_sync(0xffffffffu, s, o);
    __shared__ float smr[4];
    if ((tid & 31) == 0) smr[tid >> 5] = s;
    __syncthreads();
    float mean = (smr[0] + smr[1] + smr[2] + smr[3]) * (1.0f / Dsz);
    float dx = v.x - mean, dy = v.y - mean, dz = v.z - mean, dw = v.w - mean;
    float q = dx * dx + dy * dy + dz * dz + dw * dw;
#pragma unroll
    for (int o = 16; o; o >>= 1) q += __shfl_xor_sync(0xffffffffu, q, o);
    __syncthreads();
    if ((tid & 31) == 0) smr[tid >> 5] = q;
    __syncthreads();
    float var = (smr[0] + smr[1] + smr[2] + smr[3]) * (1.0f / Dsz);
    float rstd = rsqrtf(var + 1e-5f);
    float4 g4 = ((const float4*)gamma)[tid];
    float4 b4 = ((const float4*)beta)[tid];
    float f0 = dx * rstd * g4.x + b4.x, f1 = dy * rstd * g4.y + b4.y;
    float f2 = dz * rstd * g4.z + b4.z, f3 = dw * rstd * g4.w + b4.w;
    __half2* ph = (__half2*)(oh + (size_t)t * Dsz);
    ph[2 * tid] = __floats2half2_rn(f0, f1);
    ph[2 * tid + 1] = __floats2half2_rn(f2, f3);
}

// ---------------- u0 = W_h^T (lnb - rstd*mean*lng) -----------------------------
__global__ void u0_k(const float* __restrict__ cw, const float* __restrict__ lng,
                     const float* __restrict__ lnb, float* __restrict__ u0) {
    int w = (blockIdx.x * blockDim.x + threadIdx.x) >> 5;
    int lane = threadIdx.x & 31;
    int h = w >> 9, o = w & 511;
    const float mean = 1.0f / 512.0f;
    const float rstd = rsqrtf(mean * (511.0f / 512.0f) + 1e-5f);
    float s = 0.f;
#pragma unroll
    for (int c = 0; c < 16; c++) {
        int i = lane + 32 * c;
        float v = lnb[i] - rstd * mean * lng[i];
        s = fmaf(cw[((size_t)o * Dsz + i) * 3 + h], v, s);
    }
#pragma unroll
    for (int ofs = 16; ofs; ofs >>= 1) s += __shfl_xor_sync(0xffffffffu, s, ofs);
    if (lane == 0) u0[w] = s;
}

// ---------------- 1-term convert (Wcomb) ---------------------------------------
__global__ void wsplit1_k(const float* __restrict__ w, __half* __restrict__ wh, int n) {
    int idx = blockIdx.x * blockDim.x + threadIdx.x;
    if (idx >= n) return;
    wh[idx] = __float2half_rn(w[idx]);
}

// ---------------- bcomb = Wf·bo + fb --------------------------------------------
__global__ void bcomb_k(const float* __restrict__ fw, const float* __restrict__ bo,
                        const float* __restrict__ fb, float* __restrict__ out) {
    int w = (blockIdx.x * blockDim.x + threadIdx.x) >> 5;
    int lane = threadIdx.x & 31;
    int layer = w >> 10, e = w & 1023;
    const float* fr = fw + ((size_t)layer * 1024 + e) * Dsz;
    const float* br = bo + (size_t)layer * Dsz;
    float s = 0.f;
#pragma unroll
    for (int i = 0; i < 16; i++) s = fmaf(fr[lane + 32 * i], br[lane + 32 * i], s);
#pragma unroll
    for (int o = 16; o; o >>= 1) s += __shfl_xor_sync(0xffffffffu, s, o);
    if (lane == 0) out[w] = s + fb[(size_t)layer * 1024 + e];
}

// ============================================================================
// Unified chained scan over fp16 z2; c=0 emits in pass 1. fp16 output.
// Flags zeroed per call in prep_k -> deterministic across graph replays.
// ============================================================================
__global__ void scan_u_k(const __half* __restrict__ z2h,
                         const float* __restrict__ gatep,
                         const float* __restrict__ gt0,
                         const float* __restrict__ bgp,
                         float* __restrict__ hfin, int* __restrict__ flags,
                         __half* __restrict__ hh) {
    const int bx = blockIdx.x;
    const int c = bx >> 6, b = (bx >> 2) & 15, dch = bx & 3;
    const int tid = threadIdx.x;
    const int d = (dch << 7) + tid;
    const int l0 = c * SCH;
    __shared__ float gsm[SCH];

    if (gt0) {
        for (int j = tid; j < SCH; j += 128)
            gsm[j] = gt0[b * Lsz + l0 + j];
    } else {
        const float bgv = bgp[0];
        for (int j = tid; j < SCH; j += 128) {
            const int t = b * Lsz + l0 + j;
            float s = 0.f;
#pragma unroll
            for (int p = 0; p < 16; p++) s += gatep[(size_t)p * Tsz + t];
            gsm[j] = 1.0f / (1.0f + expf(-(s + bgv)));
        }
    }
    __syncthreads();

    const size_t base = (size_t)b * Lsz * Dsz + (size_t)l0 * Dsz + d;
    const bool first = (c == 0);
    float hv = 0.f, ap = 1.f;
    for (int l = 0; l < SCH; l += 8) {
        float xs[8], gs[8];
#pragma unroll
        for (int j = 0; j < 8; j++) {
            xs[j] = __half2float(z2h[base + (size_t)(l + j) * Dsz]);
            gs[j] = gsm[l + j];
        }
#pragma unroll
        for (int j = 0; j < 8; j++) {
            hv = fmaf(gs[j], xs[j] - hv, hv);
            ap *= (1.f - gs[j]);
            if (first) hh[base + (size_t)(l + j) * Dsz] = __float2half_rn(hv);
        }
    }
    float carry = 0.f;
    const size_t fo = (size_t)c * (Bsz * Dsz) + (size_t)b * Dsz + d;
    if (!first) {
        if (tid == 0) {
            volatile int* f = flags + (bx - 64);
            while (*f == 0) {}
        }
        __syncthreads();
        __threadfence();
        carry = __ldcg(hfin + fo - (size_t)(Bsz * Dsz));
    }
    hfin[fo] = hv + ap * carry;
    __syncthreads();
    __threadfence();
    if (tid == 0) *((volatile int*)(flags + bx)) = 1;
    if (first) return;

    hv = carry;
    for (int l = 0; l < SCH; l += 8) {
        float xs[8], gs[8];
#pragma unroll
        for (int j = 0; j < 8; j++) {
            xs[j] = __half2float(z2h[base + (size_t)(l + j) * Dsz]);
            gs[j] = gsm[l + j];
        }
#pragma unroll
        for (int j = 0; j < 8; j++) {
            hv = fmaf(gs[j], xs[j] - hv, hv);
            hh[base + (size_t)(l + j) * Dsz] = __float2half_rn(hv);
        }
    }
}

// ---------------- launch --------------------------------------------------------
extern "C" void kernel_launch(void* const* d_in, const int* in_sizes, int n_in,
                              void* d_out, int out_size) {
    const int* x = (const int*)d_in[0];
    const float* ln_g = (const float*)d_in[1];
    const float* ln_b = (const float*)d_in[2];
    const float* conv_w = (const float*)d_in[3];
    const float* conv_b = (const float*)d_in[4];
    const float* wg = (const float*)d_in[5];
    const float* bg = (const float*)d_in[6];
    const float* wout = (const float*)d_in[7];
    const float* bout = (const float*)d_in[8];
    const float* fc_w = (const float*)d_in[9];
    const float* fc_b = (const float*)d_in[10];
    const float* mo_w = (const float*)d_in[11];
    const float* mo_b = (const float*)d_in[12];
    const float* lnf_g = (const float*)d_in[13];
    const float* lnf_b = (const float*)d_in[14];
    const float* head_w = (const float*)d_in[15];
    const float* head_b = (const float*)d_in[16];

    float *y, *gt, *gp, *bcomb, *hfin, *w0t, *u0;
    int* sflag;
    __half *z2h, *zh, *hh, *gh, *wh;
    cudaGetSymbolAddress((void**)&y, g_y);
    cudaGetSymbolAddress((void**)&gt, g_gate);
    cudaGetSymbolAddress((void**)&gp, g_gatep);
    cudaGetSymbolAddress((void**)&bcomb, g_bcomb);
    cudaGetSymbolAddress((void**)&hfin, g_hfin);
    cudaGetSymbolAddress((void**)&sflag, g_sflag);
    cudaGetSymbolAddress((void**)&w0t, g_w0t);
    cudaGetSymbolAddress((void**)&u0, g_u0);
    cudaGetSymbolAddress((void**)&z2h, g_z2h);
    cudaGetSymbolAddress((void**)&zh, g_zh);
    cudaGetSymbolAddress((void**)&hh, g_hh);
    cudaGetSymbolAddress((void**)&gh, g_gh);
    cudaGetSymbolAddress((void**)&wh, g_wh);

    cudaFuncSetAttribute(mma_gemm_k, cudaFuncAttributeMaxDynamicSharedMemorySize, GSMEM);
    cudaFuncSetAttribute(mma_conv_k, cudaFuncAttributeMaxDynamicSharedMemorySize, CONVSMEM);
    cudaFuncSetAttribute(mma_fc_k, cudaFuncAttributeMaxDynamicSharedMemorySize, FCSMEM);

    const dim3 g512(4, Tsz / 128);

    // ---- prep: merged converts (+flag reset), bias fold, wout folding ----
    prep_k<<<(32 * DD) / 256, 256>>>(conv_w, mo_w, head_w, wout, fc_w, wh, w0t, gh);
    bcomb_k<<<(NLsz * 1024 * 32) / 256, 256>>>(fc_w, bout, fc_b, bcomb);
    u0_k<<<(3 * Dsz * 32) / 256, 256>>>(conv_w, ln_g, ln_b, u0);
    // Wcomb = Wf @ Wo; fp32 scratch = g_y (dead until layer-0 mo overwrites it)
    mma_gemm_k<<<dim3(4, 32), 512, GSMEM>>>(gh, wh + W_WOUT(0),
                                            nullptr, y, nullptr, Dsz, 0, (int)DD);
    wsplit1_k<<<(8 * DD) / 256, 256>>>(y, wh + W_FC(0), 8 * DD);

    for (int i = 0; i < NLsz; i++) {
        if (i == 0) {
            conv0_k<<<Tsz, 128>>>(x, w0t, u0, conv_b, ln_g, wg, bg, z2h, gt);
        } else {
            ln_h_k<<<Tsz, 128>>>(y, zh, ln_g + (size_t)i * Dsz, ln_b + (size_t)i * Dsz);
            mma_conv_k<<<g512, 512, CONVSMEM>>>(zh, wh + W_CONV(i),
                                                conv_b + (size_t)i * Dsz, z2h,
                                                wg + (size_t)i * Dsz, gp);
        }
        scan_u_k<<<NCH * 64, 128>>>(z2h, gp, (i == 0) ? gt : nullptr, bg + i,
                                    hfin, sflag + (size_t)i * (NCH * Bsz * 4), hh);
        mma_fc_k<<<g512, 512, FCSMEM>>>(hh, wh + W_FC(i),
                                        bcomb + (size_t)i * 1024, gh);
        mma_gemm_k<<<g512, 512, GSMEM>>>(gh, wh + W_MO(i),
                                         mo_b + (size_t)i * Dsz, y,
                                         (i == 0) ? x : nullptr, Dsz,
                                         (i == 0) ? (1 | 16) : (1 | 2), 0);
    }

    ln_h_k<<<Tsz, 128>>>(y, zh, lnf_g, lnf_b);
    mma_gemm_k<<<g512, 512, GSMEM>>>(zh, wh + W_HEAD, head_b,
                                     (float*)d_out, nullptr, Dsz, 1, 0);
}

// round 17
// speedup vs baseline: 2.2712x; 1.0067x over previous
#include <cuda_runtime.h>
#include <cuda_fp16.h>
#include <cstdint>
#include <cstddef>

#define Bsz 16
#define Lsz 2048
#define Dsz 512
#define NLsz 4
#define Tsz (Bsz * Lsz)  // 32768
#define DD (Dsz * Dsz)

// weight arena offsets (units of DD)
#define W_CONV(i) ((size_t)(i) * 3 * DD)
#define W_WOUT(i) ((size_t)(12 + (i)) * DD)      // wout^T (prep only)
#define W_FC(i)   ((size_t)(16 + 2 * (i)) * DD)  // after prep: Wcomb = Wf@Wo
#define W_MO(i)   ((size_t)(24 + (i)) * DD)
#define W_HEAD    ((size_t)28 * DD)

// scan chunking
#define SCH 256
#define NCH (Lsz / SCH)  // 8
#define NFLAGS (NLsz * NCH * Bsz * 4)  // 2048

// prep roles
#define PREP_BLKS 32768   // 32*DD/256
#define BCOMB_BLKS 512    // NL*1024 outputs / 8 per block
#define U0_BLKS 192       // 3*512 outputs / 8 per block

// ---------------- scratch (device globals; no allocation allowed) ----------
__device__ float g_y[Tsz * Dsz];             // residual; also Wcomb prep scratch
__device__ float g_gate[Tsz];
__device__ float g_gatep[16 * Tsz];
__device__ float g_bcomb[NLsz * 2 * Dsz];
__device__ float g_hfin[NCH * Bsz * Dsz];
__device__ int   g_sflag[NFLAGS];
__device__ float g_w0t[3 * DD];
__device__ float g_u0[3 * Dsz];
__device__ __half g_z2h[Tsz * Dsz];
__device__ __half g_zh[Tsz * Dsz];
__device__ __half g_hh[Tsz * Dsz];
__device__ __half g_gh[Tsz * Dsz];
__device__ __half g_wh[29 * DD];

// ---------------- helpers ---------------------------------------------------
__device__ __forceinline__ uint32_t smem_u32(const void* p) {
    return (uint32_t)__cvta_generic_to_shared(p);
}
__device__ __forceinline__ uint32_t swz(uint32_t x) { return x ^ ((x >> 3) & 0x70); }

__device__ __forceinline__ void cp16(uint32_t dst, const void* src, bool v) {
    int sz = v ? 16 : 0;
    asm volatile("cp.async.cg.shared.global [%0], [%1], 16, %2;"
                 :: "r"(dst), "l"(src), "r"(sz) : "memory");
}
#define CP_COMMIT() asm volatile("cp.async.commit_group;" ::: "memory")

#define LDSM_X4(r, a)                                                          \
    asm volatile("ldmatrix.sync.aligned.m8n8.x4.shared.b16 {%0,%1,%2,%3}, [%4];" \
                 : "=r"((r)[0]), "=r"((r)[1]), "=r"((r)[2]), "=r"((r)[3]) : "r"(a))

#define MMA_F16(d, a, b0, b1)                                                  \
    asm volatile(                                                              \
        "mma.sync.aligned.m16n8k16.row.col.f32.f16.f16.f32 "                   \
        "{%0,%1,%2,%3},{%4,%5,%6,%7},{%8,%9},{%0,%1,%2,%3};"                   \
        : "+f"((d)[0]), "+f"((d)[1]), "+f"((d)[2]), "+f"((d)[3])               \
        : "r"((a)[0]), "r"((a)[1]), "r"((a)[2]), "r"((a)[3]), "r"(b0), "r"(b1))

// ============================================================================
// Generic GEMM: A 1-term fp16, W 1-term. 512 thr, 128x128, 3-stage 32KB.
// flags: 1=addBias, 2=accum fp32, 16=one-hot residual add.
// ============================================================================
#define STAGE_B 32768
#define GSMEM (3 * STAGE_B)

__global__ __launch_bounds__(512, 1)
void mma_gemm_k(const __half* __restrict__ Ah, const __half* __restrict__ Wh,
                const float* __restrict__ bias, float* __restrict__ Cf,
                const int* __restrict__ xTok,
                int N, int flags, int wLayerStride) {
    extern __shared__ char smem[];
    const uint32_t smb = smem_u32(smem);
    const int tid = threadIdx.x, lane = tid & 31, wid = tid >> 5;
    const int mBase = blockIdx.y << 7, nBase = blockIdx.x << 7;
    const int wm = wid & 3, wn = wid >> 2;

    float acc[2][4][4];
#pragma unroll
    for (int t = 0; t < 2; t++)
#pragma unroll
        for (int j = 0; j < 4; j++)
#pragma unroll
            for (int q = 0; q < 4; q++) acc[t][j][q] = 0.f;

    const int rowIdx = tid >> 3, col16 = tid & 7;

    auto issue = [&](int idx) {
        const size_t wOff = (size_t)(mBase >> 10) * wLayerStride;
        const uint32_t sb = smb + (uint32_t)(idx % 3) * STAGE_B;
        const int kOff = idx * 64 + col16 * 8;
#pragma unroll
        for (int c = 0; c < 2; c++) {
            const int row = rowIdx + c * 64;
            const uint32_t dsw = swz((uint32_t)(row * 128 + col16 * 16));
            const size_t aoff = (size_t)(mBase + row) * Dsz + kOff;
            cp16(sb + dsw, Ah + aoff, true);
            const size_t woff = wOff + (size_t)(nBase + row) * Dsz + kOff;
            cp16(sb + 16384 + dsw, Wh + woff, true);
        }
        CP_COMMIT();
    };

    issue(0);
    issue(1);
    for (int idx = 0; idx < 8; idx++) {
        if (idx + 1 < 8) {
            asm volatile("cp.async.wait_group 1;" ::: "memory");
        } else {
            asm volatile("cp.async.wait_group 0;" ::: "memory");
        }
        __syncthreads();
        if (idx + 2 < 8) issue(idx + 2);
        const uint32_t sb = smb + (uint32_t)(idx % 3) * STAGE_B;
#pragma unroll
        for (int kk = 0; kk < 4; kk++) {
            uint32_t ah[2][4];
#pragma unroll
            for (int t = 0; t < 2; t++) {
                const int row = wm * 32 + t * 16 + (lane & 15);
                const uint32_t off =
                    swz((uint32_t)(row * 128 + kk * 32 + (lane >> 4) * 16));
                LDSM_X4(ah[t], sb + off);
            }
#pragma unroll
            for (int jp = 0; jp < 2; jp++) {
                const int nrow = wn * 32 + jp * 16 + (lane & 7) + ((lane >> 4) << 3);
                const uint32_t off =
                    swz((uint32_t)(nrow * 128 + kk * 32 + ((lane >> 3) & 1) * 16));
                uint32_t bh[4];
                LDSM_X4(bh, sb + 16384 + off);
#pragma unroll
                for (int t = 0; t < 2; t++)
#pragma unroll
                    for (int jj = 0; jj < 2; jj++)
                        MMA_F16(acc[t][jp * 2 + jj], ah[t], bh[jj * 2], bh[jj * 2 + 1]);
            }
        }
    }

    const bool addB = (flags & 1) != 0;
    const bool accum = (flags & 2) != 0;
    const bool onehot = (flags & 16) != 0;
#pragma unroll
    for (int t = 0; t < 2; t++) {
        const int r0 = mBase + wm * 32 + t * 16 + (lane >> 2);
#pragma unroll
        for (int j = 0; j < 4; j++) {
            const int col = nBase + wn * 32 + j * 8 + (lane & 3) * 2;
            float b0 = 0.f, b1 = 0.f;
            if (addB) { b0 = bias[col]; b1 = bias[col + 1]; }
            float v0 = acc[t][j][0] + b0, v1 = acc[t][j][1] + b1;
            float v2 = acc[t][j][2] + b0, v3 = acc[t][j][3] + b1;
            const size_t o0 = (size_t)r0 * N + col;
            const size_t o1 = (size_t)(r0 + 8) * N + col;
            if (onehot) {
                const int t0 = xTok[r0], t1 = xTok[r0 + 8];
                v0 += (col == t0) ? 1.f : 0.f;
                v1 += (col + 1 == t0) ? 1.f : 0.f;
                v2 += (col == t1) ? 1.f : 0.f;
                v3 += (col + 1 == t1) ? 1.f : 0.f;
            }
            if (accum) {
                float2 q0 = *(float2*)(Cf + o0);
                float2 q1 = *(float2*)(Cf + o1);
                v0 += q0.x; v1 += q0.y; v2 += q1.x; v3 += q1.y;
            }
            *(float2*)(Cf + o0) = make_float2(v0, v1);
            *(float2*)(Cf + o1) = make_float2(v2, v3);
        }
    }
}

// ============================================================================
// Conv GEMM: 3 taps share one 130-row A tile (1-term A).
// ============================================================================
#define CONV_A 17408
#define CONV_STAGE (CONV_A + 3 * 16384)  // 66560
#define CONVSMEM (2 * CONV_STAGE)        // 133120

__global__ __launch_bounds__(512, 1)
void mma_conv_k(const __half* __restrict__ Ah, const __half* __restrict__ Wh,
                const float* __restrict__ bias, __half* __restrict__ Ch,
                const float* __restrict__ wgv, float* __restrict__ gateOut) {
    extern __shared__ char smem[];
    const uint32_t smb = smem_u32(smem);
    const int tid = threadIdx.x, lane = tid & 31, wid = tid >> 5;
    const int mBase = blockIdx.y << 7, nBase = blockIdx.x << 7;
    const int wm = wid & 3, wn = wid >> 2;

    float acc[2][4][4];
#pragma unroll
    for (int t = 0; t < 2; t++)
#pragma unroll
        for (int j = 0; j < 4; j++)
#pragma unroll
            for (int q = 0; q < 4; q++) acc[t][j][q] = 0.f;

    const int rowIdx = tid >> 3, col16 = tid & 7;
    const bool loVal = (mBase & (Lsz - 1)) != 0;
    const bool hiVal = ((mBase + 128) & (Lsz - 1)) != 0;

    auto issue = [&](int c8) {
        const uint32_t sb = smb + (uint32_t)(c8 & 1) * CONV_STAGE;
        const int kOff = c8 * 64 + col16 * 8;
#pragma unroll
        for (int c = 0; c < 2; c++) {
            const int sr = rowIdx + c * 64 + 1;
            const uint32_t dsw = swz((uint32_t)(sr * 128 + col16 * 16));
            const size_t aoff = (size_t)(mBase + sr - 1) * Dsz + kOff;
            cp16(sb + dsw, Ah + aoff, true);
        }
        if (tid < 8) {
            const uint32_t dsw = swz((uint32_t)(tid * 16));
            const int ko = c8 * 64 + tid * 8;
            const size_t aoff = (size_t)(loVal ? mBase - 1 : mBase) * Dsz + ko;
            cp16(sb + dsw, Ah + aoff, loVal);
        } else if (tid < 16) {
            const int cc = tid - 8;
            const uint32_t dsw = swz((uint32_t)(129 * 128 + cc * 16));
            const int ko = c8 * 64 + cc * 8;
            const size_t aoff = (size_t)(hiVal ? mBase + 128 : mBase) * Dsz + ko;
            cp16(sb + dsw, Ah + aoff, hiVal);
        }
#pragma unroll
        for (int p = 0; p < 3; p++) {
#pragma unroll
            for (int c = 0; c < 2; c++) {
                const int row = rowIdx + c * 64;
                const uint32_t dsw = swz((uint32_t)(row * 128 + col16 * 16));
                const size_t woff = (size_t)p * DD + (size_t)(nBase + row) * Dsz + kOff;
                cp16(sb + CONV_A + (uint32_t)p * 16384 + dsw, Wh + woff, true);
            }
        }
        CP_COMMIT();
    };

    issue(0);
    for (int c8 = 0; c8 < 8; c8++) {
        asm volatile("cp.async.wait_group 0;" ::: "memory");
        __syncthreads();
        if (c8 + 1 < 8) issue(c8 + 1);
        const uint32_t sb = smb + (uint32_t)(c8 & 1) * CONV_STAGE;
#pragma unroll
        for (int kk = 0; kk < 4; kk++) {
#pragma unroll
            for (int p = 0; p < 3; p++) {
                uint32_t ah[2][4];
#pragma unroll
                for (int t = 0; t < 2; t++) {
                    const int row = wm * 32 + t * 16 + (lane & 15) + p;
                    const uint32_t off =
                        swz((uint32_t)(row * 128 + kk * 32 + (lane >> 4) * 16));
                    LDSM_X4(ah[t], sb + off);
                }
#pragma unroll
                for (int jp = 0; jp < 2; jp++) {
                    const int nrow = wn * 32 + jp * 16 + (lane & 7) + ((lane >> 4) << 3);
                    const uint32_t off =
                        swz((uint32_t)(nrow * 128 + kk * 32 + ((lane >> 3) & 1) * 16));
                    uint32_t bh[4];
                    LDSM_X4(bh, sb + CONV_A + (uint32_t)p * 16384 + off);
#pragma unroll
                    for (int t = 0; t < 2; t++)
#pragma unroll
                        for (int jj = 0; jj < 2; jj++)
                            MMA_F16(acc[t][jp * 2 + jj], ah[t], bh[jj * 2], bh[jj * 2 + 1]);
                }
            }
        }
    }

#pragma unroll
    for (int t = 0; t < 2; t++) {
        const int r0 = mBase + wm * 32 + t * 16 + (lane >> 2);
        float p0 = 0.f, p1 = 0.f;
#pragma unroll
        for (int j = 0; j < 4; j++) {
            const int col = nBase + wn * 32 + j * 8 + (lane & 3) * 2;
            const float b0 = bias[col], b1 = bias[col + 1];
            float v0 = acc[t][j][0] + b0, v1 = acc[t][j][1] + b1;
            float v2 = acc[t][j][2] + b0, v3 = acc[t][j][3] + b1;
            const size_t o0 = (size_t)r0 * Dsz + col;
            const size_t o1 = (size_t)(r0 + 8) * Dsz + col;
            *(__half2*)(Ch + o0) = __floats2half2_rn(v0, v1);
            *(__half2*)(Ch + o1) = __floats2half2_rn(v2, v3);
            const float w0 = __ldg(wgv + col), w1 = __ldg(wgv + col + 1);
            p0 = fmaf(v0, w0, fmaf(v1, w1, p0));
            p1 = fmaf(v2, w0, fmaf(v3, w1, p1));
        }
        p0 += __shfl_xor_sync(0xffffffffu, p0, 1);
        p0 += __shfl_xor_sync(0xffffffffu, p0, 2);
        p1 += __shfl_xor_sync(0xffffffffu, p1, 1);
        p1 += __shfl_xor_sync(0xffffffffu, p1, 2);
        if ((lane & 3) == 0) {
            float* gp = gateOut + ((size_t)((nBase >> 7) * 4 + wn)) * Tsz;
            gp[r0] = p0;
            gp[r0 + 8] = p1;
        }
    }
}

// ============================================================================
// Fused fc(+folded wout) + gated-MLP GEMM, 1-term A.
// ============================================================================
#define FC_STAGE 49152
#define FCSMEM (2 * FC_STAGE)

__global__ __launch_bounds__(512, 1)
void mma_fc_k(const __half* __restrict__ Ah, const __half* __restrict__ Wh,
              const float* __restrict__ bias, __half* __restrict__ Oh) {
    extern __shared__ char smem[];
    const uint32_t smb = smem_u32(smem);
    const int tid = threadIdx.x, lane = tid & 31, wid = tid >> 5;
    const int mBase = blockIdx.y << 7, nBase = blockIdx.x << 7;
    const int wm = wid & 3, wn = wid >> 2;

    float accg[2][4][4], accv[2][4][4];
#pragma unroll
    for (int t = 0; t < 2; t++)
#pragma unroll
        for (int j = 0; j < 4; j++)
#pragma unroll
            for (int q = 0; q < 4; q++) { accg[t][j][q] = 0.f; accv[t][j][q] = 0.f; }

    const int rowIdx = tid >> 3, col16 = tid & 7;

    auto issue = [&](int idx) {
        const uint32_t sb = smb + (uint32_t)(idx & 1) * FC_STAGE;
        const int kOff = idx * 64 + col16 * 8;
#pragma unroll
        for (int c = 0; c < 2; c++) {
            const int row = rowIdx + c * 64;
            const uint32_t dsw = swz((uint32_t)(row * 128 + col16 * 16));
            const size_t aoff = (size_t)(mBase + row) * Dsz + kOff;
            cp16(sb + dsw, Ah + aoff, true);
            const size_t wgoff = (size_t)(nBase + row) * Dsz + kOff;
            cp16(sb + 16384 + dsw, Wh + wgoff, true);
            const size_t wvoff = (size_t)(512 + nBase + row) * Dsz + kOff;
            cp16(sb + 32768 + dsw, Wh + wvoff, true);
        }
        CP_COMMIT();
    };

    issue(0);
    for (int idx = 0; idx < 8; idx++) {
        asm volatile("cp.async.wait_group 0;" ::: "memory");
        __syncthreads();
        if (idx + 1 < 8) issue(idx + 1);
        const uint32_t sb = smb + (uint32_t)(idx & 1) * FC_STAGE;
#pragma unroll
        for (int kk = 0; kk < 4; kk++) {
            uint32_t ah[2][4], bg2[2][4], bv2[2][4];
#pragma unroll
            for (int t = 0; t < 2; t++) {
                const int row = wm * 32 + t * 16 + (lane & 15);
                const uint32_t off =
                    swz((uint32_t)(row * 128 + kk * 32 + (lane >> 4) * 16));
                LDSM_X4(ah[t], sb + off);
            }
#pragma unroll
            for (int jp = 0; jp < 2; jp++) {
                const int nrow = wn * 32 + jp * 16 + (lane & 7) + ((lane >> 4) << 3);
                const uint32_t off =
                    swz((uint32_t)(nrow * 128 + kk * 32 + ((lane >> 3) & 1) * 16));
                LDSM_X4(bg2[jp], sb + 16384 + off);
                LDSM_X4(bv2[jp], sb + 32768 + off);
            }
#pragma unroll
            for (int jp = 0; jp < 2; jp++)
#pragma unroll
                for (int t = 0; t < 2; t++)
#pragma unroll
                    for (int jj = 0; jj < 2; jj++) {
                        MMA_F16(accg[t][jp * 2 + jj], ah[t],
                                bg2[jp][jj * 2], bg2[jp][jj * 2 + 1]);
                        MMA_F16(accv[t][jp * 2 + jj], ah[t],
                                bv2[jp][jj * 2], bv2[jp][jj * 2 + 1]);
                    }
        }
    }

#pragma unroll
    for (int t = 0; t < 2; t++) {
#pragma unroll
        for (int j = 0; j < 4; j++) {
            const int r0 = mBase + wm * 32 + t * 16 + (lane >> 2);
            const int col = nBase + wn * 32 + j * 8 + (lane & 3) * 2;
            const float bg0 = bias[col], bg1 = bias[col + 1];
            const float bv0 = bias[512 + col], bv1 = bias[512 + col + 1];
            float s0 = 1.f / (1.f + expf(-(accg[t][j][0] + bg0)));
            float s1 = 1.f / (1.f + expf(-(accg[t][j][1] + bg1)));
            float s2 = 1.f / (1.f + expf(-(accg[t][j][2] + bg0)));
            float s3 = 1.f / (1.f + expf(-(accg[t][j][3] + bg1)));
            float v0 = s0 * (accv[t][j][0] + bv0);
            float v1 = s1 * (accv[t][j][1] + bv1);
            float v2 = s2 * (accv[t][j][2] + bv0);
            float v3 = s3 * (accv[t][j][3] + bv1);
            const size_t o0 = (size_t)r0 * Dsz + col;
            const size_t o1 = (size_t)(r0 + 8) * Dsz + col;
            *(__half2*)(Oh + o0) = __floats2half2_rn(v0, v1);
            *(__half2*)(Oh + o1) = __floats2half2_rn(v2, v3);
        }
    }
}

// ============================================================================
// Layer-0 conv as gather (exact fp32) + fused gate. Warp-per-token, 8/block.
// ============================================================================
__global__ __launch_bounds__(256)
void conv0_k(const int* __restrict__ x, const float* __restrict__ w0t,
             const float* __restrict__ u0, const float* __restrict__ cb,
             const float* __restrict__ lng, const float* __restrict__ wgv,
             const float* __restrict__ bg,
             __half* __restrict__ z2h, float* __restrict__ gt) {
    const int wid = threadIdx.x >> 5, lane = threadIdx.x & 31;
    const int t = blockIdx.x * 8 + wid;
    const int l = t & (Lsz - 1);
    const float mean = 1.0f / 512.0f;
    const float rstd = rsqrtf(mean * (511.0f / 512.0f) + 1e-5f);

    const int tokm = (l > 0) ? x[t - 1] : -1;
    const int tok0 = x[t];
    const int tokp = (l < Lsz - 1) ? x[t + 1] : -1;

    float4 acc[4];
#pragma unroll
    for (int i = 0; i < 4; i++) acc[i] = ((const float4*)cb)[lane + 32 * i];
    {
        const float s = rstd * lng[tok0];
        const float4* wr = (const float4*)(w0t + (size_t)DD + (size_t)tok0 * Dsz);
        const float4* ur = (const float4*)(u0 + Dsz);
#pragma unroll
        for (int i = 0; i < 4; i++) {
            float4 w = wr[lane + 32 * i], u = ur[lane + 32 * i];
            acc[i].x += s * w.x + u.x; acc[i].y += s * w.y + u.y;
            acc[i].z += s * w.z + u.z; acc[i].w += s * w.w + u.w;
        }
    }
    if (tokm >= 0) {
        const float s = rstd * lng[tokm];
        const float4* wr = (const float4*)(w0t + (size_t)tokm * Dsz);
        const float4* ur = (const float4*)u0;
#pragma unroll
        for (int i = 0; i < 4; i++) {
            float4 w = wr[lane + 32 * i], u = ur[lane + 32 * i];
            acc[i].x += s * w.x + u.x; acc[i].y += s * w.y + u.y;
            acc[i].z += s * w.z + u.z; acc[i].w += s * w.w + u.w;
        }
    }
    if (tokp >= 0) {
        const float s = rstd * lng[tokp];
        const float4* wr = (const float4*)(w0t + (size_t)2 * DD + (size_t)tokp * Dsz);
        const float4* ur = (const float4*)(u0 + 2 * Dsz);
#pragma unroll
        for (int i = 0; i < 4; i++) {
            float4 w = wr[lane + 32 * i], u = ur[lane + 32 * i];
            acc[i].x += s * w.x + u.x; acc[i].y += s * w.y + u.y;
            acc[i].z += s * w.z + u.z; acc[i].w += s * w.w + u.w;
        }
    }
    uint2* po = (uint2*)(z2h + (size_t)t * Dsz);
    float p = 0.f;
#pragma unroll
    for (int i = 0; i < 4; i++) {
        __half2 h01 = __floats2half2_rn(acc[i].x, acc[i].y);
        __half2 h23 = __floats2half2_rn(acc[i].z, acc[i].w);
        po[lane + 32 * i] = make_uint2(*(uint32_t*)&h01, *(uint32_t*)&h23);
        float4 wv = ((const float4*)wgv)[lane + 32 * i];
        p += acc[i].x * wv.x + acc[i].y * wv.y + acc[i].z * wv.z + acc[i].w * wv.w;
    }
#pragma unroll
    for (int o = 16; o; o >>= 1) p += __shfl_xor_sync(0xffffffffu, p, o);
    if (lane == 0) gt[t] = 1.0f / (1.0f + expf(-(p + bg[0])));
}

// ---------------- merged prep: converts + w0t + fc + bcomb + u0 + flags -------
__global__ __launch_bounds__(256)
void prep_k(const float* __restrict__ conv_w, const float* __restrict__ mo_w,
            const float* __restrict__ head_w, const float* __restrict__ wout,
            const float* __restrict__ fc_w, const float* __restrict__ bo,
            const float* __restrict__ fb, const float* __restrict__ lng,
            const float* __restrict__ lnb,
            __half* __restrict__ wh, float* __restrict__ w0t,
            __half* __restrict__ fch, float* __restrict__ bcombO,
            float* __restrict__ u0O) {
    const int bid = blockIdx.x;
    const int tid = threadIdx.x;
    if (bid < PREP_BLKS) {
        const int idx = bid * 256 + tid;
        if (idx < NFLAGS) g_sflag[idx] = 0;
        if (idx < 12 * DD) {
            int layer = idx / (3 * DD);
            int r = idx - layer * (3 * DD);
            int h = r / DD;
            int rr = r - h * DD;
            int o = rr >> 9, i = rr & 511;
            wh[idx] = __float2half_rn(conv_w[(size_t)layer * 3 * DD + ((size_t)o * Dsz + i) * 3 + h]);
        } else if (idx < 16 * DD) {
            int j = idx - 12 * DD;
            wh[W_MO(0) + j] = __float2half_rn(mo_w[j]);
        } else if (idx < 17 * DD) {
            int j = idx - 16 * DD;
            wh[W_HEAD + j] = __float2half_rn(head_w[j]);
        } else if (idx < 21 * DD) {
            int j = idx - 17 * DD;
            int layer = j / DD;
            int r = j - layer * DD;
            int n = r >> 9, k = r & 511;
            wh[W_WOUT(0) + j] = __float2half_rn(wout[(size_t)layer * DD + (size_t)k * Dsz + n]);
        } else if (idx < 24 * DD) {
            int j = idx - 21 * DD;
            int h = j / DD;
            int r = j - h * DD;
            int i = r >> 9, o = r & 511;
            w0t[j] = conv_w[((size_t)o * Dsz + i) * 3 + h];
        } else {
            int j = idx - 24 * DD;
            fch[j] = __float2half_rn(fc_w[j]);
        }
    } else if (bid < PREP_BLKS + BCOMB_BLKS) {
        // bcomb role: w = Wf·bo + fb  (8 outputs per block, warp each)
        const int w = (bid - PREP_BLKS) * 8 + (tid >> 5);
        const int lane = tid & 31;
        const int layer = w >> 10, e = w & 1023;
        const float* fr = fc_w + ((size_t)layer * 1024 + e) * Dsz;
        const float* br = bo + (size_t)layer * Dsz;
        float s = 0.f;
#pragma unroll
        for (int i = 0; i < 16; i++) s = fmaf(fr[lane + 32 * i], br[lane + 32 * i], s);
#pragma unroll
        for (int o = 16; o; o >>= 1) s += __shfl_xor_sync(0xffffffffu, s, o);
        if (lane == 0) bcombO[w] = s + fb[(size_t)layer * 1024 + e];
    } else {
        // u0 role
        const int w = (bid - PREP_BLKS - BCOMB_BLKS) * 8 + (tid >> 5);
        const int lane = tid & 31;
        const int h = w >> 9, o = w & 511;
        const float mean = 1.0f / 512.0f;
        const float rstd = rsqrtf(mean * (511.0f / 512.0f) + 1e-5f);
        float s = 0.f;
#pragma unroll
        for (int c = 0; c < 16; c++) {
            int i = lane + 32 * c;
            float v = lnb[i] - rstd * mean * lng[i];
            s = fmaf(conv_w[((size_t)o * Dsz + i) * 3 + h], v, s);
        }
#pragma unroll
        for (int ofs = 16; ofs; ofs >>= 1) s += __shfl_xor_sync(0xffffffffu, s, ofs);
        if (lane == 0) u0O[w] = s;
    }
}

// ---------------- layernorm, warp-per-token (8 tokens / 256-thr block) --------
__global__ __launch_bounds__(256)
void ln_h_k(const float* __restrict__ in, __half* __restrict__ oh,
            const float* __restrict__ gamma, const float* __restrict__ beta) {
    const int wid = threadIdx.x >> 5, lane = threadIdx.x & 31;
    const int t = blockIdx.x * 8 + wid;
    const float4* rp = (const float4*)(in + (size_t)t * Dsz);
    float4 v[4];
    float s = 0.f;
#pragma unroll
    for (int i = 0; i < 4; i++) {
        v[i] = rp[lane + 32 * i];
        s += v[i].x + v[i].y + v[i].z + v[i].w;
    }
#pragma unroll
    for (int o = 16; o; o >>= 1) s += __shfl_xor_sync(0xffffffffu, s, o);
    const float mean = s * (1.0f / Dsz);
    float q = 0.f;
#pragma unroll
    for (int i = 0; i < 4; i++) {
        v[i].x -= mean; v[i].y -= mean; v[i].z -= mean; v[i].w -= mean;
        q += v[i].x * v[i].x + v[i].y * v[i].y + v[i].z * v[i].z + v[i].w * v[i].w;
    }
#pragma unroll
    for (int o = 16; o; o >>= 1) q += __shfl_xor_sync(0xffffffffu, q, o);
    const float rstd = rsqrtf(q * (1.0f / Dsz) + 1e-5f);
    uint2* po = (uint2*)(oh + (size_t)t * Dsz);
#pragma unroll
    for (int i = 0; i < 4; i++) {
        float4 g4 = ((const float4*)gamma)[lane + 32 * i];
        float4 b4 = ((const float4*)beta)[lane + 32 * i];
        float f0 = v[i].x * rstd * g4.x + b4.x, f1 = v[i].y * rstd * g4.y + b4.y;
        float f2 = v[i].z * rstd * g4.z + b4.z, f3 = v[i].w * rstd * g4.w + b4.w;
        __half2 h01 = __floats2half2_rn(f0, f1);
        __half2 h23 = __floats2half2_rn(f2, f3);
        po[lane + 32 * i] = make_uint2(*(uint32_t*)&h01, *(uint32_t*)&h23);
    }
}

// ---------------- 1-term convert (Wcomb) ---------------------------------------
__global__ void wsplit1_k(const float* __restrict__ w, __half* __restrict__ wh, int n) {
    int idx = blockIdx.x * blockDim.x + threadIdx.x;
    if (idx >= n) return;
    wh[idx] = __float2half_rn(w[idx]);
}

// ============================================================================
// Unified chained scan over fp16 z2; pass 1 stashes local states in smem,
// pass 2 = local + P*carry (no z2 re-read). c=0 emits in pass 1.
// Flags zeroed per call in prep_k -> deterministic across graph replays.
// Dyn smem: gsm 1KB | P 1KB | hloc 64KB = 67584 B -> 3 blocks/SM (>= chain ok:
// dependencies point to strictly lower blockIdx, scheduled earlier).
// ============================================================================
#define SCAN_SM (2048 + SCH * 128 * 2)

__global__ __launch_bounds__(128)
void scan_u_k(const __half* __restrict__ z2h,
              const float* __restrict__ gatep,
              const float* __restrict__ gt0,
              const float* __restrict__ bgp,
              float* __restrict__ hfin, int* __restrict__ flags,
              __half* __restrict__ hh) {
    extern __shared__ char sm[];
    float* gsm = (float*)sm;
    float* Pp = (float*)(sm + 1024);
    __half* hloc = (__half*)(sm + 2048);

    const int bx = blockIdx.x;
    const int c = bx >> 6, b = (bx >> 2) & 15, dch = bx & 3;
    const int tid = threadIdx.x;
    const int d = (dch << 7) + tid;
    const int l0 = c * SCH;

    if (gt0) {
        for (int j = tid; j < SCH; j += 128)
            gsm[j] = gt0[b * Lsz + l0 + j];
    } else {
        const float bgv = bgp[0];
        for (int j = tid; j < SCH; j += 128) {
            const int t = b * Lsz + l0 + j;
            float s = 0.f;
#pragma unroll
            for (int p = 0; p < 16; p++) s += gatep[(size_t)p * Tsz + t];
            gsm[j] = 1.0f / (1.0f + expf(-(s + bgv)));
        }
    }
    __syncthreads();

    const size_t base = (size_t)b * Lsz * Dsz + (size_t)l0 * Dsz + d;
    const bool first = (c == 0);
    float hv = 0.f, ap = 1.f;
    for (int l = 0; l < SCH; l += 8) {
        float xs[8], gs[8];
#pragma unroll
        for (int j = 0; j < 8; j++) {
            xs[j] = __half2float(z2h[base + (size_t)(l + j) * Dsz]);
            gs[j] = gsm[l + j];
        }
#pragma unroll
        for (int j = 0; j < 8; j++) {
            hv = fmaf(gs[j], xs[j] - hv, hv);
            ap *= (1.f - gs[j]);
            if (first) {
                hh[base + (size_t)(l + j) * Dsz] = __float2half_rn(hv);
            } else {
                hloc[(l + j) * 128 + tid] = __float2half_rn(hv);
                if (tid == 0) Pp[l + j] = ap;
            }
        }
    }
    float carry = 0.f;
    const size_t fo = (size_t)c * (Bsz * Dsz) + (size_t)b * Dsz + d;
    if (!first) {
        if (tid == 0) {
            volatile int* f = flags + (bx - 64);
            while (*f == 0) {}
        }
        __syncthreads();   // also publishes Pp/hloc to all threads
        __threadfence();
        carry = __ldcg(hfin + fo - (size_t)(Bsz * Dsz));
    }
    hfin[fo] = hv + ap * carry;
    __syncthreads();
    __threadfence();
    if (tid == 0) *((volatile int*)(flags + bx)) = 1;
    if (first) return;

    // pass 2: h_l = local_l + P_l * carry (from smem)
    for (int l = 0; l < SCH; l += 8) {
#pragma unroll
        for (int j = 0; j < 8; j++) {
            float h = __half2float(hloc[(l + j) * 128 + tid]) + Pp[l + j] * carry;
            hh[base + (size_t)(l + j) * Dsz] = __float2half_rn(h);
        }
    }
}

// ---------------- launch --------------------------------------------------------
extern "C" void kernel_launch(void* const* d_in, const int* in_sizes, int n_in,
                              void* d_out, int out_size) {
    const int* x = (const int*)d_in[0];
    const float* ln_g = (const float*)d_in[1];
    const float* ln_b = (const float*)d_in[2];
    const float* conv_w = (const float*)d_in[3];
    const float* conv_b = (const float*)d_in[4];
    const float* wg = (const float*)d_in[5];
    const float* bg = (const float*)d_in[6];
    const float* wout = (const float*)d_in[7];
    const float* bout = (const float*)d_in[8];
    const float* fc_w = (const float*)d_in[9];
    const float* fc_b = (const float*)d_in[10];
    const float* mo_w = (const float*)d_in[11];
    const float* mo_b = (const float*)d_in[12];
    const float* lnf_g = (const float*)d_in[13];
    const float* lnf_b = (const float*)d_in[14];
    const float* head_w = (const float*)d_in[15];
    const float* head_b = (const float*)d_in[16];

    float *y, *gt, *gp, *bcomb, *hfin, *w0t, *u0;
    int* sflag;
    __half *z2h, *zh, *hh, *gh, *wh;
    cudaGetSymbolAddress((void**)&y, g_y);
    cudaGetSymbolAddress((void**)&gt, g_gate);
    cudaGetSymbolAddress((void**)&gp, g_gatep);
    cudaGetSymbolAddress((void**)&bcomb, g_bcomb);
    cudaGetSymbolAddress((void**)&hfin, g_hfin);
    cudaGetSymbolAddress((void**)&sflag, g_sflag);
    cudaGetSymbolAddress((void**)&w0t, g_w0t);
    cudaGetSymbolAddress((void**)&u0, g_u0);
    cudaGetSymbolAddress((void**)&z2h, g_z2h);
    cudaGetSymbolAddress((void**)&zh, g_zh);
    cudaGetSymbolAddress((void**)&hh, g_hh);
    cudaGetSymbolAddress((void**)&gh, g_gh);
    cudaGetSymbolAddress((void**)&wh, g_wh);

    cudaFuncSetAttribute(mma_gemm_k, cudaFuncAttributeMaxDynamicSharedMemorySize, GSMEM);
    cudaFuncSetAttribute(mma_conv_k, cudaFuncAttributeMaxDynamicSharedMemorySize, CONVSMEM);
    cudaFuncSetAttribute(mma_fc_k, cudaFuncAttributeMaxDynamicSharedMemorySize, FCSMEM);
    cudaFuncSetAttribute(scan_u_k, cudaFuncAttributeMaxDynamicSharedMemorySize, SCAN_SM);

    const dim3 g512(4, Tsz / 128);

    // ---- prep: one merged kernel (converts + bcomb + u0 + flag reset) ----
    prep_k<<<PREP_BLKS + BCOMB_BLKS + U0_BLKS, 256>>>(
        conv_w, mo_w, head_w, wout, fc_w, bout, fc_b, ln_g, ln_b,
        wh, w0t, gh, bcomb, u0);
    // Wcomb = Wf @ Wo; fp32 scratch = g_y (dead until layer-0 mo overwrites it)
    mma_gemm_k<<<dim3(4, 32), 512, GSMEM>>>(gh, wh + W_WOUT(0),
                                            nullptr, y, nullptr, Dsz, 0, (int)DD);
    wsplit1_k<<<(8 * DD) / 256, 256>>>(y, wh + W_FC(0), 8 * DD);

    for (int i = 0; i < NLsz; i++) {
        if (i == 0) {
            conv0_k<<<Tsz / 8, 256>>>(x, w0t, u0, conv_b, ln_g, wg, bg, z2h, gt);
        } else {
            ln_h_k<<<Tsz / 8, 256>>>(y, zh, ln_g + (size_t)i * Dsz, ln_b + (size_t)i * Dsz);
            mma_conv_k<<<g512, 512, CONVSMEM>>>(zh, wh + W_CONV(i),
                                                conv_b + (size_t)i * Dsz, z2h,
                                                wg + (size_t)i * Dsz, gp);
        }
        scan_u_k<<<NCH * 64, 128, SCAN_SM>>>(z2h, gp, (i == 0) ? gt : nullptr, bg + i,
                                             hfin, sflag + (size_t)i * (NCH * Bsz * 4), hh);
        mma_fc_k<<<g512, 512, FCSMEM>>>(hh, wh + W_FC(i),
                                        bcomb + (size_t)i * 1024, gh);
        mma_gemm_k<<<g512, 512, GSMEM>>>(gh, wh + W_MO(i),
                                         mo_b + (size_t)i * Dsz, y,
                                         (i == 0) ? x : nullptr, Dsz,
                                         (i == 0) ? (1 | 16) : (1 | 2), 0);
    }

    ln_h_k<<<Tsz / 8, 256>>>(y, zh, lnf_g, lnf_b);
    mma_gemm_k<<<g512, 512, GSMEM>>>(zh, wh + W_HEAD, head_b,
                                     (float*)d_out, nullptr, Dsz, 1, 0);
}